// round 1
// baseline (speedup 1.0000x reference)
#include <cuda_runtime.h>
#include <cuda_bf16.h>
#include <math.h>

#define N_NODES 100000
#define NNZ     1000000
#define F_IN    1433
#define F_HID   128
#define F_OUTD  64
#define N_EDGES 40000
#define EPSV    1e-6f

// -------- static device scratch (no allocation allowed) --------
__device__ float g_support[(size_t)N_NODES * F_HID];
__device__ float g_agg[(size_t)N_NODES * F_HID];
__device__ float g_x[(size_t)N_NODES * F_HID];
__device__ float g_colsum[F_HID];

// -------- zero agg + colsum --------
__global__ void zero_kernel(int F) {
    size_t n4 = ((size_t)N_NODES * F) >> 2;
    size_t stride = (size_t)gridDim.x * blockDim.x;
    float4 z = make_float4(0.f, 0.f, 0.f, 0.f);
    float4* p = (float4*)g_agg;
    for (size_t i = (size_t)blockIdx.x * blockDim.x + threadIdx.x; i < n4; i += stride)
        p[i] = z;
    size_t t = (size_t)blockIdx.x * blockDim.x + threadIdx.x;
    if (t < F_HID) g_colsum[t] = 0.f;
}

// -------- SGEMM: C[M,N] = A[M,K] @ B[K,N], row-major, 128x128 tile, 8x8/thread --------
__global__ __launch_bounds__(256) void sgemm_kernel(
    const float* __restrict__ A, const float* __restrict__ B,
    float* __restrict__ C, int M, int K, int N)
{
    __shared__ float As[16][128];   // As[k][m]
    __shared__ float Bs[16][128];   // Bs[k][n]

    const int bm = blockIdx.y * 128;
    const int bn = blockIdx.x * 128;
    const int tid = threadIdx.x;
    const int tx = tid & 15;        // 0..15 -> n
    const int ty = tid >> 4;        // 0..15 -> m

    float acc[8][8];
#pragma unroll
    for (int i = 0; i < 8; i++)
#pragma unroll
        for (int j = 0; j < 8; j++) acc[i][j] = 0.f;

    const int arow  = tid >> 1;          // 0..127
    const int akofs = (tid & 1) << 3;    // 0 or 8
    const int brow  = tid >> 4;          // 0..15
    const int bcol0 = tid & 15;          // 0..15
    const bool amValid = (bm + arow) < M;
    const float* Arow = A + (size_t)(bm + arow) * K;

    for (int k0 = 0; k0 < K; k0 += 16) {
#pragma unroll
        for (int e = 0; e < 8; e++) {
            int k = k0 + akofs + e;
            As[akofs + e][arow] = (amValid && k < K) ? Arow[k] : 0.f;
        }
        {
            int kk = k0 + brow;
            const float* Brow = B + (size_t)kk * N;
            bool kv = kk < K;
#pragma unroll
            for (int j = 0; j < 8; j++) {
                int c = bcol0 + j * 16;
                Bs[brow][c] = (kv && (bn + c) < N) ? Brow[bn + c] : 0.f;
            }
        }
        __syncthreads();
#pragma unroll
        for (int kk = 0; kk < 16; kk++) {
            float a[8], b[8];
#pragma unroll
            for (int i = 0; i < 8; i++) a[i] = As[kk][(ty << 3) + i];
#pragma unroll
            for (int j = 0; j < 8; j++) b[j] = Bs[kk][(tx << 3) + j];
#pragma unroll
            for (int i = 0; i < 8; i++)
#pragma unroll
                for (int j = 0; j < 8; j++)
                    acc[i][j] = fmaf(a[i], b[j], acc[i][j]);
        }
        __syncthreads();
    }

#pragma unroll
    for (int i = 0; i < 8; i++) {
        int m = bm + (ty << 3) + i;
        if (m >= M) continue;
        float* Crow = C + (size_t)m * N;
#pragma unroll
        for (int j = 0; j < 8; j++) {
            int n = bn + (tx << 3) + j;
            if (n < N) Crow[n] = acc[i][j];
        }
    }
}

// -------- SpMM: g_agg[row] += val * g_support[col], atomic scatter --------
// One thread per (edge, 4-feature chunk). shift = log2(F/4).
__global__ void spmm_kernel(const int* __restrict__ row, const int* __restrict__ col,
                            const float* __restrict__ val, int F, int shift) {
    long long t = (long long)blockIdx.x * blockDim.x + threadIdx.x;
    int tpe = 1 << shift;
    long long total = (long long)NNZ * tpe;
    if (t >= total) return;
    int e  = (int)(t >> shift);
    int f4 = ((int)t & (tpe - 1)) << 2;
    int r = row[e];
    int c = col[e];
    float v = val[e];
    float4 s = *(const float4*)&g_support[(size_t)c * F + f4];
    float* dst = &g_agg[(size_t)r * F + f4];
    atomicAdd(dst + 0, v * s.x);
    atomicAdd(dst + 1, v * s.y);
    atomicAdd(dst + 2, v * s.z);
    atomicAdd(dst + 3, v * s.w);
}

// -------- bias + relu + column-sum (partials via atomics) --------
#define BRC_ROWS 100
__global__ void bias_relu_colsum_kernel(const float* __restrict__ bias, int F) {
    int f = threadIdx.x;            // blockDim.x == F
    int r0 = blockIdx.x * BRC_ROWS;
    float b = bias[f];
    float sum = 0.f;
#pragma unroll 4
    for (int i = 0; i < BRC_ROWS; i++) {
        int r = r0 + i;
        if (r >= N_NODES) break;
        float y = g_agg[(size_t)r * F + f] + b;
        y = fmaxf(y, 0.f);
        g_x[(size_t)r * F + f] = y;
        sum += y;
    }
    atomicAdd(&g_colsum[f], sum);
}

// -------- PairNorm (PN-SI): subtract col mean, per-row L2 normalize --------
__global__ void pairnorm_kernel(int F) {
    int gwarp = ((int)blockIdx.x * blockDim.x + threadIdx.x) >> 5;
    int lane = threadIdx.x & 31;
    if (gwarp >= N_NODES) return;
    int nf = F >> 5;  // values per lane (4 for F=128, 2 for F=64)
    float vals[4];
    float ss = 0.f;
#pragma unroll
    for (int j = 0; j < 4; j++) {
        if (j < nf) {
            int f = lane + (j << 5);
            float v = g_x[(size_t)gwarp * F + f] - g_colsum[f] * (1.0f / N_NODES);
            vals[j] = v;
            ss += v * v;
        }
    }
#pragma unroll
    for (int o = 16; o > 0; o >>= 1) ss += __shfl_xor_sync(0xffffffffu, ss, o);
    float inv = rsqrtf(EPSV + ss);
#pragma unroll
    for (int j = 0; j < 4; j++) {
        if (j < nf) {
            int f = lane + (j << 5);
            g_x[(size_t)gwarp * F + f] = vals[j] * inv;
        }
    }
}

// -------- decode: sigmoid(dot(x[a], x[b])), warp per edge, F=64 --------
__global__ void decode_kernel(const int* __restrict__ pos, const int* __restrict__ neg,
                              float* __restrict__ out) {
    int gwarp = ((int)blockIdx.x * blockDim.x + threadIdx.x) >> 5;
    int lane = threadIdx.x & 31;
    if (gwarp >= N_EDGES) return;
    const int* ei = (gwarp < 20000) ? (pos + (size_t)gwarp * 2)
                                    : (neg + (size_t)(gwarp - 20000) * 2);
    int a = ei[0];
    int b = ei[1];
    const float* xa = &g_x[(size_t)a * F_OUTD];
    const float* xb = &g_x[(size_t)b * F_OUTD];
    float s = xa[lane] * xb[lane] + xa[lane + 32] * xb[lane + 32];
#pragma unroll
    for (int o = 16; o > 0; o >>= 1) s += __shfl_xor_sync(0xffffffffu, s, o);
    if (lane == 0) out[gwarp] = 1.0f / (1.0f + expf(-s));
}

// ---------------------------------------------------------------
extern "C" void kernel_launch(void* const* d_in, const int* in_sizes, int n_in,
                              void* d_out, int out_size) {
    const float* in_feature = (const float*)d_in[0];
    const int*   adj_row    = (const int*)d_in[1];
    const int*   adj_col    = (const int*)d_in[2];
    const float* adj_val    = (const float*)d_in[3];
    const int*   pos_ei     = (const int*)d_in[4];
    const int*   neg_ei     = (const int*)d_in[5];
    const float* W[3] = { (const float*)d_in[6], (const float*)d_in[8], (const float*)d_in[10] };
    const float* Bv[3] = { (const float*)d_in[7], (const float*)d_in[9], (const float*)d_in[11] };
    float* out = (float*)d_out;

    // resolve device symbol addresses for GEMM A/C arguments
    float* d_support = nullptr;
    float* d_x = nullptr;
    cudaGetSymbolAddress((void**)&d_support, g_support);
    cudaGetSymbolAddress((void**)&d_x, g_x);

    const int Kdims[3] = { F_IN, F_HID, F_HID };
    const int Ndims[3] = { F_HID, F_HID, F_OUTD };

    for (int l = 0; l < 3; l++) {
        int K = Kdims[l], F = Ndims[l];
        const float* Ain = (l == 0) ? in_feature : d_x;

        // zero g_agg (N*F region) + colsum
        zero_kernel<<<2048, 256>>>(F);

        // support = Ain @ W
        dim3 ggrid((F + 127) / 128, (N_NODES + 127) / 128);
        sgemm_kernel<<<ggrid, 256>>>(Ain, W[l], d_support, N_NODES, K, F);

        // agg = spmm(adj, support)
        int shift = (F == 128) ? 5 : 4;
        long long tot = (long long)NNZ << shift;
        int sblocks = (int)((tot + 255) / 256);
        spmm_kernel<<<sblocks, 256>>>(adj_row, adj_col, adj_val, F, shift);

        // x = relu(agg + b), column sums
        int nblk = (N_NODES + BRC_ROWS - 1) / BRC_ROWS;
        bias_relu_colsum_kernel<<<nblk, F>>>(Bv[l], F);

        // pairnorm in place
        int pwarps = N_NODES;
        int pblocks = (pwarps * 32 + 255) / 256;
        pairnorm_kernel<<<pblocks, 256>>>(F);
    }

    // decode
    int dblocks = (N_EDGES * 32 + 255) / 256;
    decode_kernel<<<dblocks, 256>>>(pos_ei, neg_ei, out);
}

// round 2
// speedup vs baseline: 1.2163x; 1.2163x over previous
#include <cuda_runtime.h>
#include <cuda_bf16.h>
#include <math.h>

#define N_NODES 100000
#define NNZ     1000000
#define F_IN    1433
#define F_HID   128
#define F_OUTD  64
#define N_EDGES 40000
#define EPSV    1e-6f

// -------- static device scratch (no allocation allowed) --------
__device__ float g_support[(size_t)N_NODES * F_HID];
__device__ float g_agg[(size_t)N_NODES * F_HID];
__device__ float g_x[(size_t)N_NODES * F_HID];
__device__ float g_colsum[F_HID];

// -------- zero agg + colsum --------
__global__ void zero_kernel(int F) {
    size_t n4 = ((size_t)N_NODES * F) >> 2;
    size_t stride = (size_t)gridDim.x * blockDim.x;
    float4 z = make_float4(0.f, 0.f, 0.f, 0.f);
    float4* p = (float4*)g_agg;
    for (size_t i = (size_t)blockIdx.x * blockDim.x + threadIdx.x; i < n4; i += stride)
        p[i] = z;
    size_t t = (size_t)blockIdx.x * blockDim.x + threadIdx.x;
    if (t < F_HID) g_colsum[t] = 0.f;
}

// ============ Tensor-core GEMM: C = A @ B (fp32 in/out), bf16 hi/lo split ============
// Block tile 128(M) x 128(N), BK=32, 8 warps (4x2), warp tile 32x64.
// Each logical mma is 3x mma.sync.m16n8k16.bf16: Ah*Bh + Ah*Bl + Al*Bh.
#define BM 128
#define BN 128
#define BK 32
#define BKP (BK + 2)

__device__ __forceinline__ void mma16816(float c[4], const unsigned a[4], const unsigned b[2]) {
    asm volatile(
        "mma.sync.aligned.m16n8k16.row.col.f32.bf16.bf16.f32 "
        "{%0,%1,%2,%3}, {%4,%5,%6,%7}, {%8,%9}, {%0,%1,%2,%3};"
        : "+f"(c[0]), "+f"(c[1]), "+f"(c[2]), "+f"(c[3])
        : "r"(a[0]), "r"(a[1]), "r"(a[2]), "r"(a[3]), "r"(b[0]), "r"(b[1]));
}

__global__ __launch_bounds__(256) void gemm_bf16x_kernel(
    const float* __restrict__ A, const float* __restrict__ B,
    float* __restrict__ C, int M, int K, int N)
{
    __shared__ __align__(16) __nv_bfloat16 Ah[BM][BKP];
    __shared__ __align__(16) __nv_bfloat16 Al[BM][BKP];
    __shared__ __align__(16) __nv_bfloat16 Bh[BN][BKP];
    __shared__ __align__(16) __nv_bfloat16 Bl[BN][BKP];

    const int tid  = threadIdx.x;
    const int wid  = tid >> 5;
    const int lane = tid & 31;
    const int bm   = blockIdx.y * BM;
    const int g    = lane >> 2;     // 0..7
    const int qt   = lane & 3;      // 0..3
    const int warp_m = (wid >> 1) * 32;
    const int warp_n = (wid & 1) * 64;

    float acc[2][8][4];
#pragma unroll
    for (int mi = 0; mi < 2; mi++)
#pragma unroll
        for (int ni = 0; ni < 8; ni++)
#pragma unroll
            for (int q = 0; q < 4; q++) acc[mi][ni][q] = 0.f;

    for (int k0 = 0; k0 < K; k0 += BK) {
        __syncthreads();   // protect smem from previous iteration's readers

        // ---- load + split A tile: rows bm..bm+127, cols k0..k0+31 (lane = k) ----
#pragma unroll
        for (int p = 0; p < 16; p++) {
            int r = wid * 16 + p;        // 0..127
            int m = bm + r;
            int k = k0 + lane;
            float v = 0.f;
            if (m < M && k < K) v = __ldg(&A[(size_t)m * K + k]);
            __nv_bfloat16 h = __float2bfloat16(v);
            Ah[r][lane] = h;
            Al[r][lane] = __float2bfloat16(v - __bfloat162float(h));
        }
        // ---- load + split B tile: rows k0..k0+31, cols 0..127, store transposed ----
#pragma unroll
        for (int p = 0; p < 16; p++) {
            int idx = p * 256 + tid;
            int kk  = idx >> 7;          // 0..31
            int n   = idx & 127;
            int k   = k0 + kk;
            float v = 0.f;
            if (k < K && n < N) v = __ldg(&B[(size_t)k * N + n]);
            __nv_bfloat16 h = __float2bfloat16(v);
            Bh[n][kk] = h;
            Bl[n][kk] = __float2bfloat16(v - __bfloat162float(h));
        }
        __syncthreads();

        // ---- compute: two k16 halves ----
#pragma unroll
        for (int kh = 0; kh < BK; kh += 16) {
            unsigned ah[2][4], al[2][4];
#pragma unroll
            for (int mi = 0; mi < 2; mi++) {
                int r0 = warp_m + mi * 16;
                ah[mi][0] = *(const unsigned*)&Ah[r0 + g    ][kh + 2 * qt];
                ah[mi][1] = *(const unsigned*)&Ah[r0 + 8 + g][kh + 2 * qt];
                ah[mi][2] = *(const unsigned*)&Ah[r0 + g    ][kh + 8 + 2 * qt];
                ah[mi][3] = *(const unsigned*)&Ah[r0 + 8 + g][kh + 8 + 2 * qt];
                al[mi][0] = *(const unsigned*)&Al[r0 + g    ][kh + 2 * qt];
                al[mi][1] = *(const unsigned*)&Al[r0 + 8 + g][kh + 2 * qt];
                al[mi][2] = *(const unsigned*)&Al[r0 + g    ][kh + 8 + 2 * qt];
                al[mi][3] = *(const unsigned*)&Al[r0 + 8 + g][kh + 8 + 2 * qt];
            }
#pragma unroll
            for (int ni = 0; ni < 8; ni++) {
                int c0 = warp_n + ni * 8 + g;
                unsigned bh[2], bl[2];
                bh[0] = *(const unsigned*)&Bh[c0][kh + 2 * qt];
                bh[1] = *(const unsigned*)&Bh[c0][kh + 8 + 2 * qt];
                bl[0] = *(const unsigned*)&Bl[c0][kh + 2 * qt];
                bl[1] = *(const unsigned*)&Bl[c0][kh + 8 + 2 * qt];
#pragma unroll
                for (int mi = 0; mi < 2; mi++) {
                    mma16816(acc[mi][ni], ah[mi], bh);
                    mma16816(acc[mi][ni], ah[mi], bl);
                    mma16816(acc[mi][ni], al[mi], bh);
                }
            }
        }
    }

    // ---- store C ----
#pragma unroll
    for (int mi = 0; mi < 2; mi++) {
#pragma unroll
        for (int ni = 0; ni < 8; ni++) {
            int row0 = bm + warp_m + mi * 16 + g;
            int col  = warp_n + ni * 8 + 2 * qt;
            if (col < N) {
                if (row0 < M)
                    *(float2*)&C[(size_t)row0 * N + col] =
                        make_float2(acc[mi][ni][0], acc[mi][ni][1]);
                if (row0 + 8 < M)
                    *(float2*)&C[(size_t)(row0 + 8) * N + col] =
                        make_float2(acc[mi][ni][2], acc[mi][ni][3]);
            }
        }
    }
}

// -------- SpMM: g_agg[row] += val * g_support[col], atomic scatter --------
__global__ void spmm_kernel(const int* __restrict__ row, const int* __restrict__ col,
                            const float* __restrict__ val, int F, int shift) {
    long long t = (long long)blockIdx.x * blockDim.x + threadIdx.x;
    int tpe = 1 << shift;
    long long total = (long long)NNZ * tpe;
    if (t >= total) return;
    int e  = (int)(t >> shift);
    int f4 = ((int)t & (tpe - 1)) << 2;
    int r = row[e];
    int c = col[e];
    float v = val[e];
    float4 s = *(const float4*)&g_support[(size_t)c * F + f4];
    float* dst = &g_agg[(size_t)r * F + f4];
    atomicAdd(dst + 0, v * s.x);
    atomicAdd(dst + 1, v * s.y);
    atomicAdd(dst + 2, v * s.z);
    atomicAdd(dst + 3, v * s.w);
}

// -------- bias + relu + column-sum (partials via atomics) --------
#define BRC_ROWS 100
__global__ void bias_relu_colsum_kernel(const float* __restrict__ bias, int F) {
    int f = threadIdx.x;            // blockDim.x == F
    int r0 = blockIdx.x * BRC_ROWS;
    float b = bias[f];
    float sum = 0.f;
#pragma unroll 4
    for (int i = 0; i < BRC_ROWS; i++) {
        int r = r0 + i;
        if (r >= N_NODES) break;
        float y = g_agg[(size_t)r * F + f] + b;
        y = fmaxf(y, 0.f);
        g_x[(size_t)r * F + f] = y;
        sum += y;
    }
    atomicAdd(&g_colsum[f], sum);
}

// -------- PairNorm (PN-SI): subtract col mean, per-row L2 normalize --------
__global__ void pairnorm_kernel(int F) {
    int gwarp = ((int)blockIdx.x * blockDim.x + threadIdx.x) >> 5;
    int lane = threadIdx.x & 31;
    if (gwarp >= N_NODES) return;
    int nf = F >> 5;
    float vals[4];
    float ss = 0.f;
#pragma unroll
    for (int j = 0; j < 4; j++) {
        if (j < nf) {
            int f = lane + (j << 5);
            float v = g_x[(size_t)gwarp * F + f] - g_colsum[f] * (1.0f / N_NODES);
            vals[j] = v;
            ss += v * v;
        }
    }
#pragma unroll
    for (int o = 16; o > 0; o >>= 1) ss += __shfl_xor_sync(0xffffffffu, ss, o);
    float inv = rsqrtf(EPSV + ss);
#pragma unroll
    for (int j = 0; j < 4; j++) {
        if (j < nf) {
            int f = lane + (j << 5);
            g_x[(size_t)gwarp * F + f] = vals[j] * inv;
        }
    }
}

// -------- decode: sigmoid(dot(x[a], x[b])), warp per edge, F=64 --------
__global__ void decode_kernel(const int* __restrict__ pos, const int* __restrict__ neg,
                              float* __restrict__ out) {
    int gwarp = ((int)blockIdx.x * blockDim.x + threadIdx.x) >> 5;
    int lane = threadIdx.x & 31;
    if (gwarp >= N_EDGES) return;
    const int* ei = (gwarp < 20000) ? (pos + (size_t)gwarp * 2)
                                    : (neg + (size_t)(gwarp - 20000) * 2);
    int a = ei[0];
    int b = ei[1];
    const float* xa = &g_x[(size_t)a * F_OUTD];
    const float* xb = &g_x[(size_t)b * F_OUTD];
    float s = xa[lane] * xb[lane] + xa[lane + 32] * xb[lane + 32];
#pragma unroll
    for (int o = 16; o > 0; o >>= 1) s += __shfl_xor_sync(0xffffffffu, s, o);
    if (lane == 0) out[gwarp] = 1.0f / (1.0f + expf(-s));
}

// ---------------------------------------------------------------
extern "C" void kernel_launch(void* const* d_in, const int* in_sizes, int n_in,
                              void* d_out, int out_size) {
    const float* in_feature = (const float*)d_in[0];
    const int*   adj_row    = (const int*)d_in[1];
    const int*   adj_col    = (const int*)d_in[2];
    const float* adj_val    = (const float*)d_in[3];
    const int*   pos_ei     = (const int*)d_in[4];
    const int*   neg_ei     = (const int*)d_in[5];
    const float* W[3] = { (const float*)d_in[6], (const float*)d_in[8], (const float*)d_in[10] };
    const float* Bv[3] = { (const float*)d_in[7], (const float*)d_in[9], (const float*)d_in[11] };
    float* out = (float*)d_out;

    float* d_support = nullptr;
    float* d_x = nullptr;
    cudaGetSymbolAddress((void**)&d_support, g_support);
    cudaGetSymbolAddress((void**)&d_x, g_x);

    const int Kdims[3] = { F_IN, F_HID, F_HID };
    const int Ndims[3] = { F_HID, F_HID, F_OUTD };

    for (int l = 0; l < 3; l++) {
        int K = Kdims[l], F = Ndims[l];
        const float* Ain = (l == 0) ? in_feature : d_x;

        zero_kernel<<<2048, 256>>>(F);

        dim3 ggrid(1, (N_NODES + BM - 1) / BM);
        gemm_bf16x_kernel<<<ggrid, 256>>>(Ain, W[l], d_support, N_NODES, K, F);

        int shift = (F == 128) ? 5 : 4;
        long long tot = (long long)NNZ << shift;
        int sblocks = (int)((tot + 255) / 256);
        spmm_kernel<<<sblocks, 256>>>(adj_row, adj_col, adj_val, F, shift);

        int nblk = (N_NODES + BRC_ROWS - 1) / BRC_ROWS;
        bias_relu_colsum_kernel<<<nblk, F>>>(Bv[l], F);

        int pblocks = (N_NODES * 32 + 255) / 256;
        pairnorm_kernel<<<pblocks, 256>>>(F);
    }

    int dblocks = (N_EDGES * 32 + 255) / 256;
    decode_kernel<<<dblocks, 256>>>(pos_ei, neg_ei, out);
}

// round 3
// speedup vs baseline: 2.0496x; 1.6851x over previous
#include <cuda_runtime.h>
#include <cuda_bf16.h>
#include <math.h>

#define N_NODES 100000
#define NNZ     1000000
#define F_IN    1433
#define F_HID   128
#define F_OUTD  64
#define N_EDGES 40000
#define EPSV    1e-6f
#define KPAD_MAX 1440

// -------- static device scratch --------
__device__ float g_support[(size_t)N_NODES * F_HID];
__device__ float g_agg[(size_t)N_NODES * F_HID];
__device__ float g_x[(size_t)N_NODES * F_HID];
__device__ float g_colsum[F_HID];
__device__ __nv_bfloat16 g_Xh[(size_t)N_NODES * F_HID];
__device__ __nv_bfloat16 g_Xl[(size_t)N_NODES * F_HID];
__device__ __nv_bfloat16 g_Wth[(size_t)128 * KPAD_MAX];
__device__ __nv_bfloat16 g_Wtl[(size_t)128 * KPAD_MAX];

__device__ __forceinline__ unsigned pack2(float f0, float f1) {
    unsigned r;
    asm("cvt.rn.bf16x2.f32 %0, %1, %2;" : "=r"(r) : "f"(f1), "f"(f0));
    return r;  // low half = f0
}

// -------- zero agg + colsum --------
__global__ void zero_kernel(int F) {
    size_t n4 = ((size_t)N_NODES * F) >> 2;
    size_t stride = (size_t)gridDim.x * blockDim.x;
    float4 z = make_float4(0.f, 0.f, 0.f, 0.f);
    float4* p = (float4*)g_agg;
    for (size_t i = (size_t)blockIdx.x * blockDim.x + threadIdx.x; i < n4; i += stride)
        p[i] = z;
    size_t t = (size_t)blockIdx.x * blockDim.x + threadIdx.x;
    if (t < F_HID) g_colsum[t] = 0.f;
}

// -------- split + transpose W: Wt[n][k] bf16 hi/lo planes, zero-padded --------
__global__ void splitW_kernel(const float* __restrict__ W, int K, int N, int Kpadl) {
    int oct = Kpadl >> 3;
    int u = blockIdx.x * blockDim.x + threadIdx.x;
    if (u >= 128 * oct) return;
    int n = u / oct;
    int k0 = (u - n * oct) << 3;
    float v[8];
#pragma unroll
    for (int e = 0; e < 8; e++) {
        int k = k0 + e;
        v[e] = (k < K && n < N) ? __ldg(&W[(size_t)k * N + n]) : 0.f;
    }
    unsigned hh[4], ll[4];
#pragma unroll
    for (int p = 0; p < 4; p++) {
        unsigned h = pack2(v[2 * p], v[2 * p + 1]);
        float h0 = __uint_as_float(h << 16);
        float h1 = __uint_as_float(h & 0xffff0000u);
        hh[p] = h;
        ll[p] = pack2(v[2 * p] - h0, v[2 * p + 1] - h1);
    }
    *(uint4*)&g_Wth[(size_t)n * KPAD_MAX + k0] = make_uint4(hh[0], hh[1], hh[2], hh[3]);
    *(uint4*)&g_Wtl[(size_t)n * KPAD_MAX + k0] = make_uint4(ll[0], ll[1], ll[2], ll[3]);
}

// ============ Tensor-core GEMM, bf16 hi/lo 3-term ============
#define BM 128
#define BN 128
#define BK 32
#define BKP 40   // pad to 80B rows: 16B-aligned STS.128, conflict-free LDS

__device__ __forceinline__ void mma16816(float c[4], const unsigned a[4], const unsigned b[2]) {
    asm volatile(
        "mma.sync.aligned.m16n8k16.row.col.f32.bf16.bf16.f32 "
        "{%0,%1,%2,%3}, {%4,%5,%6,%7}, {%8,%9}, {%0,%1,%2,%3};"
        : "+f"(c[0]), "+f"(c[1]), "+f"(c[2]), "+f"(c[3])
        : "r"(a[0]), "r"(a[1]), "r"(a[2]), "r"(a[3]), "r"(b[0]), "r"(b[1]));
}

// AMODE 0: A fp32, convert in-kernel. AMODE 1: A bf16 planes (Aph/Apl, stride lda).
template <int AMODE>
__global__ __launch_bounds__(256) void gemm_tc_kernel(
    const float* __restrict__ A,
    const __nv_bfloat16* __restrict__ Aph, const __nv_bfloat16* __restrict__ Apl,
    float* __restrict__ C, int M, int K, int Kpad, int lda, int N)
{
    __shared__ __align__(16) __nv_bfloat16 Ah[BM][BKP];
    __shared__ __align__(16) __nv_bfloat16 Al[BM][BKP];
    __shared__ __align__(16) __nv_bfloat16 Bh[BN][BKP];
    __shared__ __align__(16) __nv_bfloat16 Bl[BN][BKP];

    const int tid  = threadIdx.x;
    const int wid  = tid >> 5;
    const int lane = tid & 31;
    const int bm   = blockIdx.y * BM;
    const int g    = lane >> 2;
    const int qt   = lane & 3;
    const int warp_m = (wid >> 1) * 32;
    const int warp_n = (wid & 1) * 64;

    float acc[2][8][4];
#pragma unroll
    for (int mi = 0; mi < 2; mi++)
#pragma unroll
        for (int ni = 0; ni < 8; ni++)
#pragma unroll
            for (int q = 0; q < 4; q++) acc[mi][ni][q] = 0.f;

    const int lr = tid >> 1;            // 0..127 (row for bf16/B loads)
    const int lho = (tid & 1) << 4;     // 0 or 16 (half offset)

    for (int k0 = 0; k0 < Kpad; k0 += BK) {
        __syncthreads();

        // ---- A tile ----
        if (AMODE == 0) {
#pragma unroll
            for (int u2 = 0; u2 < 2; u2++) {
                int u = tid + u2 * 256;       // 0..511
                int r = u >> 2;
                int o = (u & 3) << 3;         // 0,8,16,24
                int m = bm + r;
                float v[8];
#pragma unroll
                for (int e = 0; e < 8; e++) {
                    int k = k0 + o + e;
                    v[e] = (m < M && k < K) ? __ldg(&A[(size_t)m * K + k]) : 0.f;
                }
                unsigned hh[4], ll[4];
#pragma unroll
                for (int p = 0; p < 4; p++) {
                    unsigned h = pack2(v[2 * p], v[2 * p + 1]);
                    float h0 = __uint_as_float(h << 16);
                    float h1 = __uint_as_float(h & 0xffff0000u);
                    hh[p] = h;
                    ll[p] = pack2(v[2 * p] - h0, v[2 * p + 1] - h1);
                }
                *(uint4*)&Ah[r][o] = make_uint4(hh[0], hh[1], hh[2], hh[3]);
                *(uint4*)&Al[r][o] = make_uint4(ll[0], ll[1], ll[2], ll[3]);
            }
        } else {
            int m = bm + lr;
            uint4 z4 = make_uint4(0u, 0u, 0u, 0u);
            const __nv_bfloat16* sh = Aph + (size_t)m * lda + k0 + lho;
            const __nv_bfloat16* sl = Apl + (size_t)m * lda + k0 + lho;
            bool ok = m < M;
            uint4 a0 = ok ? *(const uint4*)sh       : z4;
            uint4 a1 = ok ? *(const uint4*)(sh + 8) : z4;
            uint4 b0 = ok ? *(const uint4*)sl       : z4;
            uint4 b1 = ok ? *(const uint4*)(sl + 8) : z4;
            *(uint4*)&Ah[lr][lho]     = a0;
            *(uint4*)&Ah[lr][lho + 8] = a1;
            *(uint4*)&Al[lr][lho]     = b0;
            *(uint4*)&Al[lr][lho + 8] = b1;
        }

        // ---- B tile from pre-split transposed W planes ----
        {
            const __nv_bfloat16* sh = &g_Wth[(size_t)lr * KPAD_MAX + k0 + lho];
            const __nv_bfloat16* sl = &g_Wtl[(size_t)lr * KPAD_MAX + k0 + lho];
            uint4 b0 = *(const uint4*)sh;
            uint4 b1 = *(const uint4*)(sh + 8);
            uint4 c0 = *(const uint4*)sl;
            uint4 c1 = *(const uint4*)(sl + 8);
            *(uint4*)&Bh[lr][lho]     = b0;
            *(uint4*)&Bh[lr][lho + 8] = b1;
            *(uint4*)&Bl[lr][lho]     = c0;
            *(uint4*)&Bl[lr][lho + 8] = c1;
        }
        __syncthreads();

        // ---- compute ----
#pragma unroll
        for (int kh = 0; kh < BK; kh += 16) {
            unsigned ah[2][4], al[2][4];
#pragma unroll
            for (int mi = 0; mi < 2; mi++) {
                int r0 = warp_m + mi * 16;
                ah[mi][0] = *(const unsigned*)&Ah[r0 + g    ][kh + 2 * qt];
                ah[mi][1] = *(const unsigned*)&Ah[r0 + 8 + g][kh + 2 * qt];
                ah[mi][2] = *(const unsigned*)&Ah[r0 + g    ][kh + 8 + 2 * qt];
                ah[mi][3] = *(const unsigned*)&Ah[r0 + 8 + g][kh + 8 + 2 * qt];
                al[mi][0] = *(const unsigned*)&Al[r0 + g    ][kh + 2 * qt];
                al[mi][1] = *(const unsigned*)&Al[r0 + 8 + g][kh + 2 * qt];
                al[mi][2] = *(const unsigned*)&Al[r0 + g    ][kh + 8 + 2 * qt];
                al[mi][3] = *(const unsigned*)&Al[r0 + 8 + g][kh + 8 + 2 * qt];
            }
#pragma unroll
            for (int ni = 0; ni < 8; ni++) {
                int c0i = warp_n + ni * 8 + g;
                unsigned bh[2], bl[2];
                bh[0] = *(const unsigned*)&Bh[c0i][kh + 2 * qt];
                bh[1] = *(const unsigned*)&Bh[c0i][kh + 8 + 2 * qt];
                bl[0] = *(const unsigned*)&Bl[c0i][kh + 2 * qt];
                bl[1] = *(const unsigned*)&Bl[c0i][kh + 8 + 2 * qt];
#pragma unroll
                for (int mi = 0; mi < 2; mi++) {
                    mma16816(acc[mi][ni], ah[mi], bh);
                    mma16816(acc[mi][ni], ah[mi], bl);
                    mma16816(acc[mi][ni], al[mi], bh);
                }
            }
        }
    }

    // ---- store C ----
#pragma unroll
    for (int mi = 0; mi < 2; mi++) {
#pragma unroll
        for (int ni = 0; ni < 8; ni++) {
            int row0 = bm + warp_m + mi * 16 + g;
            int col  = warp_n + ni * 8 + 2 * qt;
            if (col < N) {
                if (row0 < M)
                    *(float2*)&C[(size_t)row0 * N + col] =
                        make_float2(acc[mi][ni][0], acc[mi][ni][1]);
                if (row0 + 8 < M)
                    *(float2*)&C[(size_t)(row0 + 8) * N + col] =
                        make_float2(acc[mi][ni][2], acc[mi][ni][3]);
            }
        }
    }
}

// -------- SpMM: vectorized red.global.add.v4.f32, warp(-chunk) per edge --------
__global__ void spmm_v4_kernel(const int* __restrict__ row, const int* __restrict__ col,
                               const float* __restrict__ val, int F, int eshift) {
    long long t = (long long)blockIdx.x * blockDim.x + threadIdx.x;
    if (t >= ((long long)NNZ << eshift)) return;
    int e  = (int)(t >> eshift);
    int f4 = ((int)t & ((1 << eshift) - 1)) << 2;
    int r = row[e];
    int c = col[e];
    float v = val[e];
    float4 s = *(const float4*)&g_support[(size_t)c * F + f4];
    float* dst = &g_agg[(size_t)r * F + f4];
    asm volatile("red.global.add.v4.f32 [%0], {%1,%2,%3,%4};"
                 :: "l"(dst), "f"(v * s.x), "f"(v * s.y), "f"(v * s.z), "f"(v * s.w)
                 : "memory");
}

// -------- bias + relu + colsum: warp-per-row-group, float4, smem-staged sums --------
#define BR_ROWS 16
__global__ void bias_relu_colsum2_kernel(const float* __restrict__ bias, int F) {
    __shared__ float cs[F_HID];
    int tid = threadIdx.x;
    if (tid < F) cs[tid] = 0.f;
    __syncthreads();
    int lane = tid & 31;
    int gw = ((int)blockIdx.x * blockDim.x + tid) >> 5;
    int r0 = gw * BR_ROWS;
    if (lane * 4 < F && r0 < N_NODES) {
        float4 b = *(const float4*)&bias[lane * 4];
        float4 sum = make_float4(0.f, 0.f, 0.f, 0.f);
#pragma unroll 4
        for (int i = 0; i < BR_ROWS; i++) {
            int r = r0 + i;
            if (r >= N_NODES) break;
            float4 y = *(const float4*)&g_agg[(size_t)r * F + lane * 4];
            y.x = fmaxf(y.x + b.x, 0.f);
            y.y = fmaxf(y.y + b.y, 0.f);
            y.z = fmaxf(y.z + b.z, 0.f);
            y.w = fmaxf(y.w + b.w, 0.f);
            *(float4*)&g_x[(size_t)r * F + lane * 4] = y;
            sum.x += y.x; sum.y += y.y; sum.z += y.z; sum.w += y.w;
        }
        atomicAdd(&cs[lane * 4 + 0], sum.x);
        atomicAdd(&cs[lane * 4 + 1], sum.y);
        atomicAdd(&cs[lane * 4 + 2], sum.z);
        atomicAdd(&cs[lane * 4 + 3], sum.w);
    }
    __syncthreads();
    if (tid < F) atomicAdd(&g_colsum[tid], cs[tid]);
}

// -------- PairNorm F=128, fused bf16 hi/lo split output --------
__global__ void pairnorm128_split_kernel() {
    int gw = ((int)blockIdx.x * blockDim.x + threadIdx.x) >> 5;
    int lane = threadIdx.x & 31;
    if (gw >= N_NODES) return;
    const float invN = 1.0f / N_NODES;
    float4 mean = *(const float4*)&g_colsum[lane * 4];
    float4 v = *(const float4*)&g_x[(size_t)gw * F_HID + lane * 4];
    v.x -= mean.x * invN; v.y -= mean.y * invN;
    v.z -= mean.z * invN; v.w -= mean.w * invN;
    float ss = v.x * v.x + v.y * v.y + v.z * v.z + v.w * v.w;
#pragma unroll
    for (int o = 16; o > 0; o >>= 1) ss += __shfl_xor_sync(0xffffffffu, ss, o);
    float inv = rsqrtf(EPSV + ss);
    float y0 = v.x * inv, y1 = v.y * inv, y2 = v.z * inv, y3 = v.w * inv;
    unsigned h01 = pack2(y0, y1);
    unsigned h23 = pack2(y2, y3);
    float f0 = __uint_as_float(h01 << 16), f1 = __uint_as_float(h01 & 0xffff0000u);
    float f2 = __uint_as_float(h23 << 16), f3 = __uint_as_float(h23 & 0xffff0000u);
    unsigned l01 = pack2(y0 - f0, y1 - f1);
    unsigned l23 = pack2(y2 - f2, y3 - f3);
    *(uint2*)&g_Xh[(size_t)gw * F_HID + lane * 4] = make_uint2(h01, h23);
    *(uint2*)&g_Xl[(size_t)gw * F_HID + lane * 4] = make_uint2(l01, l23);
}

// -------- PairNorm generic (F=64, fp32 in-place for decode) --------
__global__ void pairnorm_kernel(int F) {
    int gwarp = ((int)blockIdx.x * blockDim.x + threadIdx.x) >> 5;
    int lane = threadIdx.x & 31;
    if (gwarp >= N_NODES) return;
    int nf = F >> 5;
    float vals[4];
    float ss = 0.f;
#pragma unroll
    for (int j = 0; j < 4; j++) {
        if (j < nf) {
            int f = lane + (j << 5);
            float v = g_x[(size_t)gwarp * F + f] - g_colsum[f] * (1.0f / N_NODES);
            vals[j] = v;
            ss += v * v;
        }
    }
#pragma unroll
    for (int o = 16; o > 0; o >>= 1) ss += __shfl_xor_sync(0xffffffffu, ss, o);
    float inv = rsqrtf(EPSV + ss);
#pragma unroll
    for (int j = 0; j < 4; j++) {
        if (j < nf) {
            int f = lane + (j << 5);
            g_x[(size_t)gwarp * F + f] = vals[j] * inv;
        }
    }
}

// -------- decode --------
__global__ void decode_kernel(const int* __restrict__ pos, const int* __restrict__ neg,
                              float* __restrict__ out) {
    int gwarp = ((int)blockIdx.x * blockDim.x + threadIdx.x) >> 5;
    int lane = threadIdx.x & 31;
    if (gwarp >= N_EDGES) return;
    const int* ei = (gwarp < 20000) ? (pos + (size_t)gwarp * 2)
                                    : (neg + (size_t)(gwarp - 20000) * 2);
    int a = ei[0];
    int b = ei[1];
    const float* xa = &g_x[(size_t)a * F_OUTD];
    const float* xb = &g_x[(size_t)b * F_OUTD];
    float s = xa[lane] * xb[lane] + xa[lane + 32] * xb[lane + 32];
#pragma unroll
    for (int o = 16; o > 0; o >>= 1) s += __shfl_xor_sync(0xffffffffu, s, o);
    if (lane == 0) out[gwarp] = 1.0f / (1.0f + expf(-s));
}

// ---------------------------------------------------------------
extern "C" void kernel_launch(void* const* d_in, const int* in_sizes, int n_in,
                              void* d_out, int out_size) {
    const float* in_feature = (const float*)d_in[0];
    const int*   adj_row    = (const int*)d_in[1];
    const int*   adj_col    = (const int*)d_in[2];
    const float* adj_val    = (const float*)d_in[3];
    const int*   pos_ei     = (const int*)d_in[4];
    const int*   neg_ei     = (const int*)d_in[5];
    const float* W[3] = { (const float*)d_in[6], (const float*)d_in[8], (const float*)d_in[10] };
    const float* Bv[3] = { (const float*)d_in[7], (const float*)d_in[9], (const float*)d_in[11] };
    float* out = (float*)d_out;

    float* d_support = nullptr;
    float* d_x = nullptr;
    __nv_bfloat16 *d_Xh = nullptr, *d_Xl = nullptr;
    cudaGetSymbolAddress((void**)&d_support, g_support);
    cudaGetSymbolAddress((void**)&d_x, g_x);
    cudaGetSymbolAddress((void**)&d_Xh, g_Xh);
    cudaGetSymbolAddress((void**)&d_Xl, g_Xl);

    const int Kdims[3] = { F_IN, F_HID, F_HID };
    const int Ndims[3] = { F_HID, F_HID, F_OUTD };

    for (int l = 0; l < 3; l++) {
        int K = Kdims[l], F = Ndims[l];
        int Kpadl = (K + 31) & ~31;

        zero_kernel<<<2048, 256>>>(F);

        // split + transpose W into bf16 planes
        int wunits = 128 * (Kpadl >> 3);
        splitW_kernel<<<(wunits + 255) / 256, 256>>>(W[l], K, F, Kpadl);

        dim3 ggrid(1, (N_NODES + BM - 1) / BM);
        if (l == 0)
            gemm_tc_kernel<0><<<ggrid, 256>>>(in_feature, nullptr, nullptr,
                                              d_support, N_NODES, K, Kpadl, 0, F);
        else
            gemm_tc_kernel<1><<<ggrid, 256>>>(nullptr, d_Xh, d_Xl,
                                              d_support, N_NODES, K, Kpadl, F_HID, F);

        int eshift = (F == 128) ? 5 : 4;
        long long tot = (long long)NNZ << eshift;
        spmm_v4_kernel<<<(int)((tot + 255) / 256), 256>>>(adj_row, adj_col, adj_val, F, eshift);

        int nwarps = (N_NODES + BR_ROWS - 1) / BR_ROWS;
        bias_relu_colsum2_kernel<<<(nwarps * 32 + 255) / 256, 256>>>(Bv[l], F);

        if (l < 2) {
            pairnorm128_split_kernel<<<(N_NODES * 32 + 255) / 256, 256>>>();
        } else {
            pairnorm_kernel<<<(N_NODES * 32 + 255) / 256, 256>>>(F);
        }
    }

    int dblocks = (N_EDGES * 32 + 255) / 256;
    decode_kernel<<<dblocks, 256>>>(pos_ei, neg_ei, out);
}

// round 4
// speedup vs baseline: 2.5414x; 1.2399x over previous
#include <cuda_runtime.h>
#include <cuda_bf16.h>
#include <math.h>

#define N_NODES 100000
#define NNZ     1000000
#define F_IN    1433
#define F_HID   128
#define F_OUTD  64
#define N_EDGES 40000
#define EPSV    1e-6f
#define KPAD_MAX 1440
#define SCAN_BLK 1024
#define NBLK_SCAN ((N_NODES + SCAN_BLK - 1) / SCAN_BLK)   // 98

// -------- static device scratch --------
__device__ float g_support[(size_t)N_NODES * F_HID];
__device__ float g_x[(size_t)N_NODES * F_HID];
__device__ float g_colsum[F_HID];
__device__ __nv_bfloat16 g_Xh[(size_t)N_NODES * F_HID];
__device__ __nv_bfloat16 g_Xl[(size_t)N_NODES * F_HID];
__device__ __nv_bfloat16 g_Wth[(size_t)128 * KPAD_MAX];
__device__ __nv_bfloat16 g_Wtl[(size_t)128 * KPAD_MAX];
// CSR
__device__ int  g_rowcnt[N_NODES];
__device__ int  g_rowoff[N_NODES + 1];
__device__ int  g_blksum[128];
__device__ int2 g_epack[NNZ];    // (col, bitcast val)

__device__ __forceinline__ unsigned pack2(float f0, float f1) {
    unsigned r;
    asm("cvt.rn.bf16x2.f32 %0, %1, %2;" : "=r"(r) : "f"(f1), "f"(f0));
    return r;
}

// ================= CSR build =================
__global__ void csr_zero_kernel() {
    int i = blockIdx.x * blockDim.x + threadIdx.x;
    if (i < N_NODES) g_rowcnt[i] = 0;
}
__global__ void csr_hist_kernel(const int* __restrict__ row) {
    int e = blockIdx.x * blockDim.x + threadIdx.x;
    if (e < NNZ) atomicAdd(&g_rowcnt[row[e]], 1);
}
__global__ __launch_bounds__(SCAN_BLK) void csr_scanA_kernel() {
    __shared__ int sm[SCAN_BLK];
    int t = threadIdx.x;
    int i = blockIdx.x * SCAN_BLK + t;
    int v = (i < N_NODES) ? g_rowcnt[i] : 0;
    sm[t] = v;
    __syncthreads();
#pragma unroll
    for (int s = 1; s < SCAN_BLK; s <<= 1) {
        int a = (t >= s) ? sm[t - s] : 0;
        __syncthreads();
        sm[t] += a;
        __syncthreads();
    }
    if (i < N_NODES) g_rowoff[i] = sm[t] - v;   // exclusive within block
    if (t == SCAN_BLK - 1) g_blksum[blockIdx.x] = sm[t];
}
__global__ void csr_scanB_kernel() {    // single block, 128 threads
    __shared__ int sm[128];
    int t = threadIdx.x;
    int v = (t < NBLK_SCAN) ? g_blksum[t] : 0;
    sm[t] = v;
    __syncthreads();
#pragma unroll
    for (int s = 1; s < 128; s <<= 1) {
        int a = (t >= s) ? sm[t - s] : 0;
        __syncthreads();
        sm[t] += a;
        __syncthreads();
    }
    g_blksum[t] = sm[t] - v;            // exclusive
}
__global__ void csr_scanC_kernel() {
    int i = blockIdx.x * blockDim.x + threadIdx.x;
    if (i < N_NODES) {
        g_rowoff[i] += g_blksum[i >> 10];
        g_rowcnt[i] = 0;                // reuse as scatter cursor
    }
    if (i == 0) g_rowoff[N_NODES] = NNZ;
}
__global__ void csr_scatter_kernel(const int* __restrict__ row, const int* __restrict__ col,
                                   const float* __restrict__ val) {
    int e = blockIdx.x * blockDim.x + threadIdx.x;
    if (e >= NNZ) return;
    int r = row[e];
    int p = g_rowoff[r] + atomicAdd(&g_rowcnt[r], 1);
    g_epack[p] = make_int2(col[e], __float_as_int(val[e]));
}

// -------- zero colsum --------
__global__ void zero_colsum_kernel() {
    if (threadIdx.x < F_HID) g_colsum[threadIdx.x] = 0.f;
}

// -------- split + transpose W --------
__global__ void splitW_kernel(const float* __restrict__ W, int K, int N, int Kpadl) {
    int oct = Kpadl >> 3;
    int u = blockIdx.x * blockDim.x + threadIdx.x;
    if (u >= 128 * oct) return;
    int n = u / oct;
    int k0 = (u - n * oct) << 3;
    float v[8];
#pragma unroll
    for (int e = 0; e < 8; e++) {
        int k = k0 + e;
        v[e] = (k < K && n < N) ? __ldg(&W[(size_t)k * N + n]) : 0.f;
    }
    unsigned hh[4], ll[4];
#pragma unroll
    for (int p = 0; p < 4; p++) {
        unsigned h = pack2(v[2 * p], v[2 * p + 1]);
        float h0 = __uint_as_float(h << 16);
        float h1 = __uint_as_float(h & 0xffff0000u);
        hh[p] = h;
        ll[p] = pack2(v[2 * p] - h0, v[2 * p + 1] - h1);
    }
    *(uint4*)&g_Wth[(size_t)n * KPAD_MAX + k0] = make_uint4(hh[0], hh[1], hh[2], hh[3]);
    *(uint4*)&g_Wtl[(size_t)n * KPAD_MAX + k0] = make_uint4(ll[0], ll[1], ll[2], ll[3]);
}

// ============ Tensor-core GEMM, bf16 hi/lo 3-term ============
#define BM 128
#define BN 128
#define BK 32
#define BKP 40

__device__ __forceinline__ void mma16816(float c[4], const unsigned a[4], const unsigned b[2]) {
    asm volatile(
        "mma.sync.aligned.m16n8k16.row.col.f32.bf16.bf16.f32 "
        "{%0,%1,%2,%3}, {%4,%5,%6,%7}, {%8,%9}, {%0,%1,%2,%3};"
        : "+f"(c[0]), "+f"(c[1]), "+f"(c[2]), "+f"(c[3])
        : "r"(a[0]), "r"(a[1]), "r"(a[2]), "r"(a[3]), "r"(b[0]), "r"(b[1]));
}

template <int AMODE>
__global__ __launch_bounds__(256) void gemm_tc_kernel(
    const float* __restrict__ A,
    const __nv_bfloat16* __restrict__ Aph, const __nv_bfloat16* __restrict__ Apl,
    float* __restrict__ C, int M, int K, int Kpad, int lda, int N)
{
    __shared__ __align__(16) __nv_bfloat16 Ah[BM][BKP];
    __shared__ __align__(16) __nv_bfloat16 Al[BM][BKP];
    __shared__ __align__(16) __nv_bfloat16 Bh[BN][BKP];
    __shared__ __align__(16) __nv_bfloat16 Bl[BN][BKP];

    const int tid  = threadIdx.x;
    const int wid  = tid >> 5;
    const int lane = tid & 31;
    const int bm   = blockIdx.y * BM;
    const int g    = lane >> 2;
    const int qt   = lane & 3;
    const int warp_m = (wid >> 1) * 32;
    const int warp_n = (wid & 1) * 64;

    float acc[2][8][4];
#pragma unroll
    for (int mi = 0; mi < 2; mi++)
#pragma unroll
        for (int ni = 0; ni < 8; ni++)
#pragma unroll
            for (int q = 0; q < 4; q++) acc[mi][ni][q] = 0.f;

    const int lr = tid >> 1;
    const int lho = (tid & 1) << 4;

    for (int k0 = 0; k0 < Kpad; k0 += BK) {
        __syncthreads();

        if (AMODE == 0) {
#pragma unroll
            for (int u2 = 0; u2 < 2; u2++) {
                int u = tid + u2 * 256;
                int r = u >> 2;
                int o = (u & 3) << 3;
                int m = bm + r;
                float v[8];
#pragma unroll
                for (int e = 0; e < 8; e++) {
                    int k = k0 + o + e;
                    v[e] = (m < M && k < K) ? __ldg(&A[(size_t)m * K + k]) : 0.f;
                }
                unsigned hh[4], ll[4];
#pragma unroll
                for (int p = 0; p < 4; p++) {
                    unsigned h = pack2(v[2 * p], v[2 * p + 1]);
                    float h0 = __uint_as_float(h << 16);
                    float h1 = __uint_as_float(h & 0xffff0000u);
                    hh[p] = h;
                    ll[p] = pack2(v[2 * p] - h0, v[2 * p + 1] - h1);
                }
                *(uint4*)&Ah[r][o] = make_uint4(hh[0], hh[1], hh[2], hh[3]);
                *(uint4*)&Al[r][o] = make_uint4(ll[0], ll[1], ll[2], ll[3]);
            }
        } else {
            int m = bm + lr;
            uint4 z4 = make_uint4(0u, 0u, 0u, 0u);
            const __nv_bfloat16* sh = Aph + (size_t)m * lda + k0 + lho;
            const __nv_bfloat16* sl = Apl + (size_t)m * lda + k0 + lho;
            bool ok = m < M;
            uint4 a0 = ok ? *(const uint4*)sh       : z4;
            uint4 a1 = ok ? *(const uint4*)(sh + 8) : z4;
            uint4 b0 = ok ? *(const uint4*)sl       : z4;
            uint4 b1 = ok ? *(const uint4*)(sl + 8) : z4;
            *(uint4*)&Ah[lr][lho]     = a0;
            *(uint4*)&Ah[lr][lho + 8] = a1;
            *(uint4*)&Al[lr][lho]     = b0;
            *(uint4*)&Al[lr][lho + 8] = b1;
        }

        {
            const __nv_bfloat16* sh = &g_Wth[(size_t)lr * KPAD_MAX + k0 + lho];
            const __nv_bfloat16* sl = &g_Wtl[(size_t)lr * KPAD_MAX + k0 + lho];
            uint4 b0 = *(const uint4*)sh;
            uint4 b1 = *(const uint4*)(sh + 8);
            uint4 c0 = *(const uint4*)sl;
            uint4 c1 = *(const uint4*)(sl + 8);
            *(uint4*)&Bh[lr][lho]     = b0;
            *(uint4*)&Bh[lr][lho + 8] = b1;
            *(uint4*)&Bl[lr][lho]     = c0;
            *(uint4*)&Bl[lr][lho + 8] = c1;
        }
        __syncthreads();

#pragma unroll
        for (int kh = 0; kh < BK; kh += 16) {
            unsigned ah[2][4], al[2][4];
#pragma unroll
            for (int mi = 0; mi < 2; mi++) {
                int r0 = warp_m + mi * 16;
                ah[mi][0] = *(const unsigned*)&Ah[r0 + g    ][kh + 2 * qt];
                ah[mi][1] = *(const unsigned*)&Ah[r0 + 8 + g][kh + 2 * qt];
                ah[mi][2] = *(const unsigned*)&Ah[r0 + g    ][kh + 8 + 2 * qt];
                ah[mi][3] = *(const unsigned*)&Ah[r0 + 8 + g][kh + 8 + 2 * qt];
                al[mi][0] = *(const unsigned*)&Al[r0 + g    ][kh + 2 * qt];
                al[mi][1] = *(const unsigned*)&Al[r0 + 8 + g][kh + 2 * qt];
                al[mi][2] = *(const unsigned*)&Al[r0 + g    ][kh + 8 + 2 * qt];
                al[mi][3] = *(const unsigned*)&Al[r0 + 8 + g][kh + 8 + 2 * qt];
            }
#pragma unroll
            for (int ni = 0; ni < 8; ni++) {
                int c0i = warp_n + ni * 8 + g;
                unsigned bh[2], bl[2];
                bh[0] = *(const unsigned*)&Bh[c0i][kh + 2 * qt];
                bh[1] = *(const unsigned*)&Bh[c0i][kh + 8 + 2 * qt];
                bl[0] = *(const unsigned*)&Bl[c0i][kh + 2 * qt];
                bl[1] = *(const unsigned*)&Bl[c0i][kh + 8 + 2 * qt];
#pragma unroll
                for (int mi = 0; mi < 2; mi++) {
                    mma16816(acc[mi][ni], ah[mi], bh);
                    mma16816(acc[mi][ni], ah[mi], bl);
                    mma16816(acc[mi][ni], al[mi], bh);
                }
            }
        }
    }

#pragma unroll
    for (int mi = 0; mi < 2; mi++) {
#pragma unroll
        for (int ni = 0; ni < 8; ni++) {
            int row0 = bm + warp_m + mi * 16 + g;
            int col  = warp_n + ni * 8 + 2 * qt;
            if (col < N) {
                if (row0 < M)
                    *(float2*)&C[(size_t)row0 * N + col] =
                        make_float2(acc[mi][ni][0], acc[mi][ni][1]);
                if (row0 + 8 < M)
                    *(float2*)&C[(size_t)(row0 + 8) * N + col] =
                        make_float2(acc[mi][ni][2], acc[mi][ni][3]);
            }
        }
    }
}

// ======== fused CSR-gather SpMM + bias + ReLU + colsum ========
// warp per row (4 rows/warp), lane covers FV/32 features.
#define RPW 4
template <int FV>
__global__ __launch_bounds__(256) void spmm_fused_kernel(const float* __restrict__ bias) {
    constexpr int VEC = FV / 32;
    __shared__ float cs[FV];
    int tid = threadIdx.x;
    if (tid < FV) cs[tid] = 0.f;
    __syncthreads();
    int lane = tid & 31;
    int warp = (((int)blockIdx.x * blockDim.x) + tid) >> 5;
    int r0 = warp * RPW;

    float bv[VEC], bsum[VEC];
#pragma unroll
    for (int v = 0; v < VEC; v++) {
        bv[v] = bias[lane * VEC + v];
        bsum[v] = 0.f;
    }

    if (r0 < N_NODES) {
        for (int rr = 0; rr < RPW; rr++) {
            int r = r0 + rr;
            if (r >= N_NODES) break;
            int beg = g_rowoff[r];
            int end = g_rowoff[r + 1];
            float acc[VEC];
#pragma unroll
            for (int v = 0; v < VEC; v++) acc[v] = 0.f;
            for (int i = beg; i < end; i++) {
                int2 p = __ldg(&g_epack[i]);
                float w = __int_as_float(p.y);
                const float* s = &g_support[(size_t)p.x * FV + lane * VEC];
                if (VEC == 4) {
                    float4 sv = *(const float4*)s;
                    acc[0] = fmaf(w, sv.x, acc[0]);
                    acc[1] = fmaf(w, sv.y, acc[1]);
                    acc[2] = fmaf(w, sv.z, acc[2]);
                    acc[3] = fmaf(w, sv.w, acc[3]);
                } else {
                    float2 sv = *(const float2*)s;
                    acc[0] = fmaf(w, sv.x, acc[0]);
                    acc[1] = fmaf(w, sv.y, acc[1]);
                }
            }
#pragma unroll
            for (int v = 0; v < VEC; v++) {
                acc[v] = fmaxf(acc[v] + bv[v], 0.f);
                bsum[v] += acc[v];
            }
            if (VEC == 4)
                *(float4*)&g_x[(size_t)r * FV + lane * 4] =
                    make_float4(acc[0], acc[1], acc[2], acc[3]);
            else
                *(float2*)&g_x[(size_t)r * FV + lane * 2] =
                    make_float2(acc[0], acc[1]);
        }
#pragma unroll
        for (int v = 0; v < VEC; v++)
            atomicAdd(&cs[lane * VEC + v], bsum[v]);
    }
    __syncthreads();
    if (tid < FV) atomicAdd(&g_colsum[tid], cs[tid]);
}

// -------- PairNorm F=128, fused bf16 hi/lo split output --------
__global__ void pairnorm128_split_kernel() {
    int gw = ((int)blockIdx.x * blockDim.x + threadIdx.x) >> 5;
    int lane = threadIdx.x & 31;
    if (gw >= N_NODES) return;
    const float invN = 1.0f / N_NODES;
    float4 mean = *(const float4*)&g_colsum[lane * 4];
    float4 v = *(const float4*)&g_x[(size_t)gw * F_HID + lane * 4];
    v.x -= mean.x * invN; v.y -= mean.y * invN;
    v.z -= mean.z * invN; v.w -= mean.w * invN;
    float ss = v.x * v.x + v.y * v.y + v.z * v.z + v.w * v.w;
#pragma unroll
    for (int o = 16; o > 0; o >>= 1) ss += __shfl_xor_sync(0xffffffffu, ss, o);
    float inv = rsqrtf(EPSV + ss);
    float y0 = v.x * inv, y1 = v.y * inv, y2 = v.z * inv, y3 = v.w * inv;
    unsigned h01 = pack2(y0, y1);
    unsigned h23 = pack2(y2, y3);
    float f0 = __uint_as_float(h01 << 16), f1 = __uint_as_float(h01 & 0xffff0000u);
    float f2 = __uint_as_float(h23 << 16), f3 = __uint_as_float(h23 & 0xffff0000u);
    unsigned l01 = pack2(y0 - f0, y1 - f1);
    unsigned l23 = pack2(y2 - f2, y3 - f3);
    *(uint2*)&g_Xh[(size_t)gw * F_HID + lane * 4] = make_uint2(h01, h23);
    *(uint2*)&g_Xl[(size_t)gw * F_HID + lane * 4] = make_uint2(l01, l23);
}

// -------- PairNorm F=64 (final, fp32 in-place for decode) --------
__global__ void pairnorm64_kernel() {
    int gw = ((int)blockIdx.x * blockDim.x + threadIdx.x) >> 5;
    int lane = threadIdx.x & 31;
    if (gw >= N_NODES) return;
    const float invN = 1.0f / N_NODES;
    float2 mean = *(const float2*)&g_colsum[lane * 2];
    float2 v = *(const float2*)&g_x[(size_t)gw * F_OUTD + lane * 2];
    v.x -= mean.x * invN;
    v.y -= mean.y * invN;
    float ss = v.x * v.x + v.y * v.y;
#pragma unroll
    for (int o = 16; o > 0; o >>= 1) ss += __shfl_xor_sync(0xffffffffu, ss, o);
    float inv = rsqrtf(EPSV + ss);
    *(float2*)&g_x[(size_t)gw * F_OUTD + lane * 2] = make_float2(v.x * inv, v.y * inv);
}

// -------- decode --------
__global__ void decode_kernel(const int* __restrict__ pos, const int* __restrict__ neg,
                              float* __restrict__ out) {
    int gwarp = ((int)blockIdx.x * blockDim.x + threadIdx.x) >> 5;
    int lane = threadIdx.x & 31;
    if (gwarp >= N_EDGES) return;
    const int* ei = (gwarp < 20000) ? (pos + (size_t)gwarp * 2)
                                    : (neg + (size_t)(gwarp - 20000) * 2);
    int a = ei[0];
    int b = ei[1];
    const float* xa = &g_x[(size_t)a * F_OUTD];
    const float* xb = &g_x[(size_t)b * F_OUTD];
    float s = xa[lane] * xb[lane] + xa[lane + 32] * xb[lane + 32];
#pragma unroll
    for (int o = 16; o > 0; o >>= 1) s += __shfl_xor_sync(0xffffffffu, s, o);
    if (lane == 0) out[gwarp] = 1.0f / (1.0f + expf(-s));
}

// ---------------------------------------------------------------
extern "C" void kernel_launch(void* const* d_in, const int* in_sizes, int n_in,
                              void* d_out, int out_size) {
    const float* in_feature = (const float*)d_in[0];
    const int*   adj_row    = (const int*)d_in[1];
    const int*   adj_col    = (const int*)d_in[2];
    const float* adj_val    = (const float*)d_in[3];
    const int*   pos_ei     = (const int*)d_in[4];
    const int*   neg_ei     = (const int*)d_in[5];
    const float* W[3] = { (const float*)d_in[6], (const float*)d_in[8], (const float*)d_in[10] };
    const float* Bv[3] = { (const float*)d_in[7], (const float*)d_in[9], (const float*)d_in[11] };
    float* out = (float*)d_out;

    float* d_support = nullptr;
    __nv_bfloat16 *d_Xh = nullptr, *d_Xl = nullptr;
    cudaGetSymbolAddress((void**)&d_support, g_support);
    cudaGetSymbolAddress((void**)&d_Xh, g_Xh);
    cudaGetSymbolAddress((void**)&d_Xl, g_Xl);

    // ---- build CSR once ----
    csr_zero_kernel<<<(N_NODES + 255) / 256, 256>>>();
    csr_hist_kernel<<<(NNZ + 255) / 256, 256>>>(adj_row);
    csr_scanA_kernel<<<NBLK_SCAN, SCAN_BLK>>>();
    csr_scanB_kernel<<<1, 128>>>();
    csr_scanC_kernel<<<(N_NODES + 255) / 256, 256>>>();
    csr_scatter_kernel<<<(NNZ + 255) / 256, 256>>>(adj_row, adj_col, adj_val);

    const int Kdims[3] = { F_IN, F_HID, F_HID };
    const int Ndims[3] = { F_HID, F_HID, F_OUTD };

    for (int l = 0; l < 3; l++) {
        int K = Kdims[l], F = Ndims[l];
        int Kpadl = (K + 31) & ~31;

        zero_colsum_kernel<<<1, 128>>>();

        int wunits = 128 * (Kpadl >> 3);
        splitW_kernel<<<(wunits + 255) / 256, 256>>>(W[l], K, F, Kpadl);

        dim3 ggrid(1, (N_NODES + BM - 1) / BM);
        if (l == 0)
            gemm_tc_kernel<0><<<ggrid, 256>>>(in_feature, nullptr, nullptr,
                                              d_support, N_NODES, K, Kpadl, 0, F);
        else
            gemm_tc_kernel<1><<<ggrid, 256>>>(nullptr, d_Xh, d_Xl,
                                              d_support, N_NODES, K, Kpadl, F_HID, F);

        int nwarps = (N_NODES + RPW - 1) / RPW;
        int nblk = (nwarps * 32 + 255) / 256;
        if (F == 128)
            spmm_fused_kernel<128><<<nblk, 256>>>(Bv[l]);
        else
            spmm_fused_kernel<64><<<nblk, 256>>>(Bv[l]);

        if (l < 2)
            pairnorm128_split_kernel<<<(N_NODES * 32 + 255) / 256, 256>>>();
        else
            pairnorm64_kernel<<<(N_NODES * 32 + 255) / 256, 256>>>();
    }

    int dblocks = (N_EDGES * 32 + 255) / 256;
    decode_kernel<<<dblocks, 256>>>(pos_ei, neg_ei, out);
}

// round 5
// speedup vs baseline: 2.9210x; 1.1493x over previous
#include <cuda_runtime.h>
#include <cuda_bf16.h>
#include <math.h>
#include <stdint.h>

#define N_NODES 100000
#define NNZ     1000000
#define F_IN    1433
#define F_HID   128
#define F_OUTD  64
#define N_EDGES 40000
#define EPSV    1e-6f
#define KPAD_MAX 1440
#define SCAN_BLK 1024
#define NBLK_SCAN ((N_NODES + SCAN_BLK - 1) / SCAN_BLK)   // 98

// -------- static device scratch --------
__device__ float g_support[(size_t)N_NODES * F_HID];
__device__ float g_x[(size_t)N_NODES * F_HID];
__device__ float g_colsum[F_HID];
__device__ __nv_bfloat16 g_Xh[(size_t)N_NODES * F_HID];
__device__ __nv_bfloat16 g_Xl[(size_t)N_NODES * F_HID];
__device__ __nv_bfloat16 g_Wth[(size_t)128 * KPAD_MAX];
__device__ __nv_bfloat16 g_Wtl[(size_t)128 * KPAD_MAX];
// CSR
__device__ int  g_rowcnt[N_NODES];
__device__ int  g_rowoff[N_NODES + 1];
__device__ int  g_blksum[128];
__device__ int2 g_epack[NNZ];    // (col, bitcast val)

__device__ __forceinline__ unsigned pack2(float f0, float f1) {
    unsigned r;
    asm("cvt.rn.bf16x2.f32 %0, %1, %2;" : "=r"(r) : "f"(f1), "f"(f0));
    return r;
}

// ================= CSR build =================
__global__ void csr_zero_kernel() {
    int i = blockIdx.x * blockDim.x + threadIdx.x;
    if (i < N_NODES) g_rowcnt[i] = 0;
}
__global__ void csr_hist_kernel(const int* __restrict__ row) {
    int e = blockIdx.x * blockDim.x + threadIdx.x;
    if (e < NNZ) atomicAdd(&g_rowcnt[row[e]], 1);
}
__global__ __launch_bounds__(SCAN_BLK) void csr_scanA_kernel() {
    __shared__ int sm[SCAN_BLK];
    int t = threadIdx.x;
    int i = blockIdx.x * SCAN_BLK + t;
    int v = (i < N_NODES) ? g_rowcnt[i] : 0;
    sm[t] = v;
    __syncthreads();
#pragma unroll
    for (int s = 1; s < SCAN_BLK; s <<= 1) {
        int a = (t >= s) ? sm[t - s] : 0;
        __syncthreads();
        sm[t] += a;
        __syncthreads();
    }
    if (i < N_NODES) g_rowoff[i] = sm[t] - v;
    if (t == SCAN_BLK - 1) g_blksum[blockIdx.x] = sm[t];
}
__global__ void csr_scanB_kernel() {
    __shared__ int sm[128];
    int t = threadIdx.x;
    int v = (t < NBLK_SCAN) ? g_blksum[t] : 0;
    sm[t] = v;
    __syncthreads();
#pragma unroll
    for (int s = 1; s < 128; s <<= 1) {
        int a = (t >= s) ? sm[t - s] : 0;
        __syncthreads();
        sm[t] += a;
        __syncthreads();
    }
    g_blksum[t] = sm[t] - v;
}
__global__ void csr_scanC_kernel() {
    int i = blockIdx.x * blockDim.x + threadIdx.x;
    if (i < N_NODES) {
        g_rowoff[i] += g_blksum[i >> 10];
        g_rowcnt[i] = 0;
    }
    if (i == 0) g_rowoff[N_NODES] = NNZ;
}
__global__ void csr_scatter_kernel(const int* __restrict__ row, const int* __restrict__ col,
                                   const float* __restrict__ val) {
    int e = blockIdx.x * blockDim.x + threadIdx.x;
    if (e >= NNZ) return;
    int r = row[e];
    int p = g_rowoff[r] + atomicAdd(&g_rowcnt[r], 1);
    g_epack[p] = make_int2(col[e], __float_as_int(val[e]));
}

// -------- zero colsum --------
__global__ void zero_colsum_kernel() {
    if (threadIdx.x < F_HID) g_colsum[threadIdx.x] = 0.f;
}

// -------- split + transpose W --------
__global__ void splitW_kernel(const float* __restrict__ W, int K, int N, int Kpadl) {
    int oct = Kpadl >> 3;
    int u = blockIdx.x * blockDim.x + threadIdx.x;
    if (u >= 128 * oct) return;
    int n = u / oct;
    int k0 = (u - n * oct) << 3;
    float v[8];
#pragma unroll
    for (int e = 0; e < 8; e++) {
        int k = k0 + e;
        v[e] = (k < K && n < N) ? __ldg(&W[(size_t)k * N + n]) : 0.f;
    }
    unsigned hh[4], ll[4];
#pragma unroll
    for (int p = 0; p < 4; p++) {
        unsigned h = pack2(v[2 * p], v[2 * p + 1]);
        float h0 = __uint_as_float(h << 16);
        float h1 = __uint_as_float(h & 0xffff0000u);
        hh[p] = h;
        ll[p] = pack2(v[2 * p] - h0, v[2 * p + 1] - h1);
    }
    *(uint4*)&g_Wth[(size_t)n * KPAD_MAX + k0] = make_uint4(hh[0], hh[1], hh[2], hh[3]);
    *(uint4*)&g_Wtl[(size_t)n * KPAD_MAX + k0] = make_uint4(ll[0], ll[1], ll[2], ll[3]);
}

// ============ Tensor-core GEMM, bf16 hi/lo 3-term, double-buffered + ldmatrix ============
#define BM 128
#define BN 128
#define BK 32
#define BKP 40                   // 80B rows: conflict-free ldmatrix / STS.128
#define PLANE_BYTES (128 * BKP * 2)          // 10240
#define OFF_AH 0
#define OFF_AL (PLANE_BYTES)
#define OFF_BH (2 * PLANE_BYTES)
#define OFF_BL (3 * PLANE_BYTES)
#define STAGE_BYTES (4 * PLANE_BYTES)        // 40960
#define GEMM_SMEM (2 * STAGE_BYTES)          // 81920

__device__ __forceinline__ void mma16816(float c[4], const unsigned a[4], const unsigned* b) {
    asm volatile(
        "mma.sync.aligned.m16n8k16.row.col.f32.bf16.bf16.f32 "
        "{%0,%1,%2,%3}, {%4,%5,%6,%7}, {%8,%9}, {%0,%1,%2,%3};"
        : "+f"(c[0]), "+f"(c[1]), "+f"(c[2]), "+f"(c[3])
        : "r"(a[0]), "r"(a[1]), "r"(a[2]), "r"(a[3]), "r"(b[0]), "r"(b[1]));
}

__device__ __forceinline__ void ldmx4(unsigned r[4], uint32_t addr) {
    asm volatile("ldmatrix.sync.aligned.m8n8.x4.shared.b16 {%0,%1,%2,%3}, [%4];"
                 : "=r"(r[0]), "=r"(r[1]), "=r"(r[2]), "=r"(r[3]) : "r"(addr));
}

__device__ __forceinline__ void cp_async16(uint32_t dst, const void* src, bool ok) {
    int bytes = ok ? 16 : 0;
    asm volatile("cp.async.cg.shared.global [%0], [%1], 16, %2;"
                 :: "r"(dst), "l"(src), "r"(bytes));
}

template <int AMODE>
__global__ __launch_bounds__(256) void gemm_tc_kernel(
    const float* __restrict__ A,
    const __nv_bfloat16* __restrict__ Aph, const __nv_bfloat16* __restrict__ Apl,
    float* __restrict__ C, int M, int K, int Kpad, int lda, int N)
{
    extern __shared__ __align__(16) char dynsmem[];
    const uint32_t sbase = (uint32_t)__cvta_generic_to_shared(dynsmem);

    const int tid  = threadIdx.x;
    const int wid  = tid >> 5;
    const int lane = tid & 31;
    const int bm   = blockIdx.y * BM;
    const int g    = lane >> 2;
    const int qt   = lane & 3;
    const int warp_m = (wid >> 1) * 32;
    const int warp_n = (wid & 1) * 64;

    // ldmatrix per-lane row/col bases
    const int rA0 = warp_m + (lane & 7) + (lane & 8);
    const int cA  = (lane & 16) >> 1;
    const int rB0 = warp_n + (lane & 7) + ((lane & 16) >> 1);
    const int cB  = (lane & 8);

    float acc[2][8][4];
#pragma unroll
    for (int mi = 0; mi < 2; mi++)
#pragma unroll
        for (int ni = 0; ni < 8; ni++)
#pragma unroll
            for (int q = 0; q < 4; q++) acc[mi][ni][q] = 0.f;

    float pv[2][8];   // AMODE0 A prefetch registers

    // ---- helpers (emitted inline) ----
    // issue B-plane cp.asyncs for a stage
    auto issue_B = [&](int stage, int k0) {
        uint32_t sb = sbase + stage * STAGE_BYTES;
#pragma unroll
        for (int p = 0; p < 2; p++) {
            int c = tid + p * 256;
            int row = c >> 2;
            int off = (c & 3) << 3;
            uint32_t doff = row * (BKP * 2) + off * 2;
            cp_async16(sb + OFF_BH + doff, &g_Wth[(size_t)row * KPAD_MAX + k0 + off], true);
            cp_async16(sb + OFF_BL + doff, &g_Wtl[(size_t)row * KPAD_MAX + k0 + off], true);
        }
    };
    auto issue_A_planes = [&](int stage, int k0) {
        uint32_t sb = sbase + stage * STAGE_BYTES;
#pragma unroll
        for (int p = 0; p < 2; p++) {
            int c = tid + p * 256;
            int row = c >> 2;
            int off = (c & 3) << 3;
            int m = bm + row;
            bool ok = m < M;
            int ms = ok ? m : 0;
            uint32_t doff = row * (BKP * 2) + off * 2;
            cp_async16(sb + OFF_AH + doff, Aph + (size_t)ms * lda + k0 + off, ok);
            cp_async16(sb + OFF_AL + doff, Apl + (size_t)ms * lda + k0 + off, ok);
        }
    };
    auto prefetch_A = [&](int k0) {
#pragma unroll
        for (int u2 = 0; u2 < 2; u2++) {
            int u = tid + u2 * 256;
            int r = u >> 2;
            int o = (u & 3) << 3;
            int m = bm + r;
#pragma unroll
            for (int e = 0; e < 8; e++) {
                int k = k0 + o + e;
                pv[u2][e] = (m < M && k < K) ? __ldg(&A[(size_t)m * K + k]) : 0.f;
            }
        }
    };
    auto cvt_sts_A = [&](int stage) {
#pragma unroll
        for (int u2 = 0; u2 < 2; u2++) {
            int u = tid + u2 * 256;
            int r = u >> 2;
            int o = (u & 3) << 3;
            unsigned hh[4], ll[4];
#pragma unroll
            for (int p = 0; p < 4; p++) {
                unsigned h = pack2(pv[u2][2 * p], pv[u2][2 * p + 1]);
                float h0 = __uint_as_float(h << 16);
                float h1 = __uint_as_float(h & 0xffff0000u);
                hh[p] = h;
                ll[p] = pack2(pv[u2][2 * p] - h0, pv[u2][2 * p + 1] - h1);
            }
            char* base = dynsmem + stage * STAGE_BYTES + r * (BKP * 2) + o * 2;
            *(uint4*)(base + OFF_AH) = make_uint4(hh[0], hh[1], hh[2], hh[3]);
            *(uint4*)(base + OFF_AL) = make_uint4(ll[0], ll[1], ll[2], ll[3]);
        }
    };

    const int nt = Kpad / BK;

    // ---- prologue: stage 0 ----
    if (AMODE == 0) {
        prefetch_A(0);
        cvt_sts_A(0);
    } else {
        issue_A_planes(0, 0);
    }
    issue_B(0, 0);
    asm volatile("cp.async.commit_group;" ::: "memory");

    for (int kt = 0; kt < nt; kt++) {
        int cur = kt & 1;
        int nxt = cur ^ 1;
        asm volatile("cp.async.wait_group 0;" ::: "memory");
        __syncthreads();

        bool hn = (kt + 1) < nt;
        int k1 = (kt + 1) * BK;
        if (hn) {
            if (AMODE == 0) prefetch_A(k1);
            else            issue_A_planes(nxt, k1);
            issue_B(nxt, k1);
        }
        asm volatile("cp.async.commit_group;" ::: "memory");

        // ---- compute current stage ----
        uint32_t sA = sbase + cur * STAGE_BYTES;
#pragma unroll
        for (int kh = 0; kh < BK; kh += 16) {
            unsigned ah[2][4], al[2][4];
#pragma unroll
            for (int mi = 0; mi < 2; mi++) {
                uint32_t ra = sA + OFF_AH + (rA0 + mi * 16) * (BKP * 2) + (cA + kh) * 2;
                ldmx4(ah[mi], ra);
                ldmx4(al[mi], ra + (OFF_AL - OFF_AH));
            }
#pragma unroll
            for (int nip = 0; nip < 4; nip++) {
                unsigned bh4[4], bl4[4];
                uint32_t rb = sA + OFF_BH + (rB0 + nip * 16) * (BKP * 2) + (cB + kh) * 2;
                ldmx4(bh4, rb);
                ldmx4(bl4, rb + (OFF_BL - OFF_BH));
#pragma unroll
                for (int mi = 0; mi < 2; mi++) {
                    mma16816(acc[mi][2 * nip],     ah[mi], &bh4[0]);
                    mma16816(acc[mi][2 * nip],     ah[mi], &bl4[0]);
                    mma16816(acc[mi][2 * nip],     al[mi], &bh4[0]);
                    mma16816(acc[mi][2 * nip + 1], ah[mi], &bh4[2]);
                    mma16816(acc[mi][2 * nip + 1], ah[mi], &bl4[2]);
                    mma16816(acc[mi][2 * nip + 1], al[mi], &bh4[2]);
                }
            }
        }

        if (AMODE == 0 && hn) cvt_sts_A(nxt);
    }

    // ---- store C ----
#pragma unroll
    for (int mi = 0; mi < 2; mi++) {
#pragma unroll
        for (int ni = 0; ni < 8; ni++) {
            int row0 = bm + warp_m + mi * 16 + g;
            int col  = warp_n + ni * 8 + 2 * qt;
            if (col < N) {
                if (row0 < M)
                    *(float2*)&C[(size_t)row0 * N + col] =
                        make_float2(acc[mi][ni][0], acc[mi][ni][1]);
                if (row0 + 8 < M)
                    *(float2*)&C[(size_t)(row0 + 8) * N + col] =
                        make_float2(acc[mi][ni][2], acc[mi][ni][3]);
            }
        }
    }
}

// ======== fused CSR-gather SpMM + bias + ReLU + colsum ========
#define RPW 4
template <int FV>
__global__ __launch_bounds__(256) void spmm_fused_kernel(const float* __restrict__ bias) {
    constexpr int VEC = FV / 32;
    __shared__ float cs[FV];
    int tid = threadIdx.x;
    if (tid < FV) cs[tid] = 0.f;
    __syncthreads();
    int lane = tid & 31;
    int warp = (((int)blockIdx.x * blockDim.x) + tid) >> 5;
    int r0 = warp * RPW;

    float bv[VEC], bsum[VEC];
#pragma unroll
    for (int v = 0; v < VEC; v++) {
        bv[v] = bias[lane * VEC + v];
        bsum[v] = 0.f;
    }

    if (r0 < N_NODES) {
        for (int rr = 0; rr < RPW; rr++) {
            int r = r0 + rr;
            if (r >= N_NODES) break;
            int beg = g_rowoff[r];
            int end = g_rowoff[r + 1];
            float acc[VEC];
#pragma unroll
            for (int v = 0; v < VEC; v++) acc[v] = 0.f;
            for (int i = beg; i < end; i++) {
                int2 p = __ldg(&g_epack[i]);
                float w = __int_as_float(p.y);
                const float* s = &g_support[(size_t)p.x * FV + lane * VEC];
                if (VEC == 4) {
                    float4 sv = *(const float4*)s;
                    acc[0] = fmaf(w, sv.x, acc[0]);
                    acc[1] = fmaf(w, sv.y, acc[1]);
                    acc[2] = fmaf(w, sv.z, acc[2]);
                    acc[3] = fmaf(w, sv.w, acc[3]);
                } else {
                    float2 sv = *(const float2*)s;
                    acc[0] = fmaf(w, sv.x, acc[0]);
                    acc[1] = fmaf(w, sv.y, acc[1]);
                }
            }
#pragma unroll
            for (int v = 0; v < VEC; v++) {
                acc[v] = fmaxf(acc[v] + bv[v], 0.f);
                bsum[v] += acc[v];
            }
            if (VEC == 4)
                *(float4*)&g_x[(size_t)r * FV + lane * 4] =
                    make_float4(acc[0], acc[1], acc[2], acc[3]);
            else
                *(float2*)&g_x[(size_t)r * FV + lane * 2] =
                    make_float2(acc[0], acc[1]);
        }
#pragma unroll
        for (int v = 0; v < VEC; v++)
            atomicAdd(&cs[lane * VEC + v], bsum[v]);
    }
    __syncthreads();
    if (tid < FV) atomicAdd(&g_colsum[tid], cs[tid]);
}

// -------- PairNorm F=128, fused bf16 hi/lo split output --------
__global__ void pairnorm128_split_kernel() {
    int gw = ((int)blockIdx.x * blockDim.x + threadIdx.x) >> 5;
    int lane = threadIdx.x & 31;
    if (gw >= N_NODES) return;
    const float invN = 1.0f / N_NODES;
    float4 mean = *(const float4*)&g_colsum[lane * 4];
    float4 v = *(const float4*)&g_x[(size_t)gw * F_HID + lane * 4];
    v.x -= mean.x * invN; v.y -= mean.y * invN;
    v.z -= mean.z * invN; v.w -= mean.w * invN;
    float ss = v.x * v.x + v.y * v.y + v.z * v.z + v.w * v.w;
#pragma unroll
    for (int o = 16; o > 0; o >>= 1) ss += __shfl_xor_sync(0xffffffffu, ss, o);
    float inv = rsqrtf(EPSV + ss);
    float y0 = v.x * inv, y1 = v.y * inv, y2 = v.z * inv, y3 = v.w * inv;
    unsigned h01 = pack2(y0, y1);
    unsigned h23 = pack2(y2, y3);
    float f0 = __uint_as_float(h01 << 16), f1 = __uint_as_float(h01 & 0xffff0000u);
    float f2 = __uint_as_float(h23 << 16), f3 = __uint_as_float(h23 & 0xffff0000u);
    unsigned l01 = pack2(y0 - f0, y1 - f1);
    unsigned l23 = pack2(y2 - f2, y3 - f3);
    *(uint2*)&g_Xh[(size_t)gw * F_HID + lane * 4] = make_uint2(h01, h23);
    *(uint2*)&g_Xl[(size_t)gw * F_HID + lane * 4] = make_uint2(l01, l23);
}

// -------- PairNorm F=64 (final, fp32 in-place for decode) --------
__global__ void pairnorm64_kernel() {
    int gw = ((int)blockIdx.x * blockDim.x + threadIdx.x) >> 5;
    int lane = threadIdx.x & 31;
    if (gw >= N_NODES) return;
    const float invN = 1.0f / N_NODES;
    float2 mean = *(const float2*)&g_colsum[lane * 2];
    float2 v = *(const float2*)&g_x[(size_t)gw * F_OUTD + lane * 2];
    v.x -= mean.x * invN;
    v.y -= mean.y * invN;
    float ss = v.x * v.x + v.y * v.y;
#pragma unroll
    for (int o = 16; o > 0; o >>= 1) ss += __shfl_xor_sync(0xffffffffu, ss, o);
    float inv = rsqrtf(EPSV + ss);
    *(float2*)&g_x[(size_t)gw * F_OUTD + lane * 2] = make_float2(v.x * inv, v.y * inv);
}

// -------- decode --------
__global__ void decode_kernel(const int* __restrict__ pos, const int* __restrict__ neg,
                              float* __restrict__ out) {
    int gwarp = ((int)blockIdx.x * blockDim.x + threadIdx.x) >> 5;
    int lane = threadIdx.x & 31;
    if (gwarp >= N_EDGES) return;
    const int* ei = (gwarp < 20000) ? (pos + (size_t)gwarp * 2)
                                    : (neg + (size_t)(gwarp - 20000) * 2);
    int a = ei[0];
    int b = ei[1];
    const float* xa = &g_x[(size_t)a * F_OUTD];
    const float* xb = &g_x[(size_t)b * F_OUTD];
    float s = xa[lane] * xb[lane] + xa[lane + 32] * xb[lane + 32];
#pragma unroll
    for (int o = 16; o > 0; o >>= 1) s += __shfl_xor_sync(0xffffffffu, s, o);
    if (lane == 0) out[gwarp] = 1.0f / (1.0f + expf(-s));
}

// ---------------------------------------------------------------
extern "C" void kernel_launch(void* const* d_in, const int* in_sizes, int n_in,
                              void* d_out, int out_size) {
    const float* in_feature = (const float*)d_in[0];
    const int*   adj_row    = (const int*)d_in[1];
    const int*   adj_col    = (const int*)d_in[2];
    const float* adj_val    = (const float*)d_in[3];
    const int*   pos_ei     = (const int*)d_in[4];
    const int*   neg_ei     = (const int*)d_in[5];
    const float* W[3] = { (const float*)d_in[6], (const float*)d_in[8], (const float*)d_in[10] };
    const float* Bv[3] = { (const float*)d_in[7], (const float*)d_in[9], (const float*)d_in[11] };
    float* out = (float*)d_out;

    float* d_support = nullptr;
    __nv_bfloat16 *d_Xh = nullptr, *d_Xl = nullptr;
    cudaGetSymbolAddress((void**)&d_support, g_support);
    cudaGetSymbolAddress((void**)&d_Xh, g_Xh);
    cudaGetSymbolAddress((void**)&d_Xl, g_Xl);

    // allow 80KB dynamic smem for the GEMMs (idempotent)
    cudaFuncSetAttribute(gemm_tc_kernel<0>, cudaFuncAttributeMaxDynamicSharedMemorySize, GEMM_SMEM);
    cudaFuncSetAttribute(gemm_tc_kernel<1>, cudaFuncAttributeMaxDynamicSharedMemorySize, GEMM_SMEM);

    // ---- build CSR once ----
    csr_zero_kernel<<<(N_NODES + 255) / 256, 256>>>();
    csr_hist_kernel<<<(NNZ + 255) / 256, 256>>>(adj_row);
    csr_scanA_kernel<<<NBLK_SCAN, SCAN_BLK>>>();
    csr_scanB_kernel<<<1, 128>>>();
    csr_scanC_kernel<<<(N_NODES + 255) / 256, 256>>>();
    csr_scatter_kernel<<<(NNZ + 255) / 256, 256>>>(adj_row, adj_col, adj_val);

    const int Kdims[3] = { F_IN, F_HID, F_HID };
    const int Ndims[3] = { F_HID, F_HID, F_OUTD };

    for (int l = 0; l < 3; l++) {
        int K = Kdims[l], F = Ndims[l];
        int Kpadl = (K + 31) & ~31;

        zero_colsum_kernel<<<1, 128>>>();

        int wunits = 128 * (Kpadl >> 3);
        splitW_kernel<<<(wunits + 255) / 256, 256>>>(W[l], K, F, Kpadl);

        dim3 ggrid(1, (N_NODES + BM - 1) / BM);
        if (l == 0)
            gemm_tc_kernel<0><<<ggrid, 256, GEMM_SMEM>>>(in_feature, nullptr, nullptr,
                                                         d_support, N_NODES, K, Kpadl, 0, F);
        else
            gemm_tc_kernel<1><<<ggrid, 256, GEMM_SMEM>>>(nullptr, d_Xh, d_Xl,
                                                         d_support, N_NODES, K, Kpadl, F_HID, F);

        int nwarps = (N_NODES + RPW - 1) / RPW;
        int nblk = (nwarps * 32 + 255) / 256;
        if (F == 128)
            spmm_fused_kernel<128><<<nblk, 256>>>(Bv[l]);
        else
            spmm_fused_kernel<64><<<nblk, 256>>>(Bv[l]);

        if (l < 2)
            pairnorm128_split_kernel<<<(N_NODES * 32 + 255) / 256, 256>>>();
        else
            pairnorm64_kernel<<<(N_NODES * 32 + 255) / 256, 256>>>();
    }

    int dblocks = (N_EDGES * 32 + 255) / 256;
    decode_kernel<<<dblocks, 256>>>(pos_ei, neg_ei, out);
}

// round 7
// speedup vs baseline: 3.0947x; 1.0595x over previous
#include <cuda_runtime.h>
#include <cuda_bf16.h>
#include <math.h>
#include <stdint.h>

#define N_NODES 100000
#define NNZ     1000000
#define F_IN    1433
#define F_HID   128
#define F_OUTD  64
#define N_EDGES 40000
#define EPSV    1e-6f
#define KPAD0   1440
#define SCAN_BLK 1024
#define NBLK_SCAN ((N_NODES + SCAN_BLK - 1) / SCAN_BLK)   // 98

// -------- static device scratch --------
__device__ float g_support[(size_t)N_NODES * F_HID];
__device__ float g_x[(size_t)N_NODES * F_HID];
__device__ float g_colsum3[3][F_HID];
__device__ __nv_bfloat16 g_Xh[(size_t)N_NODES * F_HID];
__device__ __nv_bfloat16 g_Xl[(size_t)N_NODES * F_HID];
// per-layer pre-split transposed weights
__device__ __nv_bfloat16 g_W0h[(size_t)128 * KPAD0];
__device__ __nv_bfloat16 g_W0l[(size_t)128 * KPAD0];
__device__ __nv_bfloat16 g_W1h[(size_t)128 * F_HID];
__device__ __nv_bfloat16 g_W1l[(size_t)128 * F_HID];
__device__ __nv_bfloat16 g_W2h[(size_t)128 * F_HID];
__device__ __nv_bfloat16 g_W2l[(size_t)128 * F_HID];
// CSR
__device__ int  g_rowcnt[N_NODES];
__device__ int  g_rowoff[N_NODES + 1];
__device__ int  g_blksum[128];
__device__ int2 g_epack[NNZ];

__device__ __forceinline__ unsigned pack2(float f0, float f1) {
    unsigned r;
    asm("cvt.rn.bf16x2.f32 %0, %1, %2;" : "=r"(r) : "f"(f1), "f"(f0));
    return r;
}

// ================= prep: zero rowcnt + colsums, split all W =================
// unit layout: [0,100000) rowcnt zero; [100000,100384) colsum zero;
// [102400, 102400+U0+U1+U2) splitW units (8 k per unit).
#define U0 (128 * (KPAD0 / 8))        // 23040
#define U12 (128 * (F_HID / 8))       // 2048
#define PREP_BASE 102400
#define PREP_TOTAL (PREP_BASE + U0 + 2 * U12)

__device__ __forceinline__ void split8(const float* __restrict__ W, int K, int n, int k0,
                                       __nv_bfloat16* dsth, __nv_bfloat16* dstl, int ldk) {
    float v[8];
#pragma unroll
    for (int e = 0; e < 8; e++) {
        int k = k0 + e;
        v[e] = (k < K) ? __ldg(&W[(size_t)k * 128 + n]) : 0.f;
    }
    unsigned hh[4], ll[4];
#pragma unroll
    for (int p = 0; p < 4; p++) {
        unsigned h = pack2(v[2 * p], v[2 * p + 1]);
        float h0 = __uint_as_float(h << 16);
        float h1 = __uint_as_float(h & 0xffff0000u);
        hh[p] = h;
        ll[p] = pack2(v[2 * p] - h0, v[2 * p + 1] - h1);
    }
    *(uint4*)&dsth[(size_t)n * ldk + k0] = make_uint4(hh[0], hh[1], hh[2], hh[3]);
    *(uint4*)&dstl[(size_t)n * ldk + k0] = make_uint4(ll[0], ll[1], ll[2], ll[3]);
}

__global__ void prep_kernel(const float* __restrict__ W0, const float* __restrict__ W1,
                            const float* __restrict__ W2) {
    int t = blockIdx.x * blockDim.x + threadIdx.x;
    if (t < N_NODES) { g_rowcnt[t] = 0; return; }
    if (t < N_NODES + 384) { ((float*)g_colsum3)[t - N_NODES] = 0.f; return; }
    if (t < PREP_BASE) return;
    int u = t - PREP_BASE;
    if (u < U0) {
        int n = u / (KPAD0 / 8);
        int k0 = (u - n * (KPAD0 / 8)) << 3;
        split8(W0, F_IN, n, k0, g_W0h, g_W0l, KPAD0);
    } else if (u < U0 + U12) {
        int v = u - U0;
        int n = v >> 4;
        int k0 = (v & 15) << 3;
        split8(W1, F_HID, n, k0, g_W1h, g_W1l, F_HID);
    } else if (u < U0 + 2 * U12) {
        int v = u - U0 - U12;
        int n = v >> 4;
        int k0 = (v & 15) << 3;
        // W2 is [128,64]: transpose n<64 valid, rest zero
        float v8[8];
#pragma unroll
        for (int e = 0; e < 8; e++)
            v8[e] = (n < F_OUTD) ? __ldg(&W2[(size_t)(k0 + e) * F_OUTD + n]) : 0.f;
        unsigned hh[4], ll[4];
#pragma unroll
        for (int p = 0; p < 4; p++) {
            unsigned h = pack2(v8[2 * p], v8[2 * p + 1]);
            float h0 = __uint_as_float(h << 16);
            float h1 = __uint_as_float(h & 0xffff0000u);
            hh[p] = h;
            ll[p] = pack2(v8[2 * p] - h0, v8[2 * p + 1] - h1);
        }
        *(uint4*)&g_W2h[(size_t)n * F_HID + k0] = make_uint4(hh[0], hh[1], hh[2], hh[3]);
        *(uint4*)&g_W2l[(size_t)n * F_HID + k0] = make_uint4(ll[0], ll[1], ll[2], ll[3]);
    }
}

// ================= CSR build =================
__global__ void csr_hist_kernel(const int* __restrict__ row) {
    int e = blockIdx.x * blockDim.x + threadIdx.x;
    if (e < NNZ) atomicAdd(&g_rowcnt[row[e]], 1);
}
__global__ __launch_bounds__(SCAN_BLK) void csr_scanA_kernel() {
    __shared__ int sm[SCAN_BLK];
    int t = threadIdx.x;
    int i = blockIdx.x * SCAN_BLK + t;
    int v = (i < N_NODES) ? g_rowcnt[i] : 0;
    sm[t] = v;
    __syncthreads();
#pragma unroll
    for (int s = 1; s < SCAN_BLK; s <<= 1) {
        int a = (t >= s) ? sm[t - s] : 0;
        __syncthreads();
        sm[t] += a;
        __syncthreads();
    }
    if (i < N_NODES) g_rowoff[i] = sm[t] - v;
    if (t == SCAN_BLK - 1) g_blksum[blockIdx.x] = sm[t];
}
__global__ void csr_scanB_kernel() {
    __shared__ int sm[128];
    int t = threadIdx.x;
    int v = (t < NBLK_SCAN) ? g_blksum[t] : 0;
    sm[t] = v;
    __syncthreads();
#pragma unroll
    for (int s = 1; s < 128; s <<= 1) {
        int a = (t >= s) ? sm[t - s] : 0;
        __syncthreads();
        sm[t] += a;
        __syncthreads();
    }
    g_blksum[t] = sm[t] - v;
}
__global__ void csr_scanC_kernel() {
    int i = blockIdx.x * blockDim.x + threadIdx.x;
    if (i < N_NODES) {
        g_rowoff[i] += g_blksum[i >> 10];
        g_rowcnt[i] = 0;
    }
    if (i == 0) g_rowoff[N_NODES] = NNZ;
}
__global__ void csr_scatter_kernel(const int* __restrict__ row, const int* __restrict__ col,
                                   const float* __restrict__ val) {
    int e = blockIdx.x * blockDim.x + threadIdx.x;
    if (e >= NNZ) return;
    int r = row[e];
    int p = g_rowoff[r] + atomicAdd(&g_rowcnt[r], 1);
    g_epack[p] = make_int2(col[e], __float_as_int(val[e]));
}

// ============ mma.sync GEMM, bf16 hi/lo 3-term, double-buffered + ldmatrix ============
#define BM 128
#define BN 128
#define BK 32
#define BKP 40
#define PLANE_BYTES (128 * BKP * 2)
#define OFF_AH 0
#define OFF_AL (PLANE_BYTES)
#define OFF_BH (2 * PLANE_BYTES)
#define OFF_BL (3 * PLANE_BYTES)
#define STAGE_BYTES (4 * PLANE_BYTES)
#define GEMM_SMEM (2 * STAGE_BYTES)

__device__ __forceinline__ void mma16816(float c[4], const unsigned a[4], const unsigned* b) {
    asm volatile(
        "mma.sync.aligned.m16n8k16.row.col.f32.bf16.bf16.f32 "
        "{%0,%1,%2,%3}, {%4,%5,%6,%7}, {%8,%9}, {%0,%1,%2,%3};"
        : "+f"(c[0]), "+f"(c[1]), "+f"(c[2]), "+f"(c[3])
        : "r"(a[0]), "r"(a[1]), "r"(a[2]), "r"(a[3]), "r"(b[0]), "r"(b[1]));
}
__device__ __forceinline__ void ldmx4(unsigned r[4], uint32_t addr) {
    asm volatile("ldmatrix.sync.aligned.m8n8.x4.shared.b16 {%0,%1,%2,%3}, [%4];"
                 : "=r"(r[0]), "=r"(r[1]), "=r"(r[2]), "=r"(r[3]) : "r"(addr));
}
__device__ __forceinline__ void cp_async16(uint32_t dst, const void* src, bool ok) {
    int bytes = ok ? 16 : 0;
    asm volatile("cp.async.cg.shared.global [%0], [%1], 16, %2;"
                 :: "r"(dst), "l"(src), "r"(bytes));
}

// AMODE 0: A fp32 (layer0). AMODE 1: A bf16 planes.
template <int AMODE>
__global__ __launch_bounds__(256, 2) void gemm_tc_kernel(
    const float* __restrict__ A,
    const __nv_bfloat16* __restrict__ Aph, const __nv_bfloat16* __restrict__ Apl,
    const __nv_bfloat16* __restrict__ Wh, const __nv_bfloat16* __restrict__ Wl,
    float* __restrict__ C, int M, int K, int Kpad, int lda, int ldw, int N)
{
    extern __shared__ __align__(16) char dynsmem[];
    const uint32_t sbase = (uint32_t)__cvta_generic_to_shared(dynsmem);

    const int tid  = threadIdx.x;
    const int wid  = tid >> 5;
    const int lane = tid & 31;
    const int bm   = blockIdx.y * BM;
    const int g    = lane >> 2;
    const int qt   = lane & 3;
    const int warp_m = (wid >> 1) * 32;
    const int warp_n = (wid & 1) * 64;

    const int rA0 = warp_m + (lane & 7) + (lane & 8);
    const int cA  = (lane & 16) >> 1;
    const int rB0 = warp_n + (lane & 7) + ((lane & 16) >> 1);
    const int cB  = (lane & 8);

    float acc[2][8][4];
#pragma unroll
    for (int mi = 0; mi < 2; mi++)
#pragma unroll
        for (int ni = 0; ni < 8; ni++)
#pragma unroll
            for (int q = 0; q < 4; q++) acc[mi][ni][q] = 0.f;

    float pv[2][8];

    auto issue_B = [&](int stage, int k0) {
        uint32_t sb = sbase + stage * STAGE_BYTES;
#pragma unroll
        for (int p = 0; p < 2; p++) {
            int c = tid + p * 256;
            int row = c >> 2;
            int off = (c & 3) << 3;
            uint32_t doff = row * (BKP * 2) + off * 2;
            cp_async16(sb + OFF_BH + doff, &Wh[(size_t)row * ldw + k0 + off], true);
            cp_async16(sb + OFF_BL + doff, &Wl[(size_t)row * ldw + k0 + off], true);
        }
    };
    auto issue_A_planes = [&](int stage, int k0) {
        uint32_t sb = sbase + stage * STAGE_BYTES;
#pragma unroll
        for (int p = 0; p < 2; p++) {
            int c = tid + p * 256;
            int row = c >> 2;
            int off = (c & 3) << 3;
            int m = bm + row;
            bool ok = m < M;
            int ms = ok ? m : 0;
            uint32_t doff = row * (BKP * 2) + off * 2;
            cp_async16(sb + OFF_AH + doff, Aph + (size_t)ms * lda + k0 + off, ok);
            cp_async16(sb + OFF_AL + doff, Apl + (size_t)ms * lda + k0 + off, ok);
        }
    };
    auto prefetch_A = [&](int k0) {
        bool full = (k0 + BK <= K);
#pragma unroll
        for (int u2 = 0; u2 < 2; u2++) {
            int u = tid + u2 * 256;
            int r = u >> 2;
            int o = (u & 3) << 3;
            int m = bm + r;
            bool mok = m < M;
            const float* Ar = A + (size_t)m * K + k0 + o;
            if (full) {
#pragma unroll
                for (int e = 0; e < 8; e++) pv[u2][e] = mok ? __ldg(Ar + e) : 0.f;
            } else {
#pragma unroll
                for (int e = 0; e < 8; e++) {
                    int k = k0 + o + e;
                    pv[u2][e] = (mok && k < K) ? __ldg(Ar + e) : 0.f;
                }
            }
        }
    };
    auto cvt_sts_A = [&](int stage) {
#pragma unroll
        for (int u2 = 0; u2 < 2; u2++) {
            int u = tid + u2 * 256;
            int r = u >> 2;
            int o = (u & 3) << 3;
            unsigned hh[4], ll[4];
#pragma unroll
            for (int p = 0; p < 4; p++) {
                unsigned h = pack2(pv[u2][2 * p], pv[u2][2 * p + 1]);
                float h0 = __uint_as_float(h << 16);
                float h1 = __uint_as_float(h & 0xffff0000u);
                hh[p] = h;
                ll[p] = pack2(pv[u2][2 * p] - h0, pv[u2][2 * p + 1] - h1);
            }
            char* base = dynsmem + stage * STAGE_BYTES + r * (BKP * 2) + o * 2;
            *(uint4*)(base + OFF_AH) = make_uint4(hh[0], hh[1], hh[2], hh[3]);
            *(uint4*)(base + OFF_AL) = make_uint4(ll[0], ll[1], ll[2], ll[3]);
        }
    };

    const int nt = Kpad / BK;
    if (AMODE == 0) {
        prefetch_A(0);
        cvt_sts_A(0);
    } else {
        issue_A_planes(0, 0);
    }
    issue_B(0, 0);
    asm volatile("cp.async.commit_group;" ::: "memory");

    for (int kt = 0; kt < nt; kt++) {
        int cur = kt & 1;
        int nxt = cur ^ 1;
        asm volatile("cp.async.wait_group 0;" ::: "memory");
        __syncthreads();

        bool hn = (kt + 1) < nt;
        int k1 = (kt + 1) * BK;
        if (hn) {
            if (AMODE == 0) prefetch_A(k1);
            else            issue_A_planes(nxt, k1);
            issue_B(nxt, k1);
        }
        asm volatile("cp.async.commit_group;" ::: "memory");

        uint32_t sA = sbase + cur * STAGE_BYTES;
#pragma unroll
        for (int kh = 0; kh < BK; kh += 16) {
            unsigned ah[2][4], al[2][4];
#pragma unroll
            for (int mi = 0; mi < 2; mi++) {
                uint32_t ra = sA + OFF_AH + (rA0 + mi * 16) * (BKP * 2) + (cA + kh) * 2;
                ldmx4(ah[mi], ra);
                ldmx4(al[mi], ra + (OFF_AL - OFF_AH));
            }
#pragma unroll
            for (int nip = 0; nip < 4; nip++) {
                unsigned bh4[4], bl4[4];
                uint32_t rb = sA + OFF_BH + (rB0 + nip * 16) * (BKP * 2) + (cB + kh) * 2;
                ldmx4(bh4, rb);
                ldmx4(bl4, rb + (OFF_BL - OFF_BH));
#pragma unroll
                for (int mi = 0; mi < 2; mi++) {
                    mma16816(acc[mi][2 * nip],     ah[mi], &bh4[0]);
                    mma16816(acc[mi][2 * nip],     ah[mi], &bl4[0]);
                    mma16816(acc[mi][2 * nip],     al[mi], &bh4[0]);
                    mma16816(acc[mi][2 * nip + 1], ah[mi], &bh4[2]);
                    mma16816(acc[mi][2 * nip + 1], ah[mi], &bl4[2]);
                    mma16816(acc[mi][2 * nip + 1], al[mi], &bh4[2]);
                }
            }
        }

        if (AMODE == 0 && hn) cvt_sts_A(nxt);
    }

#pragma unroll
    for (int mi = 0; mi < 2; mi++) {
#pragma unroll
        for (int ni = 0; ni < 8; ni++) {
            int row0 = bm + warp_m + mi * 16 + g;
            int col  = warp_n + ni * 8 + 2 * qt;
            if (col < N) {
                if (row0 < M)
                    *(float2*)&C[(size_t)row0 * N + col] =
                        make_float2(acc[mi][ni][0], acc[mi][ni][1]);
                if (row0 + 8 < M)
                    *(float2*)&C[(size_t)(row0 + 8) * N + col] =
                        make_float2(acc[mi][ni][2], acc[mi][ni][3]);
            }
        }
    }
}

// ======== fused CSR-gather SpMM + bias + ReLU + colsum ========
#define RPW 4
template <int FV>
__global__ __launch_bounds__(256) void spmm_fused_kernel(const float* __restrict__ bias,
                                                         float* __restrict__ colsum) {
    constexpr int VEC = FV / 32;
    __shared__ float cs[FV];
    int tid = threadIdx.x;
    if (tid < FV) cs[tid] = 0.f;
    __syncthreads();
    int lane = tid & 31;
    int warp = (((int)blockIdx.x * blockDim.x) + tid) >> 5;
    int r0 = warp * RPW;

    float bv[VEC], bsum[VEC];
#pragma unroll
    for (int v = 0; v < VEC; v++) {
        bv[v] = bias[lane * VEC + v];
        bsum[v] = 0.f;
    }

    if (r0 < N_NODES) {
        for (int rr = 0; rr < RPW; rr++) {
            int r = r0 + rr;
            if (r >= N_NODES) break;
            int beg = __ldg(&g_rowoff[r]);
            int end = __ldg(&g_rowoff[r + 1]);
            float acc[VEC];
#pragma unroll
            for (int v = 0; v < VEC; v++) acc[v] = 0.f;
            int i = beg;
            for (; i + 2 <= end; i += 2) {
                int2 p0 = __ldg(&g_epack[i]);
                int2 p1 = __ldg(&g_epack[i + 1]);
                float w0 = __int_as_float(p0.y);
                float w1 = __int_as_float(p1.y);
                const float* s0 = &g_support[(size_t)p0.x * FV + lane * VEC];
                const float* s1 = &g_support[(size_t)p1.x * FV + lane * VEC];
                if (VEC == 4) {
                    float4 a4 = *(const float4*)s0;
                    float4 b4 = *(const float4*)s1;
                    acc[0] = fmaf(w0, a4.x, fmaf(w1, b4.x, acc[0]));
                    acc[1] = fmaf(w0, a4.y, fmaf(w1, b4.y, acc[1]));
                    acc[2] = fmaf(w0, a4.z, fmaf(w1, b4.z, acc[2]));
                    acc[3] = fmaf(w0, a4.w, fmaf(w1, b4.w, acc[3]));
                } else {
                    float2 a2 = *(const float2*)s0;
                    float2 b2 = *(const float2*)s1;
                    acc[0] = fmaf(w0, a2.x, fmaf(w1, b2.x, acc[0]));
                    acc[1] = fmaf(w0, a2.y, fmaf(w1, b2.y, acc[1]));
                }
            }
            if (i < end) {
                int2 p = __ldg(&g_epack[i]);
                float w = __int_as_float(p.y);
                const float* s = &g_support[(size_t)p.x * FV + lane * VEC];
                if (VEC == 4) {
                    float4 sv = *(const float4*)s;
                    acc[0] = fmaf(w, sv.x, acc[0]);
                    acc[1] = fmaf(w, sv.y, acc[1]);
                    acc[2] = fmaf(w, sv.z, acc[2]);
                    acc[3] = fmaf(w, sv.w, acc[3]);
                } else {
                    float2 sv = *(const float2*)s;
                    acc[0] = fmaf(w, sv.x, acc[0]);
                    acc[1] = fmaf(w, sv.y, acc[1]);
                }
            }
#pragma unroll
            for (int v = 0; v < VEC; v++) {
                acc[v] = fmaxf(acc[v] + bv[v], 0.f);
                bsum[v] += acc[v];
            }
            if (VEC == 4)
                *(float4*)&g_x[(size_t)r * FV + lane * 4] =
                    make_float4(acc[0], acc[1], acc[2], acc[3]);
            else
                *(float2*)&g_x[(size_t)r * FV + lane * 2] =
                    make_float2(acc[0], acc[1]);
        }
#pragma unroll
        for (int v = 0; v < VEC; v++)
            atomicAdd(&cs[lane * VEC + v], bsum[v]);
    }
    __syncthreads();
    if (tid < FV) atomicAdd(&colsum[tid], cs[tid]);
}

// -------- PairNorm F=128, fused bf16 hi/lo split output --------
__global__ void pairnorm128_split_kernel(const float* __restrict__ colsum) {
    int gw = ((int)blockIdx.x * blockDim.x + threadIdx.x) >> 5;
    int lane = threadIdx.x & 31;
    if (gw >= N_NODES) return;
    const float invN = 1.0f / N_NODES;
    float4 mean = *(const float4*)&colsum[lane * 4];
    float4 v = *(const float4*)&g_x[(size_t)gw * F_HID + lane * 4];
    v.x -= mean.x * invN; v.y -= mean.y * invN;
    v.z -= mean.z * invN; v.w -= mean.w * invN;
    float ss = v.x * v.x + v.y * v.y + v.z * v.z + v.w * v.w;
#pragma unroll
    for (int o = 16; o > 0; o >>= 1) ss += __shfl_xor_sync(0xffffffffu, ss, o);
    float inv = rsqrtf(EPSV + ss);
    float y0 = v.x * inv, y1 = v.y * inv, y2 = v.z * inv, y3 = v.w * inv;
    unsigned h01 = pack2(y0, y1);
    unsigned h23 = pack2(y2, y3);
    float f0 = __uint_as_float(h01 << 16), f1 = __uint_as_float(h01 & 0xffff0000u);
    float f2 = __uint_as_float(h23 << 16), f3 = __uint_as_float(h23 & 0xffff0000u);
    unsigned l01 = pack2(y0 - f0, y1 - f1);
    unsigned l23 = pack2(y2 - f2, y3 - f3);
    *(uint2*)&g_Xh[(size_t)gw * F_HID + lane * 4] = make_uint2(h01, h23);
    *(uint2*)&g_Xl[(size_t)gw * F_HID + lane * 4] = make_uint2(l01, l23);
}

// -------- PairNorm F=64 --------
__global__ void pairnorm64_kernel(const float* __restrict__ colsum) {
    int gw = ((int)blockIdx.x * blockDim.x + threadIdx.x) >> 5;
    int lane = threadIdx.x & 31;
    if (gw >= N_NODES) return;
    const float invN = 1.0f / N_NODES;
    float2 mean = *(const float2*)&colsum[lane * 2];
    float2 v = *(const float2*)&g_x[(size_t)gw * F_OUTD + lane * 2];
    v.x -= mean.x * invN;
    v.y -= mean.y * invN;
    float ss = v.x * v.x + v.y * v.y;
#pragma unroll
    for (int o = 16; o > 0; o >>= 1) ss += __shfl_xor_sync(0xffffffffu, ss, o);
    float inv = rsqrtf(EPSV + ss);
    *(float2*)&g_x[(size_t)gw * F_OUTD + lane * 2] = make_float2(v.x * inv, v.y * inv);
}

// -------- decode --------
__global__ void decode_kernel(const int* __restrict__ pos, const int* __restrict__ neg,
                              float* __restrict__ out) {
    int gwarp = ((int)blockIdx.x * blockDim.x + threadIdx.x) >> 5;
    int lane = threadIdx.x & 31;
    if (gwarp >= N_EDGES) return;
    const int* ei = (gwarp < 20000) ? (pos + (size_t)gwarp * 2)
                                    : (neg + (size_t)(gwarp - 20000) * 2);
    int a = ei[0];
    int b = ei[1];
    const float* xa = &g_x[(size_t)a * F_OUTD];
    const float* xb = &g_x[(size_t)b * F_OUTD];
    float s = xa[lane] * xb[lane] + xa[lane + 32] * xb[lane + 32];
#pragma unroll
    for (int o = 16; o > 0; o >>= 1) s += __shfl_xor_sync(0xffffffffu, s, o);
    if (lane == 0) out[gwarp] = 1.0f / (1.0f + expf(-s));
}

// ---------------------------------------------------------------
extern "C" void kernel_launch(void* const* d_in, const int* in_sizes, int n_in,
                              void* d_out, int out_size) {
    const float* in_feature = (const float*)d_in[0];
    const int*   adj_row    = (const int*)d_in[1];
    const int*   adj_col    = (const int*)d_in[2];
    const float* adj_val    = (const float*)d_in[3];
    const int*   pos_ei     = (const int*)d_in[4];
    const int*   neg_ei     = (const int*)d_in[5];
    const float* W0 = (const float*)d_in[6];
    const float* W1 = (const float*)d_in[8];
    const float* W2 = (const float*)d_in[10];
    const float* Bv[3] = { (const float*)d_in[7], (const float*)d_in[9], (const float*)d_in[11] };
    float* out = (float*)d_out;

    float* d_support = nullptr;
    float* d_colsum = nullptr;
    __nv_bfloat16 *d_Xh = nullptr, *d_Xl = nullptr;
    __nv_bfloat16 *d_Wh[3], *d_Wl[3];
    cudaGetSymbolAddress((void**)&d_support, g_support);
    cudaGetSymbolAddress((void**)&d_colsum, g_colsum3);
    cudaGetSymbolAddress((void**)&d_Xh, g_Xh);
    cudaGetSymbolAddress((void**)&d_Xl, g_Xl);
    cudaGetSymbolAddress((void**)&d_Wh[0], g_W0h);
    cudaGetSymbolAddress((void**)&d_Wl[0], g_W0l);
    cudaGetSymbolAddress((void**)&d_Wh[1], g_W1h);
    cudaGetSymbolAddress((void**)&d_Wl[1], g_W1l);
    cudaGetSymbolAddress((void**)&d_Wh[2], g_W2h);
    cudaGetSymbolAddress((void**)&d_Wl[2], g_W2l);

    cudaFuncSetAttribute(gemm_tc_kernel<0>, cudaFuncAttributeMaxDynamicSharedMemorySize, GEMM_SMEM);
    cudaFuncSetAttribute(gemm_tc_kernel<1>, cudaFuncAttributeMaxDynamicSharedMemorySize, GEMM_SMEM);

    // ---- prep (zero + all W splits) and CSR build ----
    prep_kernel<<<(PREP_TOTAL + 255) / 256, 256>>>(W0, W1, W2);
    csr_hist_kernel<<<(NNZ + 255) / 256, 256>>>(adj_row);
    csr_scanA_kernel<<<NBLK_SCAN, SCAN_BLK>>>();
    csr_scanB_kernel<<<1, 128>>>();
    csr_scanC_kernel<<<(N_NODES + 255) / 256, 256>>>();
    csr_scatter_kernel<<<(NNZ + 255) / 256, 256>>>(adj_row, adj_col, adj_val);

    const int Kdims[3] = { F_IN, F_HID, F_HID };
    const int Ndims[3] = { F_HID, F_HID, F_OUTD };
    const int Kpads[3] = { KPAD0, F_HID, F_HID };

    for (int l = 0; l < 3; l++) {
        int K = Kdims[l], F = Ndims[l], Kpadl = Kpads[l];

        dim3 ggrid(1, (N_NODES + BM - 1) / BM);
        if (l == 0)
            gemm_tc_kernel<0><<<ggrid, 256, GEMM_SMEM>>>(
                in_feature, nullptr, nullptr, d_Wh[0], d_Wl[0],
                d_support, N_NODES, K, Kpadl, 0, KPAD0, F);
        else
            gemm_tc_kernel<1><<<ggrid, 256, GEMM_SMEM>>>(
                nullptr, d_Xh, d_Xl, d_Wh[l], d_Wl[l],
                d_support, N_NODES, K, Kpadl, F_HID, F_HID, F);

        int nwarps = (N_NODES + RPW - 1) / RPW;
        int nblk = (nwarps * 32 + 255) / 256;
        float* csum = d_colsum + l * F_HID;
        if (F == 128)
            spmm_fused_kernel<128><<<nblk, 256>>>(Bv[l], csum);
        else
            spmm_fused_kernel<64><<<nblk, 256>>>(Bv[l], csum);

        if (l < 2)
            pairnorm128_split_kernel<<<(N_NODES * 32 + 255) / 256, 256>>>(csum);
        else
            pairnorm64_kernel<<<(N_NODES * 32 + 255) / 256, 256>>>(csum);
    }

    int dblocks = (N_EDGES * 32 + 255) / 256;
    decode_kernel<<<dblocks, 256>>>(pos_ei, neg_ei, out);
}

// round 10
// speedup vs baseline: 3.2836x; 1.0610x over previous
#include <cuda_runtime.h>
#include <cuda_bf16.h>
#include <math.h>
#include <stdint.h>

#define N_NODES 100000
#define NNZ     1000000
#define F_IN    1433
#define F_HID   128
#define F_OUTD  64
#define N_EDGES 40000
#define EPSV    1e-6f
#define KPAD0   1440
#define SCAN_BLK 1024
#define NBLK_SCAN ((N_NODES + SCAN_BLK - 1) / SCAN_BLK)   // 98

// -------- static device scratch --------
__device__ float g_support[(size_t)N_NODES * F_HID];
__device__ float g_x[(size_t)N_NODES * F_HID];
__device__ float g_colsum3[3][F_HID];
__device__ __nv_bfloat16 g_Xh[(size_t)N_NODES * F_HID];
__device__ __nv_bfloat16 g_Xl[(size_t)N_NODES * F_HID];
__device__ __nv_bfloat16 g_W0h[(size_t)128 * KPAD0];
__device__ __nv_bfloat16 g_W0l[(size_t)128 * KPAD0];
__device__ __nv_bfloat16 g_W1h[(size_t)128 * F_HID];
__device__ __nv_bfloat16 g_W1l[(size_t)128 * F_HID];
__device__ __nv_bfloat16 g_W2h[(size_t)128 * F_HID];
__device__ __nv_bfloat16 g_W2l[(size_t)128 * F_HID];
// CSR
__device__ int  g_rowcnt[N_NODES];
__device__ int  g_rowoff[N_NODES + 1];
__device__ int  g_blksum[128];
__device__ int2 g_epack[NNZ];

__device__ __forceinline__ unsigned pack2(float f0, float f1) {
    unsigned r;
    asm("cvt.rn.bf16x2.f32 %0, %1, %2;" : "=r"(r) : "f"(f1), "f"(f0));
    return r;
}

// ================= prep: zero colsums, split all W =================
#define U0 (128 * (KPAD0 / 8))        // 23040
#define U12 (128 * (F_HID / 8))       // 2048
#define PREP_BASE 512
#define PREP_TOTAL (PREP_BASE + U0 + 2 * U12)

__device__ __forceinline__ void split8(const float* __restrict__ W, int K, int n, int k0,
                                       __nv_bfloat16* dsth, __nv_bfloat16* dstl, int ldk) {
    float v[8];
#pragma unroll
    for (int e = 0; e < 8; e++) {
        int k = k0 + e;
        v[e] = (k < K) ? __ldg(&W[(size_t)k * 128 + n]) : 0.f;
    }
    unsigned hh[4], ll[4];
#pragma unroll
    for (int p = 0; p < 4; p++) {
        unsigned h = pack2(v[2 * p], v[2 * p + 1]);
        float h0 = __uint_as_float(h << 16);
        float h1 = __uint_as_float(h & 0xffff0000u);
        hh[p] = h;
        ll[p] = pack2(v[2 * p] - h0, v[2 * p + 1] - h1);
    }
    *(uint4*)&dsth[(size_t)n * ldk + k0] = make_uint4(hh[0], hh[1], hh[2], hh[3]);
    *(uint4*)&dstl[(size_t)n * ldk + k0] = make_uint4(ll[0], ll[1], ll[2], ll[3]);
}

__global__ void prep_kernel(const float* __restrict__ W0, const float* __restrict__ W1,
                            const float* __restrict__ W2) {
    int t = blockIdx.x * blockDim.x + threadIdx.x;
    if (t < 384) { ((float*)g_colsum3)[t] = 0.f; return; }
    if (t < PREP_BASE) return;
    int u = t - PREP_BASE;
    if (u < U0) {
        int n = u / (KPAD0 / 8);
        int k0 = (u - n * (KPAD0 / 8)) << 3;
        split8(W0, F_IN, n, k0, g_W0h, g_W0l, KPAD0);
    } else if (u < U0 + U12) {
        int v = u - U0;
        int n = v >> 4;
        int k0 = (v & 15) << 3;
        split8(W1, F_HID, n, k0, g_W1h, g_W1l, F_HID);
    } else if (u < U0 + 2 * U12) {
        int v = u - U0 - U12;
        int n = v >> 4;
        int k0 = (v & 15) << 3;
        float v8[8];
#pragma unroll
        for (int e = 0; e < 8; e++)
            v8[e] = (n < F_OUTD) ? __ldg(&W2[(size_t)(k0 + e) * F_OUTD + n]) : 0.f;
        unsigned hh[4], ll[4];
#pragma unroll
        for (int p = 0; p < 4; p++) {
            unsigned h = pack2(v8[2 * p], v8[2 * p + 1]);
            float h0 = __uint_as_float(h << 16);
            float h1 = __uint_as_float(h & 0xffff0000u);
            hh[p] = h;
            ll[p] = pack2(v8[2 * p] - h0, v8[2 * p + 1] - h1);
        }
        *(uint4*)&g_W2h[(size_t)n * F_HID + k0] = make_uint4(hh[0], hh[1], hh[2], hh[3]);
        *(uint4*)&g_W2l[(size_t)n * F_HID + k0] = make_uint4(ll[0], ll[1], ll[2], ll[3]);
    }
}

// ================= CSR build =================
__global__ void csr_zero_kernel() {
    int i = blockIdx.x * blockDim.x + threadIdx.x;
    if (i < N_NODES) g_rowcnt[i] = 0;
}
__global__ void csr_hist_kernel(const int* __restrict__ row) {
    int e = blockIdx.x * blockDim.x + threadIdx.x;
    if (e < NNZ) atomicAdd(&g_rowcnt[row[e]], 1);
}
__global__ __launch_bounds__(SCAN_BLK) void csr_scanA_kernel() {
    __shared__ int sm[SCAN_BLK];
    int t = threadIdx.x;
    int i = blockIdx.x * SCAN_BLK + t;
    int v = (i < N_NODES) ? g_rowcnt[i] : 0;
    sm[t] = v;
    __syncthreads();
#pragma unroll
    for (int s = 1; s < SCAN_BLK; s <<= 1) {
        int a = (t >= s) ? sm[t - s] : 0;
        __syncthreads();
        sm[t] += a;
        __syncthreads();
    }
    if (i < N_NODES) g_rowoff[i] = sm[t] - v;
    if (t == SCAN_BLK - 1) g_blksum[blockIdx.x] = sm[t];
}
__global__ void csr_scanB_kernel() {
    __shared__ int sm[128];
    int t = threadIdx.x;
    int v = (t < NBLK_SCAN) ? g_blksum[t] : 0;
    sm[t] = v;
    __syncthreads();
#pragma unroll
    for (int s = 1; s < 128; s <<= 1) {
        int a = (t >= s) ? sm[t - s] : 0;
        __syncthreads();
        sm[t] += a;
        __syncthreads();
    }
    g_blksum[t] = sm[t] - v;
}
__global__ void csr_scanC_kernel() {
    int i = blockIdx.x * blockDim.x + threadIdx.x;
    if (i < N_NODES) {
        g_rowoff[i] += g_blksum[i >> 10];
        g_rowcnt[i] = 0;
    }
    if (i == 0) g_rowoff[N_NODES] = NNZ;
}
__global__ void csr_scatter_kernel(const int* __restrict__ row, const int* __restrict__ col,
                                   const float* __restrict__ val) {
    int e = blockIdx.x * blockDim.x + threadIdx.x;
    if (e >= NNZ) return;
    int r = row[e];
    int p = g_rowoff[r] + atomicAdd(&g_rowcnt[r], 1);
    g_epack[p] = make_int2(col[e], __float_as_int(val[e]));
}

// ============ mma.sync GEMM, bf16 hi/lo 3-term, double-buffered + ldmatrix ============
#define BM 128
#define BK 32
#define BKP 40
#define PLANE_BYTES (128 * BKP * 2)
#define OFF_AH 0
#define OFF_AL (PLANE_BYTES)
#define OFF_BH (2 * PLANE_BYTES)
#define OFF_BL (3 * PLANE_BYTES)
#define STAGE_BYTES (4 * PLANE_BYTES)
#define GEMM_SMEM (2 * STAGE_BYTES)

__device__ __forceinline__ void mma16816(float c[4], const unsigned a[4], const unsigned* b) {
    asm volatile(
        "mma.sync.aligned.m16n8k16.row.col.f32.bf16.bf16.f32 "
        "{%0,%1,%2,%3}, {%4,%5,%6,%7}, {%8,%9}, {%0,%1,%2,%3};"
        : "+f"(c[0]), "+f"(c[1]), "+f"(c[2]), "+f"(c[3])
        : "r"(a[0]), "r"(a[1]), "r"(a[2]), "r"(a[3]), "r"(b[0]), "r"(b[1]));
}
__device__ __forceinline__ void ldmx4(unsigned r[4], uint32_t addr) {
    asm volatile("ldmatrix.sync.aligned.m8n8.x4.shared.b16 {%0,%1,%2,%3}, [%4];"
                 : "=r"(r[0]), "=r"(r[1]), "=r"(r[2]), "=r"(r[3]) : "r"(addr));
}
__device__ __forceinline__ void cp_async16(uint32_t dst, const void* src, bool ok) {
    int bytes = ok ? 16 : 0;
    asm volatile("cp.async.cg.shared.global [%0], [%1], 16, %2;"
                 :: "r"(dst), "l"(src), "r"(bytes));
}

// AMODE 0: A fp32 (layer0). AMODE 1: A bf16 planes. BNT: B tile width (128 or 64).
template <int AMODE, int BNT>
__global__ __launch_bounds__(256, 2) void gemm_tc_kernel(
    const float* __restrict__ A,
    const __nv_bfloat16* __restrict__ Aph, const __nv_bfloat16* __restrict__ Apl,
    const __nv_bfloat16* __restrict__ Wh, const __nv_bfloat16* __restrict__ Wl,
    float* __restrict__ C, int M, int K, int Kpad, int lda, int ldw, int N)
{
    constexpr int NN = BNT / 16;          // 8-col tiles per warp (8 or 4)
    extern __shared__ __align__(16) char dynsmem[];
    const uint32_t sbase = (uint32_t)__cvta_generic_to_shared(dynsmem);

    const int tid  = threadIdx.x;
    const int wid  = tid >> 5;
    const int lane = tid & 31;
    const int bm   = blockIdx.y * BM;
    const int g    = lane >> 2;
    const int qt   = lane & 3;
    const int warp_m = (wid >> 1) * 32;
    const int warp_n = (wid & 1) * (BNT / 2);

    const int rA0 = warp_m + (lane & 7) + (lane & 8);
    const int cA  = (lane & 16) >> 1;
    const int rB0 = warp_n + (lane & 7) + ((lane & 16) >> 1);
    const int cB  = (lane & 8);

    float acc[2][NN][4];
#pragma unroll
    for (int mi = 0; mi < 2; mi++)
#pragma unroll
        for (int ni = 0; ni < NN; ni++)
#pragma unroll
            for (int q = 0; q < 4; q++) acc[mi][ni][q] = 0.f;

    float pv[2][8];

    auto issue_B = [&](int stage, int k0) {
        uint32_t sb = sbase + stage * STAGE_BYTES;
#pragma unroll
        for (int p = 0; p < BNT / 64; p++) {
            int c = tid + p * 256;
            int row = c >> 2;
            int off = (c & 3) << 3;
            uint32_t doff = row * (BKP * 2) + off * 2;
            cp_async16(sb + OFF_BH + doff, &Wh[(size_t)row * ldw + k0 + off], true);
            cp_async16(sb + OFF_BL + doff, &Wl[(size_t)row * ldw + k0 + off], true);
        }
    };
    auto issue_A_planes = [&](int stage, int k0) {
        uint32_t sb = sbase + stage * STAGE_BYTES;
#pragma unroll
        for (int p = 0; p < 2; p++) {
            int c = tid + p * 256;
            int row = c >> 2;
            int off = (c & 3) << 3;
            int m = bm + row;
            bool ok = m < M;
            int ms = ok ? m : 0;
            uint32_t doff = row * (BKP * 2) + off * 2;
            cp_async16(sb + OFF_AH + doff, Aph + (size_t)ms * lda + k0 + off, ok);
            cp_async16(sb + OFF_AL + doff, Apl + (size_t)ms * lda + k0 + off, ok);
        }
    };
    auto prefetch_A = [&](int k0) {
        bool full = (k0 + BK <= K);
#pragma unroll
        for (int u2 = 0; u2 < 2; u2++) {
            int u = tid + u2 * 256;
            int r = u >> 2;
            int o = (u & 3) << 3;
            int m = bm + r;
            bool mok = m < M;
            const float* Ar = A + (size_t)m * K + k0 + o;
            if (full) {
#pragma unroll
                for (int e = 0; e < 8; e++) pv[u2][e] = mok ? __ldg(Ar + e) : 0.f;
            } else {
#pragma unroll
                for (int e = 0; e < 8; e++) {
                    int k = k0 + o + e;
                    pv[u2][e] = (mok && k < K) ? __ldg(Ar + e) : 0.f;
                }
            }
        }
    };
    auto cvt_sts_A = [&](int stage) {
#pragma unroll
        for (int u2 = 0; u2 < 2; u2++) {
            int u = tid + u2 * 256;
            int r = u >> 2;
            int o = (u & 3) << 3;
            unsigned hh[4], ll[4];
#pragma unroll
            for (int p = 0; p < 4; p++) {
                unsigned h = pack2(pv[u2][2 * p], pv[u2][2 * p + 1]);
                float h0 = __uint_as_float(h << 16);
                float h1 = __uint_as_float(h & 0xffff0000u);
                hh[p] = h;
                ll[p] = pack2(pv[u2][2 * p] - h0, pv[u2][2 * p + 1] - h1);
            }
            char* base = dynsmem + stage * STAGE_BYTES + r * (BKP * 2) + o * 2;
            *(uint4*)(base + OFF_AH) = make_uint4(hh[0], hh[1], hh[2], hh[3]);
            *(uint4*)(base + OFF_AL) = make_uint4(ll[0], ll[1], ll[2], ll[3]);
        }
    };

    const int nt = Kpad / BK;
    if (AMODE == 0) {
        prefetch_A(0);
        cvt_sts_A(0);
    } else {
        issue_A_planes(0, 0);
    }
    issue_B(0, 0);
    asm volatile("cp.async.commit_group;" ::: "memory");

    for (int kt = 0; kt < nt; kt++) {
        int cur = kt & 1;
        int nxt = cur ^ 1;
        asm volatile("cp.async.wait_group 0;" ::: "memory");
        __syncthreads();

        bool hn = (kt + 1) < nt;
        int k1 = (kt + 1) * BK;
        if (hn) {
            if (AMODE == 0) prefetch_A(k1);
            else            issue_A_planes(nxt, k1);
            issue_B(nxt, k1);
        }
        asm volatile("cp.async.commit_group;" ::: "memory");

        uint32_t sA = sbase + cur * STAGE_BYTES;
#pragma unroll
        for (int kh = 0; kh < BK; kh += 16) {
            unsigned ah[2][4], al[2][4];
#pragma unroll
            for (int mi = 0; mi < 2; mi++) {
                uint32_t ra = sA + OFF_AH + (rA0 + mi * 16) * (BKP * 2) + (cA + kh) * 2;
                ldmx4(ah[mi], ra);
                ldmx4(al[mi], ra + (OFF_AL - OFF_AH));
            }
#pragma unroll
            for (int nip = 0; nip < NN / 2; nip++) {
                unsigned bh4[4], bl4[4];
                uint32_t rb = sA + OFF_BH + (rB0 + nip * 16) * (BKP * 2) + (cB + kh) * 2;
                ldmx4(bh4, rb);
                ldmx4(bl4, rb + (OFF_BL - OFF_BH));
#pragma unroll
                for (int mi = 0; mi < 2; mi++) {
                    mma16816(acc[mi][2 * nip],     ah[mi], &bh4[0]);
                    mma16816(acc[mi][2 * nip],     ah[mi], &bl4[0]);
                    mma16816(acc[mi][2 * nip],     al[mi], &bh4[0]);
                    mma16816(acc[mi][2 * nip + 1], ah[mi], &bh4[2]);
                    mma16816(acc[mi][2 * nip + 1], ah[mi], &bl4[2]);
                    mma16816(acc[mi][2 * nip + 1], al[mi], &bh4[2]);
                }
            }
        }

        if (AMODE == 0 && hn) cvt_sts_A(nxt);
    }

#pragma unroll
    for (int mi = 0; mi < 2; mi++) {
#pragma unroll
        for (int ni = 0; ni < NN; ni++) {
            int row0 = bm + warp_m + mi * 16 + g;
            int col  = warp_n + ni * 8 + 2 * qt;
            if (col < N) {
                if (row0 < M)
                    *(float2*)&C[(size_t)row0 * N + col] =
                        make_float2(acc[mi][ni][0], acc[mi][ni][1]);
                if (row0 + 8 < M)
                    *(float2*)&C[(size_t)(row0 + 8) * N + col] =
                        make_float2(acc[mi][ni][2], acc[mi][ni][3]);
            }
        }
    }
}

// ======== fused CSR-gather SpMM + bias + ReLU + colsum ========
#define RPW 4
template <int FV>
__global__ __launch_bounds__(256) void spmm_fused_kernel(const float* __restrict__ bias,
                                                         float* __restrict__ colsum) {
    constexpr int VEC = FV / 32;
    __shared__ float cs[FV];
    int tid = threadIdx.x;
    if (tid < FV) cs[tid] = 0.f;
    __syncthreads();
    int lane = tid & 31;
    int warp = (((int)blockIdx.x * blockDim.x) + tid) >> 5;
    int r0 = warp * RPW;

    float bv[VEC], bsum[VEC];
#pragma unroll
    for (int v = 0; v < VEC; v++) {
        bv[v] = bias[lane * VEC + v];
        bsum[v] = 0.f;
    }

    if (r0 < N_NODES) {
        for (int rr = 0; rr < RPW; rr++) {
            int r = r0 + rr;
            if (r >= N_NODES) break;
            int beg = __ldg(&g_rowoff[r]);
            int end = __ldg(&g_rowoff[r + 1]);
            float acc[VEC];
#pragma unroll
            for (int v = 0; v < VEC; v++) acc[v] = 0.f;
            int i = beg;
            for (; i + 4 <= end; i += 4) {
                int2 p0 = __ldg(&g_epack[i]);
                int2 p1 = __ldg(&g_epack[i + 1]);
                int2 p2 = __ldg(&g_epack[i + 2]);
                int2 p3 = __ldg(&g_epack[i + 3]);
                const float* s0 = &g_support[(size_t)p0.x * FV + lane * VEC];
                const float* s1 = &g_support[(size_t)p1.x * FV + lane * VEC];
                const float* s2 = &g_support[(size_t)p2.x * FV + lane * VEC];
                const float* s3 = &g_support[(size_t)p3.x * FV + lane * VEC];
                float w0 = __int_as_float(p0.y), w1 = __int_as_float(p1.y);
                float w2 = __int_as_float(p2.y), w3 = __int_as_float(p3.y);
                if (VEC == 4) {
                    float4 a4 = *(const float4*)s0;
                    float4 b4 = *(const float4*)s1;
                    float4 c4 = *(const float4*)s2;
                    float4 d4 = *(const float4*)s3;
                    acc[0] = fmaf(w0, a4.x, fmaf(w1, b4.x, fmaf(w2, c4.x, fmaf(w3, d4.x, acc[0]))));
                    acc[1] = fmaf(w0, a4.y, fmaf(w1, b4.y, fmaf(w2, c4.y, fmaf(w3, d4.y, acc[1]))));
                    acc[2] = fmaf(w0, a4.z, fmaf(w1, b4.z, fmaf(w2, c4.z, fmaf(w3, d4.z, acc[2]))));
                    acc[3] = fmaf(w0, a4.w, fmaf(w1, b4.w, fmaf(w2, c4.w, fmaf(w3, d4.w, acc[3]))));
                } else {
                    float2 a2 = *(const float2*)s0;
                    float2 b2 = *(const float2*)s1;
                    float2 c2 = *(const float2*)s2;
                    float2 d2 = *(const float2*)s3;
                    acc[0] = fmaf(w0, a2.x, fmaf(w1, b2.x, fmaf(w2, c2.x, fmaf(w3, d2.x, acc[0]))));
                    acc[1] = fmaf(w0, a2.y, fmaf(w1, b2.y, fmaf(w2, c2.y, fmaf(w3, d2.y, acc[1]))));
                }
            }
            for (; i < end; i++) {
                int2 p = __ldg(&g_epack[i]);
                float w = __int_as_float(p.y);
                const float* s = &g_support[(size_t)p.x * FV + lane * VEC];
                if (VEC == 4) {
                    float4 sv = *(const float4*)s;
                    acc[0] = fmaf(w, sv.x, acc[0]);
                    acc[1] = fmaf(w, sv.y, acc[1]);
                    acc[2] = fmaf(w, sv.z, acc[2]);
                    acc[3] = fmaf(w, sv.w, acc[3]);
                } else {
                    float2 sv = *(const float2*)s;
                    acc[0] = fmaf(w, sv.x, acc[0]);
                    acc[1] = fmaf(w, sv.y, acc[1]);
                }
            }
#pragma unroll
            for (int v = 0; v < VEC; v++) {
                acc[v] = fmaxf(acc[v] + bv[v], 0.f);
                bsum[v] += acc[v];
            }
            if (VEC == 4)
                *(float4*)&g_x[(size_t)r * FV + lane * 4] =
                    make_float4(acc[0], acc[1], acc[2], acc[3]);
            else
                *(float2*)&g_x[(size_t)r * FV + lane * 2] =
                    make_float2(acc[0], acc[1]);
        }
#pragma unroll
        for (int v = 0; v < VEC; v++)
            atomicAdd(&cs[lane * VEC + v], bsum[v]);
    }
    __syncthreads();
    if (tid < FV) atomicAdd(&colsum[tid], cs[tid]);
}

// -------- PairNorm F=128, fused bf16 hi/lo split output --------
__global__ void pairnorm128_split_kernel(const float* __restrict__ colsum) {
    int gw = ((int)blockIdx.x * blockDim.x + threadIdx.x) >> 5;
    int lane = threadIdx.x & 31;
    if (gw >= N_NODES) return;
    const float invN = 1.0f / N_NODES;
    float4 mean = *(const float4*)&colsum[lane * 4];
    float4 v = *(const float4*)&g_x[(size_t)gw * F_HID + lane * 4];
    v.x -= mean.x * invN; v.y -= mean.y * invN;
    v.z -= mean.z * invN; v.w -= mean.w * invN;
    float ss = v.x * v.x + v.y * v.y + v.z * v.z + v.w * v.w;
#pragma unroll
    for (int o = 16; o > 0; o >>= 1) ss += __shfl_xor_sync(0xffffffffu, ss, o);
    float inv = rsqrtf(EPSV + ss);
    float y0 = v.x * inv, y1 = v.y * inv, y2 = v.z * inv, y3 = v.w * inv;
    unsigned h01 = pack2(y0, y1);
    unsigned h23 = pack2(y2, y3);
    float f0 = __uint_as_float(h01 << 16), f1 = __uint_as_float(h01 & 0xffff0000u);
    float f2 = __uint_as_float(h23 << 16), f3 = __uint_as_float(h23 & 0xffff0000u);
    unsigned l01 = pack2(y0 - f0, y1 - f1);
    unsigned l23 = pack2(y2 - f2, y3 - f3);
    *(uint2*)&g_Xh[(size_t)gw * F_HID + lane * 4] = make_uint2(h01, h23);
    *(uint2*)&g_Xl[(size_t)gw * F_HID + lane * 4] = make_uint2(l01, l23);
}

// -------- PairNorm F=64 --------
__global__ void pairnorm64_kernel(const float* __restrict__ colsum) {
    int gw = ((int)blockIdx.x * blockDim.x + threadIdx.x) >> 5;
    int lane = threadIdx.x & 31;
    if (gw >= N_NODES) return;
    const float invN = 1.0f / N_NODES;
    float2 mean = *(const float2*)&colsum[lane * 2];
    float2 v = *(const float2*)&g_x[(size_t)gw * F_OUTD + lane * 2];
    v.x -= mean.x * invN;
    v.y -= mean.y * invN;
    float ss = v.x * v.x + v.y * v.y;
#pragma unroll
    for (int o = 16; o > 0; o >>= 1) ss += __shfl_xor_sync(0xffffffffu, ss, o);
    float inv = rsqrtf(EPSV + ss);
    *(float2*)&g_x[(size_t)gw * F_OUTD + lane * 2] = make_float2(v.x * inv, v.y * inv);
}

// -------- decode --------
__global__ void decode_kernel(const int* __restrict__ pos, const int* __restrict__ neg,
                              float* __restrict__ out) {
    int gwarp = ((int)blockIdx.x * blockDim.x + threadIdx.x) >> 5;
    int lane = threadIdx.x & 31;
    if (gwarp >= N_EDGES) return;
    const int* ei = (gwarp < 20000) ? (pos + (size_t)gwarp * 2)
                                    : (neg + (size_t)(gwarp - 20000) * 2);
    int a = ei[0];
    int b = ei[1];
    const float* xa = &g_x[(size_t)a * F_OUTD];
    const float* xb = &g_x[(size_t)b * F_OUTD];
    float s = xa[lane] * xb[lane] + xa[lane + 32] * xb[lane + 32];
#pragma unroll
    for (int o = 16; o > 0; o >>= 1) s += __shfl_xor_sync(0xffffffffu, s, o);
    if (lane == 0) out[gwarp] = 1.0f / (1.0f + expf(-s));
}

// ---------------------------------------------------------------
extern "C" void kernel_launch(void* const* d_in, const int* in_sizes, int n_in,
                              void* d_out, int out_size) {
    const float* in_feature = (const float*)d_in[0];
    const int*   adj_row    = (const int*)d_in[1];
    const int*   adj_col    = (const int*)d_in[2];
    const float* adj_val    = (const float*)d_in[3];
    const int*   pos_ei     = (const int*)d_in[4];
    const int*   neg_ei     = (const int*)d_in[5];
    const float* W0 = (const float*)d_in[6];
    const float* W1 = (const float*)d_in[8];
    const float* W2 = (const float*)d_in[10];
    const float* Bv[3] = { (const float*)d_in[7], (const float*)d_in[9], (const float*)d_in[11] };
    float* out = (float*)d_out;

    float* d_support = nullptr;
    float* d_colsum = nullptr;
    __nv_bfloat16 *d_Xh = nullptr, *d_Xl = nullptr;
    __nv_bfloat16 *d_Wh[3], *d_Wl[3];
    cudaGetSymbolAddress((void**)&d_support, g_support);
    cudaGetSymbolAddress((void**)&d_colsum, g_colsum3);
    cudaGetSymbolAddress((void**)&d_Xh, g_Xh);
    cudaGetSymbolAddress((void**)&d_Xl, g_Xl);
    cudaGetSymbolAddress((void**)&d_Wh[0], g_W0h);
    cudaGetSymbolAddress((void**)&d_Wl[0], g_W0l);
    cudaGetSymbolAddress((void**)&d_Wh[1], g_W1h);
    cudaGetSymbolAddress((void**)&d_Wl[1], g_W1l);
    cudaGetSymbolAddress((void**)&d_Wh[2], g_W2h);
    cudaGetSymbolAddress((void**)&d_Wl[2], g_W2l);

    cudaFuncSetAttribute((const void*)gemm_tc_kernel<0, 128>,
                         cudaFuncAttributeMaxDynamicSharedMemorySize, GEMM_SMEM);
    cudaFuncSetAttribute((const void*)gemm_tc_kernel<1, 128>,
                         cudaFuncAttributeMaxDynamicSharedMemorySize, GEMM_SMEM);
    cudaFuncSetAttribute((const void*)gemm_tc_kernel<1, 64>,
                         cudaFuncAttributeMaxDynamicSharedMemorySize, GEMM_SMEM);

    // one-time side stream + events (work enqueued is identical every call)
    static cudaStream_t s2 = nullptr;
    static cudaEvent_t evF = nullptr, evJ = nullptr;
    if (s2 == nullptr) {
        cudaStreamCreateWithFlags(&s2, cudaStreamNonBlocking);
        cudaEventCreateWithFlags(&evF, cudaEventDisableTiming);
        cudaEventCreateWithFlags(&evJ, cudaEventDisableTiming);
    }

    // ---- fork: CSR build on side stream, overlapping prep + GEMM0 ----
    cudaEventRecord(evF, 0);
    cudaStreamWaitEvent(s2, evF, 0);
    csr_zero_kernel<<<(N_NODES + 255) / 256, 256, 0, s2>>>();
    csr_hist_kernel<<<(NNZ + 255) / 256, 256, 0, s2>>>(adj_row);
    csr_scanA_kernel<<<NBLK_SCAN, SCAN_BLK, 0, s2>>>();
    csr_scanB_kernel<<<1, 128, 0, s2>>>();
    csr_scanC_kernel<<<(N_NODES + 255) / 256, 256, 0, s2>>>();
    csr_scatter_kernel<<<(NNZ + 255) / 256, 256, 0, s2>>>(adj_row, adj_col, adj_val);
    cudaEventRecord(evJ, s2);

    // ---- main stream: prep + layer pipeline ----
    prep_kernel<<<(PREP_TOTAL + 255) / 256, 256>>>(W0, W1, W2);

    const int Kdims[3] = { F_IN, F_HID, F_HID };
    const int Ndims[3] = { F_HID, F_HID, F_OUTD };
    const int Kpads[3] = { KPAD0, F_HID, F_HID };

    for (int l = 0; l < 3; l++) {
        int K = Kdims[l], F = Ndims[l], Kpadl = Kpads[l];

        dim3 ggrid(1, (N_NODES + BM - 1) / BM);
        if (l == 0)
            gemm_tc_kernel<0, 128><<<ggrid, 256, GEMM_SMEM>>>(
                in_feature, nullptr, nullptr, d_Wh[0], d_Wl[0],
                d_support, N_NODES, K, Kpadl, 0, KPAD0, F);
        else if (l == 1)
            gemm_tc_kernel<1, 128><<<ggrid, 256, GEMM_SMEM>>>(
                nullptr, d_Xh, d_Xl, d_Wh[1], d_Wl[1],
                d_support, N_NODES, K, Kpadl, F_HID, F_HID, F);
        else
            gemm_tc_kernel<1, 64><<<ggrid, 256, GEMM_SMEM>>>(
                nullptr, d_Xh, d_Xl, d_Wh[2], d_Wl[2],
                d_support, N_NODES, K, Kpadl, F_HID, F_HID, F);

        if (l == 0) cudaStreamWaitEvent(0, evJ, 0);   // CSR must be ready before first SpMM

        int nwarps = (N_NODES + RPW - 1) / RPW;
        int nblk = (nwarps * 32 + 255) / 256;
        float* csum = d_colsum + l * F_HID;
        if (F == 128)
            spmm_fused_kernel<128><<<nblk, 256>>>(Bv[l], csum);
        else
            spmm_fused_kernel<64><<<nblk, 256>>>(Bv[l], csum);

        if (l < 2)
            pairnorm128_split_kernel<<<(N_NODES * 32 + 255) / 256, 256>>>(csum);
        else
            pairnorm64_kernel<<<(N_NODES * 32 + 255) / 256, 256>>>(csum);
    }

    int dblocks = (N_EDGES * 32 + 255) / 256;
    decode_kernel<<<dblocks, 256>>>(pos_ei, neg_ei, out);
}

// round 11
// speedup vs baseline: 4.0528x; 1.2342x over previous
#include <cuda_runtime.h>
#include <cuda_bf16.h>
#include <cuda_fp16.h>
#include <math.h>
#include <stdint.h>

#define N_NODES 100000
#define NNZ     1000000
#define F_IN    1433
#define F_HID   128
#define F_OUTD  64
#define N_EDGES 40000
#define EPSV    1e-6f
#define KPAD0   1440
#define SCAN_BLK 1024
#define NBLK_SCAN ((N_NODES + SCAN_BLK - 1) / SCAN_BLK)   // 98

// -------- static device scratch --------
__device__ float g_support[(size_t)N_NODES * F_HID];
__device__ float g_x[(size_t)N_NODES * F_HID];
__device__ float g_colsum3[3][F_HID];
__device__ __half g_Xh[(size_t)N_NODES * F_HID];          // single fp16 plane of x
__device__ __half g_W0h[(size_t)128 * KPAD0];
__device__ __half g_W0l[(size_t)128 * KPAD0];
__device__ __half g_W1h[(size_t)128 * F_HID];
__device__ __half g_W1l[(size_t)128 * F_HID];
__device__ __half g_W2h[(size_t)128 * F_HID];
__device__ __half g_W2l[(size_t)128 * F_HID];
// CSR
__device__ int  g_rowcnt[N_NODES];
__device__ int  g_rowoff[N_NODES + 1];
__device__ int  g_blksum[128];
__device__ int2 g_epack[NNZ];

__device__ __forceinline__ unsigned pack2h(float f0, float f1) {
    unsigned r;
    asm("cvt.rn.f16x2.f32 %0, %1, %2;" : "=r"(r) : "f"(f1), "f"(f0));
    return r;   // low half = f0
}

// ================= prep: zero colsums, split all W (fp16 hi/lo) =================
#define U0 (128 * (KPAD0 / 8))        // 23040
#define U12 (128 * (F_HID / 8))       // 2048
#define PREP_BASE 512
#define PREP_TOTAL (PREP_BASE + U0 + 2 * U12)

__device__ __forceinline__ void split8h(const float* __restrict__ W, int K, int n, int k0,
                                        __half* dsth, __half* dstl, int ldk) {
    float v[8];
#pragma unroll
    for (int e = 0; e < 8; e++) {
        int k = k0 + e;
        v[e] = (k < K) ? __ldg(&W[(size_t)k * 128 + n]) : 0.f;
    }
    __half hh[8], ll[8];
#pragma unroll
    for (int e = 0; e < 8; e++) {
        hh[e] = __float2half_rn(v[e]);
        ll[e] = __float2half_rn(v[e] - __half2float(hh[e]));
    }
    *(uint4*)&dsth[(size_t)n * ldk + k0] = *(uint4*)hh;
    *(uint4*)&dstl[(size_t)n * ldk + k0] = *(uint4*)ll;
}

__global__ void prep_kernel(const float* __restrict__ W0, const float* __restrict__ W1,
                            const float* __restrict__ W2) {
    int t = blockIdx.x * blockDim.x + threadIdx.x;
    if (t < 384) { ((float*)g_colsum3)[t] = 0.f; return; }
    if (t < PREP_BASE) return;
    int u = t - PREP_BASE;
    if (u < U0) {
        int n = u / (KPAD0 / 8);
        int k0 = (u - n * (KPAD0 / 8)) << 3;
        split8h(W0, F_IN, n, k0, g_W0h, g_W0l, KPAD0);
    } else if (u < U0 + U12) {
        int v = u - U0;
        int n = v >> 4;
        int k0 = (v & 15) << 3;
        split8h(W1, F_HID, n, k0, g_W1h, g_W1l, F_HID);
    } else if (u < U0 + 2 * U12) {
        int v = u - U0 - U12;
        int n = v >> 4;
        int k0 = (v & 15) << 3;
        float v8[8];
#pragma unroll
        for (int e = 0; e < 8; e++)
            v8[e] = (n < F_OUTD) ? __ldg(&W2[(size_t)(k0 + e) * F_OUTD + n]) : 0.f;
        __half hh[8], ll[8];
#pragma unroll
        for (int e = 0; e < 8; e++) {
            hh[e] = __float2half_rn(v8[e]);
            ll[e] = __float2half_rn(v8[e] - __half2float(hh[e]));
        }
        *(uint4*)&g_W2h[(size_t)n * F_HID + k0] = *(uint4*)hh;
        *(uint4*)&g_W2l[(size_t)n * F_HID + k0] = *(uint4*)ll;
    }
}

// ================= CSR build =================
__global__ void csr_zero_kernel() {
    int i = blockIdx.x * blockDim.x + threadIdx.x;
    if (i < N_NODES) g_rowcnt[i] = 0;
}
__global__ void csr_hist_kernel(const int* __restrict__ row) {
    int e = blockIdx.x * blockDim.x + threadIdx.x;
    if (e < NNZ) atomicAdd(&g_rowcnt[row[e]], 1);
}
__global__ __launch_bounds__(SCAN_BLK) void csr_scanA_kernel() {
    __shared__ int sm[SCAN_BLK];
    int t = threadIdx.x;
    int i = blockIdx.x * SCAN_BLK + t;
    int v = (i < N_NODES) ? g_rowcnt[i] : 0;
    sm[t] = v;
    __syncthreads();
#pragma unroll
    for (int s = 1; s < SCAN_BLK; s <<= 1) {
        int a = (t >= s) ? sm[t - s] : 0;
        __syncthreads();
        sm[t] += a;
        __syncthreads();
    }
    if (i < N_NODES) g_rowoff[i] = sm[t] - v;
    if (t == SCAN_BLK - 1) g_blksum[blockIdx.x] = sm[t];
}
__global__ void csr_scanB_kernel() {
    __shared__ int sm[128];
    int t = threadIdx.x;
    int v = (t < NBLK_SCAN) ? g_blksum[t] : 0;
    sm[t] = v;
    __syncthreads();
#pragma unroll
    for (int s = 1; s < 128; s <<= 1) {
        int a = (t >= s) ? sm[t - s] : 0;
        __syncthreads();
        sm[t] += a;
        __syncthreads();
    }
    g_blksum[t] = sm[t] - v;
}
__global__ void csr_scanC_kernel() {
    int i = blockIdx.x * blockDim.x + threadIdx.x;
    if (i < N_NODES) {
        g_rowoff[i] += g_blksum[i >> 10];
        g_rowcnt[i] = 0;
    }
    if (i == 0) g_rowoff[N_NODES] = NNZ;
}
__global__ void csr_scatter_kernel(const int* __restrict__ row, const int* __restrict__ col,
                                   const float* __restrict__ val) {
    int e = blockIdx.x * blockDim.x + threadIdx.x;
    if (e >= NNZ) return;
    int r = row[e];
    int p = g_rowoff[r] + atomicAdd(&g_rowcnt[r], 1);
    g_epack[p] = make_int2(col[e], __float_as_int(val[e]));
}

// ============ mma.sync fp16 GEMM, A single-plane, W 2-plane (2-term) ============
#define BM 128
#define BK 32
#define BKP 40
#define PLANE_BYTES (128 * BKP * 2)          // 10240
#define OFF_A  0
#define OFF_BH (PLANE_BYTES)
#define OFF_BL (2 * PLANE_BYTES)
#define STAGE_BYTES (3 * PLANE_BYTES)        // 30720
#define GEMM_SMEM (2 * STAGE_BYTES)          // 61440

__device__ __forceinline__ void mma16816h(float c[4], const unsigned a[4], const unsigned* b) {
    asm volatile(
        "mma.sync.aligned.m16n8k16.row.col.f32.f16.f16.f32 "
        "{%0,%1,%2,%3}, {%4,%5,%6,%7}, {%8,%9}, {%0,%1,%2,%3};"
        : "+f"(c[0]), "+f"(c[1]), "+f"(c[2]), "+f"(c[3])
        : "r"(a[0]), "r"(a[1]), "r"(a[2]), "r"(a[3]), "r"(b[0]), "r"(b[1]));
}
__device__ __forceinline__ void ldmx4(unsigned r[4], uint32_t addr) {
    asm volatile("ldmatrix.sync.aligned.m8n8.x4.shared.b16 {%0,%1,%2,%3}, [%4];"
                 : "=r"(r[0]), "=r"(r[1]), "=r"(r[2]), "=r"(r[3]) : "r"(addr));
}
__device__ __forceinline__ void cp_async16(uint32_t dst, const void* src, bool ok) {
    int bytes = ok ? 16 : 0;
    asm volatile("cp.async.cg.shared.global [%0], [%1], 16, %2;"
                 :: "r"(dst), "l"(src), "r"(bytes));
}

// AMODE 0: A fp32 (layer0, converted in-kernel). AMODE 1: A fp16 plane. BNT: 128 or 64.
template <int AMODE, int BNT>
__global__ __launch_bounds__(256, 2) void gemm_tc_kernel(
    const float* __restrict__ A,
    const __half* __restrict__ Aph,
    const __half* __restrict__ Wh, const __half* __restrict__ Wl,
    float* __restrict__ C, int M, int K, int Kpad, int lda, int ldw, int N)
{
    constexpr int NN = BNT / 16;
    extern __shared__ __align__(16) char dynsmem[];
    const uint32_t sbase = (uint32_t)__cvta_generic_to_shared(dynsmem);

    const int tid  = threadIdx.x;
    const int wid  = tid >> 5;
    const int lane = tid & 31;
    const int bm   = blockIdx.y * BM;
    const int g    = lane >> 2;
    const int qt   = lane & 3;
    const int warp_m = (wid >> 1) * 32;
    const int warp_n = (wid & 1) * (BNT / 2);

    const int rA0 = warp_m + (lane & 7) + (lane & 8);
    const int cA  = (lane & 16) >> 1;
    const int rB0 = warp_n + (lane & 7) + ((lane & 16) >> 1);
    const int cB  = (lane & 8);

    float acc[2][NN][4];
#pragma unroll
    for (int mi = 0; mi < 2; mi++)
#pragma unroll
        for (int ni = 0; ni < NN; ni++)
#pragma unroll
            for (int q = 0; q < 4; q++) acc[mi][ni][q] = 0.f;

    float pv[2][8];

    auto issue_B = [&](int stage, int k0) {
        uint32_t sb = sbase + stage * STAGE_BYTES;
#pragma unroll
        for (int p = 0; p < BNT / 64; p++) {
            int c = tid + p * 256;
            int row = c >> 2;
            int off = (c & 3) << 3;
            uint32_t doff = row * (BKP * 2) + off * 2;
            cp_async16(sb + OFF_BH + doff, &Wh[(size_t)row * ldw + k0 + off], true);
            cp_async16(sb + OFF_BL + doff, &Wl[(size_t)row * ldw + k0 + off], true);
        }
    };
    auto issue_A_plane = [&](int stage, int k0) {
        uint32_t sb = sbase + stage * STAGE_BYTES;
#pragma unroll
        for (int p = 0; p < 2; p++) {
            int c = tid + p * 256;
            int row = c >> 2;
            int off = (c & 3) << 3;
            int m = bm + row;
            bool ok = m < M;
            int ms = ok ? m : 0;
            uint32_t doff = row * (BKP * 2) + off * 2;
            cp_async16(sb + OFF_A + doff, Aph + (size_t)ms * lda + k0 + off, ok);
        }
    };
    auto prefetch_A = [&](int k0) {
        bool full = (k0 + BK <= K);
#pragma unroll
        for (int u2 = 0; u2 < 2; u2++) {
            int u = tid + u2 * 256;
            int r = u >> 2;
            int o = (u & 3) << 3;
            int m = bm + r;
            bool mok = m < M;
            const float* Ar = A + (size_t)m * K + k0 + o;
            if (full) {
#pragma unroll
                for (int e = 0; e < 8; e++) pv[u2][e] = mok ? __ldg(Ar + e) : 0.f;
            } else {
#pragma unroll
                for (int e = 0; e < 8; e++) {
                    int k = k0 + o + e;
                    pv[u2][e] = (mok && k < K) ? __ldg(Ar + e) : 0.f;
                }
            }
        }
    };
    auto cvt_sts_A = [&](int stage) {
#pragma unroll
        for (int u2 = 0; u2 < 2; u2++) {
            int u = tid + u2 * 256;
            int r = u >> 2;
            int o = (u & 3) << 3;
            unsigned ph[4];
#pragma unroll
            for (int p = 0; p < 4; p++)
                ph[p] = pack2h(pv[u2][2 * p], pv[u2][2 * p + 1]);
            *(uint4*)(dynsmem + stage * STAGE_BYTES + OFF_A + r * (BKP * 2) + o * 2) =
                make_uint4(ph[0], ph[1], ph[2], ph[3]);
        }
    };

    const int nt = Kpad / BK;
    if (AMODE == 0) {
        prefetch_A(0);
        cvt_sts_A(0);
    } else {
        issue_A_plane(0, 0);
    }
    issue_B(0, 0);
    asm volatile("cp.async.commit_group;" ::: "memory");

    for (int kt = 0; kt < nt; kt++) {
        int cur = kt & 1;
        int nxt = cur ^ 1;
        asm volatile("cp.async.wait_group 0;" ::: "memory");
        __syncthreads();

        bool hn = (kt + 1) < nt;
        int k1 = (kt + 1) * BK;
        if (hn) {
            if (AMODE == 0) prefetch_A(k1);
            else            issue_A_plane(nxt, k1);
            issue_B(nxt, k1);
        }
        asm volatile("cp.async.commit_group;" ::: "memory");

        uint32_t sA = sbase + cur * STAGE_BYTES;
#pragma unroll
        for (int kh = 0; kh < BK; kh += 16) {
            unsigned a[2][4];
#pragma unroll
            for (int mi = 0; mi < 2; mi++) {
                uint32_t ra = sA + OFF_A + (rA0 + mi * 16) * (BKP * 2) + (cA + kh) * 2;
                ldmx4(a[mi], ra);
            }
#pragma unroll
            for (int nip = 0; nip < NN / 2; nip++) {
                unsigned bh4[4], bl4[4];
                uint32_t rb = sA + OFF_BH + (rB0 + nip * 16) * (BKP * 2) + (cB + kh) * 2;
                ldmx4(bh4, rb);
                ldmx4(bl4, rb + (OFF_BL - OFF_BH));
#pragma unroll
                for (int mi = 0; mi < 2; mi++) {
                    mma16816h(acc[mi][2 * nip],     a[mi], &bh4[0]);
                    mma16816h(acc[mi][2 * nip],     a[mi], &bl4[0]);
                    mma16816h(acc[mi][2 * nip + 1], a[mi], &bh4[2]);
                    mma16816h(acc[mi][2 * nip + 1], a[mi], &bl4[2]);
                }
            }
        }

        if (AMODE == 0 && hn) cvt_sts_A(nxt);
    }

#pragma unroll
    for (int mi = 0; mi < 2; mi++) {
#pragma unroll
        for (int ni = 0; ni < NN; ni++) {
            int row0 = bm + warp_m + mi * 16 + g;
            int col  = warp_n + ni * 8 + 2 * qt;
            if (col < N) {
                if (row0 < M)
                    *(float2*)&C[(size_t)row0 * N + col] =
                        make_float2(acc[mi][ni][0], acc[mi][ni][1]);
                if (row0 + 8 < M)
                    *(float2*)&C[(size_t)(row0 + 8) * N + col] =
                        make_float2(acc[mi][ni][2], acc[mi][ni][3]);
            }
        }
    }
}

// ======== fused CSR-gather SpMM + bias + ReLU + colsum ========
#define RPW 4
template <int FV>
__global__ __launch_bounds__(256) void spmm_fused_kernel(const float* __restrict__ bias,
                                                         float* __restrict__ colsum) {
    constexpr int VEC = FV / 32;
    __shared__ float cs[FV];
    int tid = threadIdx.x;
    if (tid < FV) cs[tid] = 0.f;
    __syncthreads();
    int lane = tid & 31;
    int warp = (((int)blockIdx.x * blockDim.x) + tid) >> 5;
    int r0 = warp * RPW;

    float bv[VEC], bsum[VEC];
#pragma unroll
    for (int v = 0; v < VEC; v++) {
        bv[v] = bias[lane * VEC + v];
        bsum[v] = 0.f;
    }

    if (r0 < N_NODES) {
        for (int rr = 0; rr < RPW; rr++) {
            int r = r0 + rr;
            if (r >= N_NODES) break;
            int beg = __ldg(&g_rowoff[r]);
            int end = __ldg(&g_rowoff[r + 1]);
            float acc[VEC];
#pragma unroll
            for (int v = 0; v < VEC; v++) acc[v] = 0.f;
            int i = beg;
            for (; i + 4 <= end; i += 4) {
                int2 p0 = __ldg(&g_epack[i]);
                int2 p1 = __ldg(&g_epack[i + 1]);
                int2 p2 = __ldg(&g_epack[i + 2]);
                int2 p3 = __ldg(&g_epack[i + 3]);
                const float* s0 = &g_support[(size_t)p0.x * FV + lane * VEC];
                const float* s1 = &g_support[(size_t)p1.x * FV + lane * VEC];
                const float* s2 = &g_support[(size_t)p2.x * FV + lane * VEC];
                const float* s3 = &g_support[(size_t)p3.x * FV + lane * VEC];
                float w0 = __int_as_float(p0.y), w1 = __int_as_float(p1.y);
                float w2 = __int_as_float(p2.y), w3 = __int_as_float(p3.y);
                if (VEC == 4) {
                    float4 a4 = *(const float4*)s0;
                    float4 b4 = *(const float4*)s1;
                    float4 c4 = *(const float4*)s2;
                    float4 d4 = *(const float4*)s3;
                    acc[0] = fmaf(w0, a4.x, fmaf(w1, b4.x, fmaf(w2, c4.x, fmaf(w3, d4.x, acc[0]))));
                    acc[1] = fmaf(w0, a4.y, fmaf(w1, b4.y, fmaf(w2, c4.y, fmaf(w3, d4.y, acc[1]))));
                    acc[2] = fmaf(w0, a4.z, fmaf(w1, b4.z, fmaf(w2, c4.z, fmaf(w3, d4.z, acc[2]))));
                    acc[3] = fmaf(w0, a4.w, fmaf(w1, b4.w, fmaf(w2, c4.w, fmaf(w3, d4.w, acc[3]))));
                } else {
                    float2 a2 = *(const float2*)s0;
                    float2 b2 = *(const float2*)s1;
                    float2 c2 = *(const float2*)s2;
                    float2 d2 = *(const float2*)s3;
                    acc[0] = fmaf(w0, a2.x, fmaf(w1, b2.x, fmaf(w2, c2.x, fmaf(w3, d2.x, acc[0]))));
                    acc[1] = fmaf(w0, a2.y, fmaf(w1, b2.y, fmaf(w2, c2.y, fmaf(w3, d2.y, acc[1]))));
                }
            }
            for (; i < end; i++) {
                int2 p = __ldg(&g_epack[i]);
                float w = __int_as_float(p.y);
                const float* s = &g_support[(size_t)p.x * FV + lane * VEC];
                if (VEC == 4) {
                    float4 sv = *(const float4*)s;
                    acc[0] = fmaf(w, sv.x, acc[0]);
                    acc[1] = fmaf(w, sv.y, acc[1]);
                    acc[2] = fmaf(w, sv.z, acc[2]);
                    acc[3] = fmaf(w, sv.w, acc[3]);
                } else {
                    float2 sv = *(const float2*)s;
                    acc[0] = fmaf(w, sv.x, acc[0]);
                    acc[1] = fmaf(w, sv.y, acc[1]);
                }
            }
#pragma unroll
            for (int v = 0; v < VEC; v++) {
                acc[v] = fmaxf(acc[v] + bv[v], 0.f);
                bsum[v] += acc[v];
            }
            if (VEC == 4)
                *(float4*)&g_x[(size_t)r * FV + lane * 4] =
                    make_float4(acc[0], acc[1], acc[2], acc[3]);
            else
                *(float2*)&g_x[(size_t)r * FV + lane * 2] =
                    make_float2(acc[0], acc[1]);
        }
#pragma unroll
        for (int v = 0; v < VEC; v++)
            atomicAdd(&cs[lane * VEC + v], bsum[v]);
    }
    __syncthreads();
    if (tid < FV) atomicAdd(&colsum[tid], cs[tid]);
}

// -------- PairNorm F=128, fused single-plane fp16 output --------
__global__ void pairnorm128_split_kernel(const float* __restrict__ colsum) {
    int gw = ((int)blockIdx.x * blockDim.x + threadIdx.x) >> 5;
    int lane = threadIdx.x & 31;
    if (gw >= N_NODES) return;
    const float invN = 1.0f / N_NODES;
    float4 mean = *(const float4*)&colsum[lane * 4];
    float4 v = *(const float4*)&g_x[(size_t)gw * F_HID + lane * 4];
    v.x -= mean.x * invN; v.y -= mean.y * invN;
    v.z -= mean.z * invN; v.w -= mean.w * invN;
    float ss = v.x * v.x + v.y * v.y + v.z * v.z + v.w * v.w;
#pragma unroll
    for (int o = 16; o > 0; o >>= 1) ss += __shfl_xor_sync(0xffffffffu, ss, o);
    float inv = rsqrtf(EPSV + ss);
    unsigned h01 = pack2h(v.x * inv, v.y * inv);
    unsigned h23 = pack2h(v.z * inv, v.w * inv);
    *(uint2*)&g_Xh[(size_t)gw * F_HID + lane * 4] = make_uint2(h01, h23);
}

// -------- PairNorm F=64 (final, fp32 for decode) --------
__global__ void pairnorm64_kernel(const float* __restrict__ colsum) {
    int gw = ((int)blockIdx.x * blockDim.x + threadIdx.x) >> 5;
    int lane = threadIdx.x & 31;
    if (gw >= N_NODES) return;
    const float invN = 1.0f / N_NODES;
    float2 mean = *(const float2*)&colsum[lane * 2];
    float2 v = *(const float2*)&g_x[(size_t)gw * F_OUTD + lane * 2];
    v.x -= mean.x * invN;
    v.y -= mean.y * invN;
    float ss = v.x * v.x + v.y * v.y;
#pragma unroll
    for (int o = 16; o > 0; o >>= 1) ss += __shfl_xor_sync(0xffffffffu, ss, o);
    float inv = rsqrtf(EPSV + ss);
    *(float2*)&g_x[(size_t)gw * F_OUTD + lane * 2] = make_float2(v.x * inv, v.y * inv);
}

// -------- decode --------
__global__ void decode_kernel(const int* __restrict__ pos, const int* __restrict__ neg,
                              float* __restrict__ out) {
    int gwarp = ((int)blockIdx.x * blockDim.x + threadIdx.x) >> 5;
    int lane = threadIdx.x & 31;
    if (gwarp >= N_EDGES) return;
    const int* ei = (gwarp < 20000) ? (pos + (size_t)gwarp * 2)
                                    : (neg + (size_t)(gwarp - 20000) * 2);
    int a = ei[0];
    int b = ei[1];
    const float* xa = &g_x[(size_t)a * F_OUTD];
    const float* xb = &g_x[(size_t)b * F_OUTD];
    float s = xa[lane] * xb[lane] + xa[lane + 32] * xb[lane + 32];
#pragma unroll
    for (int o = 16; o > 0; o >>= 1) s += __shfl_xor_sync(0xffffffffu, s, o);
    if (lane == 0) out[gwarp] = 1.0f / (1.0f + expf(-s));
}

// ---------------------------------------------------------------
extern "C" void kernel_launch(void* const* d_in, const int* in_sizes, int n_in,
                              void* d_out, int out_size) {
    const float* in_feature = (const float*)d_in[0];
    const int*   adj_row    = (const int*)d_in[1];
    const int*   adj_col    = (const int*)d_in[2];
    const float* adj_val    = (const float*)d_in[3];
    const int*   pos_ei     = (const int*)d_in[4];
    const int*   neg_ei     = (const int*)d_in[5];
    const float* W0 = (const float*)d_in[6];
    const float* W1 = (const float*)d_in[8];
    const float* W2 = (const float*)d_in[10];
    const float* Bv[3] = { (const float*)d_in[7], (const float*)d_in[9], (const float*)d_in[11] };
    float* out = (float*)d_out;

    float* d_support = nullptr;
    float* d_colsum = nullptr;
    __half* d_Xh = nullptr;
    __half *d_Wh[3], *d_Wl[3];
    cudaGetSymbolAddress((void**)&d_support, g_support);
    cudaGetSymbolAddress((void**)&d_colsum, g_colsum3);
    cudaGetSymbolAddress((void**)&d_Xh, g_Xh);
    cudaGetSymbolAddress((void**)&d_Wh[0], g_W0h);
    cudaGetSymbolAddress((void**)&d_Wl[0], g_W0l);
    cudaGetSymbolAddress((void**)&d_Wh[1], g_W1h);
    cudaGetSymbolAddress((void**)&d_Wl[1], g_W1l);
    cudaGetSymbolAddress((void**)&d_Wh[2], g_W2h);
    cudaGetSymbolAddress((void**)&d_Wl[2], g_W2l);

    cudaFuncSetAttribute((const void*)gemm_tc_kernel<0, 128>,
                         cudaFuncAttributeMaxDynamicSharedMemorySize, GEMM_SMEM);
    cudaFuncSetAttribute((const void*)gemm_tc_kernel<1, 128>,
                         cudaFuncAttributeMaxDynamicSharedMemorySize, GEMM_SMEM);
    cudaFuncSetAttribute((const void*)gemm_tc_kernel<1, 64>,
                         cudaFuncAttributeMaxDynamicSharedMemorySize, GEMM_SMEM);

    // one-time side stream + events
    static cudaStream_t s2 = nullptr;
    static cudaEvent_t evF = nullptr, evJ = nullptr;
    if (s2 == nullptr) {
        cudaStreamCreateWithFlags(&s2, cudaStreamNonBlocking);
        cudaEventCreateWithFlags(&evF, cudaEventDisableTiming);
        cudaEventCreateWithFlags(&evJ, cudaEventDisableTiming);
    }

    // ---- fork: CSR build on side stream, overlapping prep + GEMM0 ----
    cudaEventRecord(evF, 0);
    cudaStreamWaitEvent(s2, evF, 0);
    csr_zero_kernel<<<(N_NODES + 255) / 256, 256, 0, s2>>>();
    csr_hist_kernel<<<(NNZ + 255) / 256, 256, 0, s2>>>(adj_row);
    csr_scanA_kernel<<<NBLK_SCAN, SCAN_BLK, 0, s2>>>();
    csr_scanB_kernel<<<1, 128, 0, s2>>>();
    csr_scanC_kernel<<<(N_NODES + 255) / 256, 256, 0, s2>>>();
    csr_scatter_kernel<<<(NNZ + 255) / 256, 256, 0, s2>>>(adj_row, adj_col, adj_val);
    cudaEventRecord(evJ, s2);

    // ---- main stream ----
    prep_kernel<<<(PREP_TOTAL + 255) / 256, 256>>>(W0, W1, W2);

    const int Kdims[3] = { F_IN, F_HID, F_HID };
    const int Ndims[3] = { F_HID, F_HID, F_OUTD };
    const int Kpads[3] = { KPAD0, F_HID, F_HID };

    for (int l = 0; l < 3; l++) {
        int K = Kdims[l], F = Ndims[l], Kpadl = Kpads[l];

        dim3 ggrid(1, (N_NODES + BM - 1) / BM);
        if (l == 0)
            gemm_tc_kernel<0, 128><<<ggrid, 256, GEMM_SMEM>>>(
                in_feature, nullptr, d_Wh[0], d_Wl[0],
                d_support, N_NODES, K, Kpadl, 0, KPAD0, F);
        else if (l == 1)
            gemm_tc_kernel<1, 128><<<ggrid, 256, GEMM_SMEM>>>(
                nullptr, d_Xh, d_Wh[1], d_Wl[1],
                d_support, N_NODES, K, Kpadl, F_HID, F_HID, F);
        else
            gemm_tc_kernel<1, 64><<<ggrid, 256, GEMM_SMEM>>>(
                nullptr, d_Xh, d_Wh[2], d_Wl[2],
                d_support, N_NODES, K, Kpadl, F_HID, F_HID, F);

        if (l == 0) cudaStreamWaitEvent(0, evJ, 0);

        int nwarps = (N_NODES + RPW - 1) / RPW;
        int nblk = (nwarps * 32 + 255) / 256;
        float* csum = d_colsum + l * F_HID;
        if (F == 128)
            spmm_fused_kernel<128><<<nblk, 256>>>(Bv[l], csum);
        else
            spmm_fused_kernel<64><<<nblk, 256>>>(Bv[l], csum);

        if (l < 2)
            pairnorm128_split_kernel<<<(N_NODES * 32 + 255) / 256, 256>>>(csum);
        else
            pairnorm64_kernel<<<(N_NODES * 32 + 255) / 256, 256>>>(csum);
    }

    int dblocks = (N_EDGES * 32 + 255) / 256;
    decode_kernel<<<dblocks, 256>>>(pos_ei, neg_ei, out);
}

// round 13
// speedup vs baseline: 4.9089x; 1.2112x over previous
#include <cuda_runtime.h>
#include <cuda_bf16.h>
#include <cuda_fp16.h>
#include <math.h>
#include <stdint.h>

#define N_NODES 100000
#define NNZ     1000000
#define F_IN    1433
#define F_HID   128
#define F_OUTD  64
#define N_EDGES 40000
#define EPSV    1e-6f
#define KPAD0   1440
#define SCAN_BLK 1024
#define NBLK_SCAN ((N_NODES + SCAN_BLK - 1) / SCAN_BLK)   // 98

// -------- static device scratch --------
__device__ __half g_supporth[(size_t)N_NODES * F_HID];    // fp16 GEMM output
__device__ float g_x[(size_t)N_NODES * F_HID];
__device__ float g_colsum3[3][F_HID];
__device__ __half g_Xh[(size_t)N_NODES * F_HID];          // fp16 plane of x
__device__ __half g_W0h[(size_t)128 * KPAD0];
__device__ __half g_W1h[(size_t)128 * F_HID];
__device__ __half g_W2h[(size_t)128 * F_HID];
// CSR
__device__ int  g_rowcnt[N_NODES];
__device__ int  g_rowoff[N_NODES + 1];
__device__ int  g_blksum[128];
__device__ int2 g_epack[NNZ];

__device__ __forceinline__ unsigned pack2h(float f0, float f1) {
    unsigned r;
    asm("cvt.rn.f16x2.f32 %0, %1, %2;" : "=r"(r) : "f"(f1), "f"(f0));
    return r;   // low half = f0
}

// ================= prep: zero colsums, convert all W to fp16 transposed =================
#define U0 (128 * (KPAD0 / 8))        // 23040
#define U12 (128 * (F_HID / 8))       // 2048
#define PREP_BASE 512
#define PREP_TOTAL (PREP_BASE + U0 + 2 * U12)

__global__ void prep_kernel(const float* __restrict__ W0, const float* __restrict__ W1,
                            const float* __restrict__ W2) {
    int t = blockIdx.x * blockDim.x + threadIdx.x;
    if (t < 384) { ((float*)g_colsum3)[t] = 0.f; return; }
    if (t < PREP_BASE) return;
    int u = t - PREP_BASE;
    if (u < U0) {
        int n = u / (KPAD0 / 8);
        int k0 = (u - n * (KPAD0 / 8)) << 3;
        __half hh[8];
#pragma unroll
        for (int e = 0; e < 8; e++) {
            int k = k0 + e;
            hh[e] = __float2half_rn((k < F_IN) ? __ldg(&W0[(size_t)k * 128 + n]) : 0.f);
        }
        *(uint4*)&g_W0h[(size_t)n * KPAD0 + k0] = *(uint4*)hh;
    } else if (u < U0 + U12) {
        int v = u - U0;
        int n = v >> 4;
        int k0 = (v & 15) << 3;
        __half hh[8];
#pragma unroll
        for (int e = 0; e < 8; e++)
            hh[e] = __float2half_rn(__ldg(&W1[(size_t)(k0 + e) * 128 + n]));
        *(uint4*)&g_W1h[(size_t)n * F_HID + k0] = *(uint4*)hh;
    } else if (u < U0 + 2 * U12) {
        int v = u - U0 - U12;
        int n = v >> 4;
        int k0 = (v & 15) << 3;
        __half hh[8];
#pragma unroll
        for (int e = 0; e < 8; e++)
            hh[e] = __float2half_rn((n < F_OUTD) ? __ldg(&W2[(size_t)(k0 + e) * F_OUTD + n]) : 0.f);
        *(uint4*)&g_W2h[(size_t)n * F_HID + k0] = *(uint4*)hh;
    }
}

// ================= CSR build =================
__global__ void csr_zero_kernel() {
    int i = blockIdx.x * blockDim.x + threadIdx.x;
    if (i < N_NODES) g_rowcnt[i] = 0;
}
__global__ void csr_hist_kernel(const int* __restrict__ row) {
    int e = blockIdx.x * blockDim.x + threadIdx.x;
    if (e < NNZ) atomicAdd(&g_rowcnt[row[e]], 1);
}
__global__ __launch_bounds__(SCAN_BLK) void csr_scanA_kernel() {
    __shared__ int sm[SCAN_BLK];
    int t = threadIdx.x;
    int i = blockIdx.x * SCAN_BLK + t;
    int v = (i < N_NODES) ? g_rowcnt[i] : 0;
    sm[t] = v;
    __syncthreads();
#pragma unroll
    for (int s = 1; s < SCAN_BLK; s <<= 1) {
        int a = (t >= s) ? sm[t - s] : 0;
        __syncthreads();
        sm[t] += a;
        __syncthreads();
    }
    if (i < N_NODES) g_rowoff[i] = sm[t] - v;
    if (t == SCAN_BLK - 1) g_blksum[blockIdx.x] = sm[t];
}
__global__ void csr_scanB_kernel() {
    __shared__ int sm[128];
    int t = threadIdx.x;
    int v = (t < NBLK_SCAN) ? g_blksum[t] : 0;
    sm[t] = v;
    __syncthreads();
#pragma unroll
    for (int s = 1; s < 128; s <<= 1) {
        int a = (t >= s) ? sm[t - s] : 0;
        __syncthreads();
        sm[t] += a;
        __syncthreads();
    }
    g_blksum[t] = sm[t] - v;
}
__global__ void csr_scanC_kernel() {
    int i = blockIdx.x * blockDim.x + threadIdx.x;
    if (i < N_NODES) {
        g_rowoff[i] += g_blksum[i >> 10];
        g_rowcnt[i] = 0;
    }
    if (i == 0) g_rowoff[N_NODES] = NNZ;
}
__global__ void csr_scatter_kernel(const int* __restrict__ row, const int* __restrict__ col,
                                   const float* __restrict__ val) {
    int e = blockIdx.x * blockDim.x + threadIdx.x;
    if (e >= NNZ) return;
    int r = row[e];
    int p = g_rowoff[r] + atomicAdd(&g_rowcnt[r], 1);
    g_epack[p] = make_int2(col[e], __float_as_int(val[e]));
}

// ============ mma.sync fp16 GEMM, single-term, fp16 output ============
#define BM 128
#define BK 32
#define BKP 40
#define PLANE_BYTES (128 * BKP * 2)          // 10240
#define OFF_A  0
#define OFF_B  (PLANE_BYTES)
#define STAGE_BYTES (2 * PLANE_BYTES)        // 20480
#define GEMM_SMEM (2 * STAGE_BYTES)          // 40960

__device__ __forceinline__ void mma16816h(float c[4], const unsigned a[4], const unsigned* b) {
    asm volatile(
        "mma.sync.aligned.m16n8k16.row.col.f32.f16.f16.f32 "
        "{%0,%1,%2,%3}, {%4,%5,%6,%7}, {%8,%9}, {%0,%1,%2,%3};"
        : "+f"(c[0]), "+f"(c[1]), "+f"(c[2]), "+f"(c[3])
        : "r"(a[0]), "r"(a[1]), "r"(a[2]), "r"(a[3]), "r"(b[0]), "r"(b[1]));
}
__device__ __forceinline__ void ldmx4(unsigned r[4], uint32_t addr) {
    asm volatile("ldmatrix.sync.aligned.m8n8.x4.shared.b16 {%0,%1,%2,%3}, [%4];"
                 : "=r"(r[0]), "=r"(r[1]), "=r"(r[2]), "=r"(r[3]) : "r"(addr));
}
__device__ __forceinline__ void cp_async16(uint32_t dst, const void* src, bool ok) {
    int bytes = ok ? 16 : 0;
    asm volatile("cp.async.cg.shared.global [%0], [%1], 16, %2;"
                 :: "r"(dst), "l"(src), "r"(bytes));
}

// AMODE 0: A fp32 (layer0). AMODE 1: A fp16 plane. BNT: 128 or 64.
template <int AMODE, int BNT>
__global__ __launch_bounds__(256, 2) void gemm_tc_kernel(
    const float* __restrict__ A,
    const __half* __restrict__ Aph,
    const __half* __restrict__ Wh,
    __half* __restrict__ C, int M, int K, int Kpad, int lda, int ldw, int N)
{
    constexpr int NN = BNT / 16;
    extern __shared__ __align__(16) char dynsmem[];
    const uint32_t sbase = (uint32_t)__cvta_generic_to_shared(dynsmem);

    const int tid  = threadIdx.x;
    const int wid  = tid >> 5;
    const int lane = tid & 31;
    const int bm   = blockIdx.y * BM;
    const int g    = lane >> 2;
    const int qt   = lane & 3;
    const int warp_m = (wid >> 1) * 32;
    const int warp_n = (wid & 1) * (BNT / 2);

    const int rA0 = warp_m + (lane & 7) + (lane & 8);
    const int cA  = (lane & 16) >> 1;
    const int rB0 = warp_n + (lane & 7) + ((lane & 16) >> 1);
    const int cB  = (lane & 8);

    float acc[2][NN][4];
#pragma unroll
    for (int mi = 0; mi < 2; mi++)
#pragma unroll
        for (int ni = 0; ni < NN; ni++)
#pragma unroll
            for (int q = 0; q < 4; q++) acc[mi][ni][q] = 0.f;

    float pv[2][8];

    auto issue_B = [&](int stage, int k0) {
        uint32_t sb = sbase + stage * STAGE_BYTES;
#pragma unroll
        for (int p = 0; p < BNT / 64; p++) {
            int c = tid + p * 256;
            int row = c >> 2;
            int off = (c & 3) << 3;
            uint32_t doff = row * (BKP * 2) + off * 2;
            cp_async16(sb + OFF_B + doff, &Wh[(size_t)row * ldw + k0 + off], true);
        }
    };
    auto issue_A_plane = [&](int stage, int k0) {
        uint32_t sb = sbase + stage * STAGE_BYTES;
#pragma unroll
        for (int p = 0; p < 2; p++) {
            int c = tid + p * 256;
            int row = c >> 2;
            int off = (c & 3) << 3;
            int m = bm + row;
            bool ok = m < M;
            int ms = ok ? m : 0;
            uint32_t doff = row * (BKP * 2) + off * 2;
            cp_async16(sb + OFF_A + doff, Aph + (size_t)ms * lda + k0 + off, ok);
        }
    };
    auto prefetch_A = [&](int k0) {
        bool full = (k0 + BK <= K);
#pragma unroll
        for (int u2 = 0; u2 < 2; u2++) {
            int u = tid + u2 * 256;
            int r = u >> 2;
            int o = (u & 3) << 3;
            int m = bm + r;
            bool mok = m < M;
            const float* Ar = A + (size_t)m * K + k0 + o;
            if (full) {
#pragma unroll
                for (int e = 0; e < 8; e++) pv[u2][e] = mok ? __ldg(Ar + e) : 0.f;
            } else {
#pragma unroll
                for (int e = 0; e < 8; e++) {
                    int k = k0 + o + e;
                    pv[u2][e] = (mok && k < K) ? __ldg(Ar + e) : 0.f;
                }
            }
        }
    };
    auto cvt_sts_A = [&](int stage) {
#pragma unroll
        for (int u2 = 0; u2 < 2; u2++) {
            int u = tid + u2 * 256;
            int r = u >> 2;
            int o = (u & 3) << 3;
            unsigned ph[4];
#pragma unroll
            for (int p = 0; p < 4; p++)
                ph[p] = pack2h(pv[u2][2 * p], pv[u2][2 * p + 1]);
            *(uint4*)(dynsmem + stage * STAGE_BYTES + OFF_A + r * (BKP * 2) + o * 2) =
                make_uint4(ph[0], ph[1], ph[2], ph[3]);
        }
    };

    const int nt = Kpad / BK;
    if (AMODE == 0) {
        prefetch_A(0);
        cvt_sts_A(0);
    } else {
        issue_A_plane(0, 0);
    }
    issue_B(0, 0);
    asm volatile("cp.async.commit_group;" ::: "memory");

    for (int kt = 0; kt < nt; kt++) {
        int cur = kt & 1;
        int nxt = cur ^ 1;
        asm volatile("cp.async.wait_group 0;" ::: "memory");
        __syncthreads();

        bool hn = (kt + 1) < nt;
        int k1 = (kt + 1) * BK;
        if (hn) {
            if (AMODE == 0) prefetch_A(k1);
            else            issue_A_plane(nxt, k1);
            issue_B(nxt, k1);
        }
        asm volatile("cp.async.commit_group;" ::: "memory");

        uint32_t sA = sbase + cur * STAGE_BYTES;
#pragma unroll
        for (int kh = 0; kh < BK; kh += 16) {
            unsigned a[2][4];
#pragma unroll
            for (int mi = 0; mi < 2; mi++) {
                uint32_t ra = sA + OFF_A + (rA0 + mi * 16) * (BKP * 2) + (cA + kh) * 2;
                ldmx4(a[mi], ra);
            }
#pragma unroll
            for (int nip = 0; nip < NN / 2; nip++) {
                unsigned b4[4];
                uint32_t rb = sA + OFF_B + (rB0 + nip * 16) * (BKP * 2) + (cB + kh) * 2;
                ldmx4(b4, rb);
#pragma unroll
                for (int mi = 0; mi < 2; mi++) {
                    mma16816h(acc[mi][2 * nip],     a[mi], &b4[0]);
                    mma16816h(acc[mi][2 * nip + 1], a[mi], &b4[2]);
                }
            }
        }

        if (AMODE == 0 && hn) cvt_sts_A(nxt);
    }

    // ---- fp16 epilogue ----
#pragma unroll
    for (int mi = 0; mi < 2; mi++) {
#pragma unroll
        for (int ni = 0; ni < NN; ni++) {
            int row0 = bm + warp_m + mi * 16 + g;
            int col  = warp_n + ni * 8 + 2 * qt;
            if (col < N) {
                if (row0 < M)
                    *(unsigned*)&C[(size_t)row0 * N + col] =
                        pack2h(acc[mi][ni][0], acc[mi][ni][1]);
                if (row0 + 8 < M)
                    *(unsigned*)&C[(size_t)(row0 + 8) * N + col] =
                        pack2h(acc[mi][ni][2], acc[mi][ni][3]);
            }
        }
    }
}

// ======== fused CSR-gather SpMM (fp16 support) + bias + ReLU + colsum ========
#define RPW 4
template <int FV>
__global__ __launch_bounds__(256) void spmm_fused_kernel(const float* __restrict__ bias,
                                                         float* __restrict__ colsum) {
    constexpr int VEC = FV / 32;      // 4 or 2 features per lane
    __shared__ float cs[FV];
    int tid = threadIdx.x;
    if (tid < FV) cs[tid] = 0.f;
    __syncthreads();
    int lane = tid & 31;
    int warp = (((int)blockIdx.x * blockDim.x) + tid) >> 5;
    int r0 = warp * RPW;

    float bv[VEC], bsum[VEC];
#pragma unroll
    for (int v = 0; v < VEC; v++) {
        bv[v] = bias[lane * VEC + v];
        bsum[v] = 0.f;
    }

    if (r0 < N_NODES) {
        for (int rr = 0; rr < RPW; rr++) {
            int r = r0 + rr;
            if (r >= N_NODES) break;
            int beg = __ldg(&g_rowoff[r]);
            int end = __ldg(&g_rowoff[r + 1]);
            float acc[VEC];
#pragma unroll
            for (int v = 0; v < VEC; v++) acc[v] = 0.f;

            auto gather = [&](int2 p) {
                float w = __int_as_float(p.y);
                const __half* s = &g_supporth[(size_t)p.x * FV + lane * VEC];
                if (VEC == 4) {
                    uint2 u = *(const uint2*)s;
                    float2 lo = __half22float2(*(__half2*)&u.x);
                    float2 hi = __half22float2(*(__half2*)&u.y);
                    acc[0] = fmaf(w, lo.x, acc[0]);
                    acc[1] = fmaf(w, lo.y, acc[1]);
                    acc[2] = fmaf(w, hi.x, acc[2]);
                    acc[3] = fmaf(w, hi.y, acc[3]);
                } else {
                    unsigned u = *(const unsigned*)s;
                    float2 lo = __half22float2(*(__half2*)&u);
                    acc[0] = fmaf(w, lo.x, acc[0]);
                    acc[1] = fmaf(w, lo.y, acc[1]);
                }
            };

            int i = beg;
            for (; i + 4 <= end; i += 4) {
                int2 p0 = __ldg(&g_epack[i]);
                int2 p1 = __ldg(&g_epack[i + 1]);
                int2 p2 = __ldg(&g_epack[i + 2]);
                int2 p3 = __ldg(&g_epack[i + 3]);
                gather(p0); gather(p1); gather(p2); gather(p3);
            }
            for (; i < end; i++) gather(__ldg(&g_epack[i]));

#pragma unroll
            for (int v = 0; v < VEC; v++) {
                acc[v] = fmaxf(acc[v] + bv[v], 0.f);
                bsum[v] += acc[v];
            }
            if (VEC == 4)
                *(float4*)&g_x[(size_t)r * FV + lane * 4] =
                    make_float4(acc[0], acc[1], acc[2], acc[3]);
            else
                *(float2*)&g_x[(size_t)r * FV + lane * 2] =
                    make_float2(acc[0], acc[1]);
        }
#pragma unroll
        for (int v = 0; v < VEC; v++)
            atomicAdd(&cs[lane * VEC + v], bsum[v]);
    }
    __syncthreads();
    if (tid < FV) atomicAdd(&colsum[tid], cs[tid]);
}

// -------- PairNorm F=128, fp16 plane output --------
__global__ void pairnorm128_split_kernel(const float* __restrict__ colsum) {
    int gw = ((int)blockIdx.x * blockDim.x + threadIdx.x) >> 5;
    int lane = threadIdx.x & 31;
    if (gw >= N_NODES) return;
    const float invN = 1.0f / N_NODES;
    float4 mean = *(const float4*)&colsum[lane * 4];
    float4 v = *(const float4*)&g_x[(size_t)gw * F_HID + lane * 4];
    v.x -= mean.x * invN; v.y -= mean.y * invN;
    v.z -= mean.z * invN; v.w -= mean.w * invN;
    float ss = v.x * v.x + v.y * v.y + v.z * v.z + v.w * v.w;
#pragma unroll
    for (int o = 16; o > 0; o >>= 1) ss += __shfl_xor_sync(0xffffffffu, ss, o);
    float inv = rsqrtf(EPSV + ss);
    unsigned h01 = pack2h(v.x * inv, v.y * inv);
    unsigned h23 = pack2h(v.z * inv, v.w * inv);
    *(uint2*)&g_Xh[(size_t)gw * F_HID + lane * 4] = make_uint2(h01, h23);
}

// -------- PairNorm F=64 (final, fp32 for decode) --------
__global__ void pairnorm64_kernel(const float* __restrict__ colsum) {
    int gw = ((int)blockIdx.x * blockDim.x + threadIdx.x) >> 5;
    int lane = threadIdx.x & 31;
    if (gw >= N_NODES) return;
    const float invN = 1.0f / N_NODES;
    float2 mean = *(const float2*)&colsum[lane * 2];
    float2 v = *(const float2*)&g_x[(size_t)gw * F_OUTD + lane * 2];
    v.x -= mean.x * invN;
    v.y -= mean.y * invN;
    float ss = v.x * v.x + v.y * v.y;
#pragma unroll
    for (int o = 16; o > 0; o >>= 1) ss += __shfl_xor_sync(0xffffffffu, ss, o);
    float inv = rsqrtf(EPSV + ss);
    *(float2*)&g_x[(size_t)gw * F_OUTD + lane * 2] = make_float2(v.x * inv, v.y * inv);
}

// -------- decode --------
__global__ void decode_kernel(const int* __restrict__ pos, const int* __restrict__ neg,
                              float* __restrict__ out) {
    int gwarp = ((int)blockIdx.x * blockDim.x + threadIdx.x) >> 5;
    int lane = threadIdx.x & 31;
    if (gwarp >= N_EDGES) return;
    const int* ei = (gwarp < 20000) ? (pos + (size_t)gwarp * 2)
                                    : (neg + (size_t)(gwarp - 20000) * 2);
    int a = ei[0];
    int b = ei[1];
    const float* xa = &g_x[(size_t)a * F_OUTD];
    const float* xb = &g_x[(size_t)b * F_OUTD];
    float s = xa[lane] * xb[lane] + xa[lane + 32] * xb[lane + 32];
#pragma unroll
    for (int o = 16; o > 0; o >>= 1) s += __shfl_xor_sync(0xffffffffu, s, o);
    if (lane == 0) out[gwarp] = 1.0f / (1.0f + expf(-s));
}

// ---------------------------------------------------------------
extern "C" void kernel_launch(void* const* d_in, const int* in_sizes, int n_in,
                              void* d_out, int out_size) {
    const float* in_feature = (const float*)d_in[0];
    const int*   adj_row    = (const int*)d_in[1];
    const int*   adj_col    = (const int*)d_in[2];
    const float* adj_val    = (const float*)d_in[3];
    const int*   pos_ei     = (const int*)d_in[4];
    const int*   neg_ei     = (const int*)d_in[5];
    const float* W0 = (const float*)d_in[6];
    const float* W1 = (const float*)d_in[8];
    const float* W2 = (const float*)d_in[10];
    const float* Bv[3] = { (const float*)d_in[7], (const float*)d_in[9], (const float*)d_in[11] };
    float* out = (float*)d_out;

    __half* d_support = nullptr;
    float* d_colsum = nullptr;
    __half* d_Xh = nullptr;
    __half *d_Wh[3];
    cudaGetSymbolAddress((void**)&d_support, g_supporth);
    cudaGetSymbolAddress((void**)&d_colsum, g_colsum3);
    cudaGetSymbolAddress((void**)&d_Xh, g_Xh);
    cudaGetSymbolAddress((void**)&d_Wh[0], g_W0h);
    cudaGetSymbolAddress((void**)&d_Wh[1], g_W1h);
    cudaGetSymbolAddress((void**)&d_Wh[2], g_W2h);

    cudaFuncSetAttribute((const void*)gemm_tc_kernel<0, 128>,
                         cudaFuncAttributeMaxDynamicSharedMemorySize, GEMM_SMEM);
    cudaFuncSetAttribute((const void*)gemm_tc_kernel<1, 128>,
                         cudaFuncAttributeMaxDynamicSharedMemorySize, GEMM_SMEM);
    cudaFuncSetAttribute((const void*)gemm_tc_kernel<1, 64>,
                         cudaFuncAttributeMaxDynamicSharedMemorySize, GEMM_SMEM);

    // one-time side stream + events
    static cudaStream_t s2 = nullptr;
    static cudaEvent_t evF = nullptr, evJ = nullptr;
    if (s2 == nullptr) {
        cudaStreamCreateWithFlags(&s2, cudaStreamNonBlocking);
        cudaEventCreateWithFlags(&evF, cudaEventDisableTiming);
        cudaEventCreateWithFlags(&evJ, cudaEventDisableTiming);
    }

    // ---- fork: CSR build on side stream, overlapping prep + GEMM0 ----
    cudaEventRecord(evF, 0);
    cudaStreamWaitEvent(s2, evF, 0);
    csr_zero_kernel<<<(N_NODES + 255) / 256, 256, 0, s2>>>();
    csr_hist_kernel<<<(NNZ + 255) / 256, 256, 0, s2>>>(adj_row);
    csr_scanA_kernel<<<NBLK_SCAN, SCAN_BLK, 0, s2>>>();
    csr_scanB_kernel<<<1, 128, 0, s2>>>();
    csr_scanC_kernel<<<(N_NODES + 255) / 256, 256, 0, s2>>>();
    csr_scatter_kernel<<<(NNZ + 255) / 256, 256, 0, s2>>>(adj_row, adj_col, adj_val);
    cudaEventRecord(evJ, s2);

    // ---- main stream ----
    prep_kernel<<<(PREP_TOTAL + 255) / 256, 256>>>(W0, W1, W2);

    const int Kdims[3] = { F_IN, F_HID, F_HID };
    const int Ndims[3] = { F_HID, F_HID, F_OUTD };
    const int Kpads[3] = { KPAD0, F_HID, F_HID };

    for (int l = 0; l < 3; l++) {
        int K = Kdims[l], F = Ndims[l], Kpadl = Kpads[l];

        dim3 ggrid(1, (N_NODES + BM - 1) / BM);
        if (l == 0)
            gemm_tc_kernel<0, 128><<<ggrid, 256, GEMM_SMEM>>>(
                in_feature, nullptr, d_Wh[0],
                d_support, N_NODES, K, Kpadl, 0, KPAD0, F);
        else if (l == 1)
            gemm_tc_kernel<1, 128><<<ggrid, 256, GEMM_SMEM>>>(
                nullptr, d_Xh, d_Wh[1],
                d_support, N_NODES, K, Kpadl, F_HID, F_HID, F);
        else
            gemm_tc_kernel<1, 64><<<ggrid, 256, GEMM_SMEM>>>(
                nullptr, d_Xh, d_Wh[2],
                d_support, N_NODES, K, Kpadl, F_HID, F_HID, F);

        if (l == 0) cudaStreamWaitEvent(0, evJ, 0);

        int nwarps = (N_NODES + RPW - 1) / RPW;
        int nblk = (nwarps * 32 + 255) / 256;
        float* csum = d_colsum + l * F_HID;
        if (F == 128)
            spmm_fused_kernel<128><<<nblk, 256>>>(Bv[l], csum);
        else
            spmm_fused_kernel<64><<<nblk, 256>>>(Bv[l], csum);

        if (l < 2)
            pairnorm128_split_kernel<<<(N_NODES * 32 + 255) / 256, 256>>>(csum);
        else
            pairnorm64_kernel<<<(N_NODES * 32 + 255) / 256, 256>>>(csum);
    }

    int dblocks = (N_EDGES * 32 + 255) / 256;
    decode_kernel<<<dblocks, 256>>>(pos_ei, neg_ei, out);
}

// round 14
// speedup vs baseline: 4.9092x; 1.0001x over previous
#include <cuda_runtime.h>
#include <cuda_bf16.h>
#include <cuda_fp16.h>
#include <math.h>
#include <stdint.h>

#define N_NODES 100000
#define NNZ     1000000
#define F_IN    1433
#define F_HID   128
#define F_OUTD  64
#define N_EDGES 40000
#define EPSV    1e-6f
#define KPAD0   1440
#define SCAN_BLK 1024
#define NBLK_SCAN ((N_NODES + SCAN_BLK - 1) / SCAN_BLK)   // 98

// -------- static device scratch --------
__device__ __half g_supporth[(size_t)N_NODES * F_HID];    // fp16 GEMM output
__device__ __half g_xh[(size_t)N_NODES * F_HID];          // fp16 x (pre-pairnorm, layers 0-1)
__device__ float g_x[(size_t)N_NODES * F_HID];            // fp32 x (layer 2 for decode)
__device__ float g_colsum3[3][F_HID];
__device__ __half g_Xh[(size_t)N_NODES * F_HID];          // fp16 x (post-pairnorm, GEMM input)
__device__ __half g_W0h[(size_t)128 * KPAD0];
__device__ __half g_W1h[(size_t)128 * F_HID];
__device__ __half g_W2h[(size_t)128 * F_HID];
// CSR
__device__ int  g_rowcnt[N_NODES];
__device__ int  g_rowoff[N_NODES + 1];
__device__ int  g_blksum[128];
__device__ int2 g_epack[NNZ];

__device__ __forceinline__ unsigned pack2h(float f0, float f1) {
    unsigned r;
    asm("cvt.rn.f16x2.f32 %0, %1, %2;" : "=r"(r) : "f"(f1), "f"(f0));
    return r;   // low half = f0
}

// ================= prep: zero colsums, convert all W to fp16 transposed =================
#define U0 (128 * (KPAD0 / 8))        // 23040
#define U12 (128 * (F_HID / 8))       // 2048
#define PREP_BASE 512
#define PREP_TOTAL (PREP_BASE + U0 + 2 * U12)

__global__ void prep_kernel(const float* __restrict__ W0, const float* __restrict__ W1,
                            const float* __restrict__ W2) {
    int t = blockIdx.x * blockDim.x + threadIdx.x;
    if (t < 384) { ((float*)g_colsum3)[t] = 0.f; return; }
    if (t < PREP_BASE) return;
    int u = t - PREP_BASE;
    if (u < U0) {
        int n = u / (KPAD0 / 8);
        int k0 = (u - n * (KPAD0 / 8)) << 3;
        __half hh[8];
#pragma unroll
        for (int e = 0; e < 8; e++) {
            int k = k0 + e;
            hh[e] = __float2half_rn((k < F_IN) ? __ldg(&W0[(size_t)k * 128 + n]) : 0.f);
        }
        *(uint4*)&g_W0h[(size_t)n * KPAD0 + k0] = *(uint4*)hh;
    } else if (u < U0 + U12) {
        int v = u - U0;
        int n = v >> 4;
        int k0 = (v & 15) << 3;
        __half hh[8];
#pragma unroll
        for (int e = 0; e < 8; e++)
            hh[e] = __float2half_rn(__ldg(&W1[(size_t)(k0 + e) * 128 + n]));
        *(uint4*)&g_W1h[(size_t)n * F_HID + k0] = *(uint4*)hh;
    } else if (u < U0 + 2 * U12) {
        int v = u - U0 - U12;
        int n = v >> 4;
        int k0 = (v & 15) << 3;
        __half hh[8];
#pragma unroll
        for (int e = 0; e < 8; e++)
            hh[e] = __float2half_rn((n < F_OUTD) ? __ldg(&W2[(size_t)(k0 + e) * F_OUTD + n]) : 0.f);
        *(uint4*)&g_W2h[(size_t)n * F_HID + k0] = *(uint4*)hh;
    }
}

// ================= CSR build =================
__global__ void csr_zero_kernel() {
    int i = blockIdx.x * blockDim.x + threadIdx.x;
    if (i < N_NODES) g_rowcnt[i] = 0;
}
__global__ void csr_hist_kernel(const int* __restrict__ row) {
    int e = blockIdx.x * blockDim.x + threadIdx.x;
    if (e < NNZ) atomicAdd(&g_rowcnt[row[e]], 1);
}
__global__ __launch_bounds__(SCAN_BLK) void csr_scanA_kernel() {
    __shared__ int sm[SCAN_BLK];
    int t = threadIdx.x;
    int i = blockIdx.x * SCAN_BLK + t;
    int v = (i < N_NODES) ? g_rowcnt[i] : 0;
    sm[t] = v;
    __syncthreads();
#pragma unroll
    for (int s = 1; s < SCAN_BLK; s <<= 1) {
        int a = (t >= s) ? sm[t - s] : 0;
        __syncthreads();
        sm[t] += a;
        __syncthreads();
    }
    if (i < N_NODES) g_rowoff[i] = sm[t] - v;
    if (t == SCAN_BLK - 1) g_blksum[blockIdx.x] = sm[t];
}
__global__ void csr_scanB_kernel() {
    __shared__ int sm[128];
    int t = threadIdx.x;
    int v = (t < NBLK_SCAN) ? g_blksum[t] : 0;
    sm[t] = v;
    __syncthreads();
#pragma unroll
    for (int s = 1; s < 128; s <<= 1) {
        int a = (t >= s) ? sm[t - s] : 0;
        __syncthreads();
        sm[t] += a;
        __syncthreads();
    }
    g_blksum[t] = sm[t] - v;
}
__global__ void csr_scanC_kernel() {
    int i = blockIdx.x * blockDim.x + threadIdx.x;
    if (i < N_NODES) {
        g_rowoff[i] += g_blksum[i >> 10];
        g_rowcnt[i] = 0;
    }
    if (i == 0) g_rowoff[N_NODES] = NNZ;
}
__global__ void csr_scatter_kernel(const int* __restrict__ row, const int* __restrict__ col,
                                   const float* __restrict__ val) {
    int e = blockIdx.x * blockDim.x + threadIdx.x;
    if (e >= NNZ) return;
    int r = row[e];
    int p = g_rowoff[r] + atomicAdd(&g_rowcnt[r], 1);
    g_epack[p] = make_int2(col[e], __float_as_int(val[e]));
}

// ============ mma.sync fp16 GEMM, single-term, fp16 output ============
#define BM 128
#define BK 32
#define BKP 40
#define PLANE_BYTES (128 * BKP * 2)          // 10240
#define OFF_A  0
#define OFF_B  (PLANE_BYTES)
#define STAGE_BYTES (2 * PLANE_BYTES)        // 20480
#define GEMM_SMEM (2 * STAGE_BYTES)          // 40960

__device__ __forceinline__ void mma16816h(float c[4], const unsigned a[4], const unsigned* b) {
    asm volatile(
        "mma.sync.aligned.m16n8k16.row.col.f32.f16.f16.f32 "
        "{%0,%1,%2,%3}, {%4,%5,%6,%7}, {%8,%9}, {%0,%1,%2,%3};"
        : "+f"(c[0]), "+f"(c[1]), "+f"(c[2]), "+f"(c[3])
        : "r"(a[0]), "r"(a[1]), "r"(a[2]), "r"(a[3]), "r"(b[0]), "r"(b[1]));
}
__device__ __forceinline__ void ldmx4(unsigned r[4], uint32_t addr) {
    asm volatile("ldmatrix.sync.aligned.m8n8.x4.shared.b16 {%0,%1,%2,%3}, [%4];"
                 : "=r"(r[0]), "=r"(r[1]), "=r"(r[2]), "=r"(r[3]) : "r"(addr));
}
__device__ __forceinline__ void cp_async16(uint32_t dst, const void* src, bool ok) {
    int bytes = ok ? 16 : 0;
    asm volatile("cp.async.cg.shared.global [%0], [%1], 16, %2;"
                 :: "r"(dst), "l"(src), "r"(bytes));
}

// AMODE 0: A fp32 (layer0). AMODE 1: A fp16 plane. BNT: 128 or 64.
template <int AMODE, int BNT>
__global__ __launch_bounds__(256, 2) void gemm_tc_kernel(
    const float* __restrict__ A,
    const __half* __restrict__ Aph,
    const __half* __restrict__ Wh,
    __half* __restrict__ C, int M, int K, int Kpad, int lda, int ldw, int N)
{
    constexpr int NN = BNT / 16;
    extern __shared__ __align__(16) char dynsmem[];
    const uint32_t sbase = (uint32_t)__cvta_generic_to_shared(dynsmem);

    const int tid  = threadIdx.x;
    const int wid  = tid >> 5;
    const int lane = tid & 31;
    const int bm   = blockIdx.y * BM;
    const int g    = lane >> 2;
    const int qt   = lane & 3;
    const int warp_m = (wid >> 1) * 32;
    const int warp_n = (wid & 1) * (BNT / 2);

    const int rA0 = warp_m + (lane & 7) + (lane & 8);
    const int cA  = (lane & 16) >> 1;
    const int rB0 = warp_n + (lane & 7) + ((lane & 16) >> 1);
    const int cB  = (lane & 8);

    float acc[2][NN][4];
#pragma unroll
    for (int mi = 0; mi < 2; mi++)
#pragma unroll
        for (int ni = 0; ni < NN; ni++)
#pragma unroll
            for (int q = 0; q < 4; q++) acc[mi][ni][q] = 0.f;

    float pv[2][8];

    auto issue_B = [&](int stage, int k0) {
        uint32_t sb = sbase + stage * STAGE_BYTES;
#pragma unroll
        for (int p = 0; p < BNT / 64; p++) {
            int c = tid + p * 256;
            int row = c >> 2;
            int off = (c & 3) << 3;
            uint32_t doff = row * (BKP * 2) + off * 2;
            cp_async16(sb + OFF_B + doff, &Wh[(size_t)row * ldw + k0 + off], true);
        }
    };
    auto issue_A_plane = [&](int stage, int k0) {
        uint32_t sb = sbase + stage * STAGE_BYTES;
#pragma unroll
        for (int p = 0; p < 2; p++) {
            int c = tid + p * 256;
            int row = c >> 2;
            int off = (c & 3) << 3;
            int m = bm + row;
            bool ok = m < M;
            int ms = ok ? m : 0;
            uint32_t doff = row * (BKP * 2) + off * 2;
            cp_async16(sb + OFF_A + doff, Aph + (size_t)ms * lda + k0 + off, ok);
        }
    };
    auto prefetch_A = [&](int k0) {
        bool full = (k0 + BK <= K);
#pragma unroll
        for (int u2 = 0; u2 < 2; u2++) {
            int u = tid + u2 * 256;
            int r = u >> 2;
            int o = (u & 3) << 3;
            int m = bm + r;
            bool mok = m < M;
            const float* Ar = A + (size_t)m * K + k0 + o;
            if (full) {
#pragma unroll
                for (int e = 0; e < 8; e++) pv[u2][e] = mok ? __ldg(Ar + e) : 0.f;
            } else {
#pragma unroll
                for (int e = 0; e < 8; e++) {
                    int k = k0 + o + e;
                    pv[u2][e] = (mok && k < K) ? __ldg(Ar + e) : 0.f;
                }
            }
        }
    };
    auto cvt_sts_A = [&](int stage) {
#pragma unroll
        for (int u2 = 0; u2 < 2; u2++) {
            int u = tid + u2 * 256;
            int r = u >> 2;
            int o = (u & 3) << 3;
            unsigned ph[4];
#pragma unroll
            for (int p = 0; p < 4; p++)
                ph[p] = pack2h(pv[u2][2 * p], pv[u2][2 * p + 1]);
            *(uint4*)(dynsmem + stage * STAGE_BYTES + OFF_A + r * (BKP * 2) + o * 2) =
                make_uint4(ph[0], ph[1], ph[2], ph[3]);
        }
    };

    const int nt = Kpad / BK;
    if (AMODE == 0) {
        prefetch_A(0);
        cvt_sts_A(0);
    } else {
        issue_A_plane(0, 0);
    }
    issue_B(0, 0);
    asm volatile("cp.async.commit_group;" ::: "memory");

    for (int kt = 0; kt < nt; kt++) {
        int cur = kt & 1;
        int nxt = cur ^ 1;
        asm volatile("cp.async.wait_group 0;" ::: "memory");
        __syncthreads();

        bool hn = (kt + 1) < nt;
        int k1 = (kt + 1) * BK;
        if (hn) {
            if (AMODE == 0) prefetch_A(k1);
            else            issue_A_plane(nxt, k1);
            issue_B(nxt, k1);
        }
        asm volatile("cp.async.commit_group;" ::: "memory");

        uint32_t sA = sbase + cur * STAGE_BYTES;
#pragma unroll
        for (int kh = 0; kh < BK; kh += 16) {
            unsigned a[2][4];
#pragma unroll
            for (int mi = 0; mi < 2; mi++) {
                uint32_t ra = sA + OFF_A + (rA0 + mi * 16) * (BKP * 2) + (cA + kh) * 2;
                ldmx4(a[mi], ra);
            }
#pragma unroll
            for (int nip = 0; nip < NN / 2; nip++) {
                unsigned b4[4];
                uint32_t rb = sA + OFF_B + (rB0 + nip * 16) * (BKP * 2) + (cB + kh) * 2;
                ldmx4(b4, rb);
#pragma unroll
                for (int mi = 0; mi < 2; mi++) {
                    mma16816h(acc[mi][2 * nip],     a[mi], &b4[0]);
                    mma16816h(acc[mi][2 * nip + 1], a[mi], &b4[2]);
                }
            }
        }

        if (AMODE == 0 && hn) cvt_sts_A(nxt);
    }

    // ---- fp16 epilogue ----
#pragma unroll
    for (int mi = 0; mi < 2; mi++) {
#pragma unroll
        for (int ni = 0; ni < NN; ni++) {
            int row0 = bm + warp_m + mi * 16 + g;
            int col  = warp_n + ni * 8 + 2 * qt;
            if (col < N) {
                if (row0 < M)
                    *(unsigned*)&C[(size_t)row0 * N + col] =
                        pack2h(acc[mi][ni][0], acc[mi][ni][1]);
                if (row0 + 8 < M)
                    *(unsigned*)&C[(size_t)(row0 + 8) * N + col] =
                        pack2h(acc[mi][ni][2], acc[mi][ni][3]);
            }
        }
    }
}

// ======== fused CSR-gather SpMM (fp16 support) + bias + ReLU + colsum ========
// HOUT 1: write fp16 g_xh (layers 0-1). HOUT 0: write fp32 g_x (layer 2).
#define RPW 2
template <int FV, int HOUT>
__global__ __launch_bounds__(256) void spmm_fused_kernel(const float* __restrict__ bias,
                                                         float* __restrict__ colsum) {
    constexpr int VEC = FV / 32;      // 4 or 2 features per lane
    __shared__ float cs[FV];
    int tid = threadIdx.x;
    if (tid < FV) cs[tid] = 0.f;
    __syncthreads();
    int lane = tid & 31;
    int warp = (((int)blockIdx.x * blockDim.x) + tid) >> 5;
    int r0 = warp * RPW;

    float bv[VEC], bsum[VEC];
#pragma unroll
    for (int v = 0; v < VEC; v++) {
        bv[v] = bias[lane * VEC + v];
        bsum[v] = 0.f;
    }

    if (r0 < N_NODES) {
        for (int rr = 0; rr < RPW; rr++) {
            int r = r0 + rr;
            if (r >= N_NODES) break;
            int beg = __ldg(&g_rowoff[r]);
            int end = __ldg(&g_rowoff[r + 1]);
            float acc[VEC];
#pragma unroll
            for (int v = 0; v < VEC; v++) acc[v] = 0.f;

            auto gather = [&](int2 p) {
                float w = __int_as_float(p.y);
                const __half* s = &g_supporth[(size_t)p.x * FV + lane * VEC];
                if (VEC == 4) {
                    uint2 u = *(const uint2*)s;
                    float2 lo = __half22float2(*(__half2*)&u.x);
                    float2 hi = __half22float2(*(__half2*)&u.y);
                    acc[0] = fmaf(w, lo.x, acc[0]);
                    acc[1] = fmaf(w, lo.y, acc[1]);
                    acc[2] = fmaf(w, hi.x, acc[2]);
                    acc[3] = fmaf(w, hi.y, acc[3]);
                } else {
                    unsigned u = *(const unsigned*)s;
                    float2 lo = __half22float2(*(__half2*)&u);
                    acc[0] = fmaf(w, lo.x, acc[0]);
                    acc[1] = fmaf(w, lo.y, acc[1]);
                }
            };

            int i = beg;
            for (; i + 4 <= end; i += 4) {
                int2 p0 = __ldg(&g_epack[i]);
                int2 p1 = __ldg(&g_epack[i + 1]);
                int2 p2 = __ldg(&g_epack[i + 2]);
                int2 p3 = __ldg(&g_epack[i + 3]);
                gather(p0); gather(p1); gather(p2); gather(p3);
            }
            for (; i < end; i++) gather(__ldg(&g_epack[i]));

#pragma unroll
            for (int v = 0; v < VEC; v++) {
                acc[v] = fmaxf(acc[v] + bv[v], 0.f);
                bsum[v] += acc[v];
            }
            if (HOUT) {
                // fp16 x (layers 0-1); VEC==4 here
                *(uint2*)&g_xh[(size_t)r * FV + lane * 4] =
                    make_uint2(pack2h(acc[0], acc[1]), pack2h(acc[2], acc[3]));
            } else if (VEC == 4) {
                *(float4*)&g_x[(size_t)r * FV + lane * 4] =
                    make_float4(acc[0], acc[1], acc[2], acc[3]);
            } else {
                *(float2*)&g_x[(size_t)r * FV + lane * 2] =
                    make_float2(acc[0], acc[1]);
            }
        }
#pragma unroll
        for (int v = 0; v < VEC; v++)
            atomicAdd(&cs[lane * VEC + v], bsum[v]);
    }
    __syncthreads();
    if (tid < FV) atomicAdd(&colsum[tid], cs[tid]);
}

// -------- PairNorm F=128: read fp16 x, write fp16 plane --------
__global__ void pairnorm128_split_kernel(const float* __restrict__ colsum) {
    int gw = ((int)blockIdx.x * blockDim.x + threadIdx.x) >> 5;
    int lane = threadIdx.x & 31;
    if (gw >= N_NODES) return;
    const float invN = 1.0f / N_NODES;
    float4 mean = *(const float4*)&colsum[lane * 4];
    uint2 u = *(const uint2*)&g_xh[(size_t)gw * F_HID + lane * 4];
    float2 lo = __half22float2(*(__half2*)&u.x);
    float2 hi = __half22float2(*(__half2*)&u.y);
    float v0 = lo.x - mean.x * invN;
    float v1 = lo.y - mean.y * invN;
    float v2 = hi.x - mean.z * invN;
    float v3 = hi.y - mean.w * invN;
    float ss = v0 * v0 + v1 * v1 + v2 * v2 + v3 * v3;
#pragma unroll
    for (int o = 16; o > 0; o >>= 1) ss += __shfl_xor_sync(0xffffffffu, ss, o);
    float inv = rsqrtf(EPSV + ss);
    unsigned h01 = pack2h(v0 * inv, v1 * inv);
    unsigned h23 = pack2h(v2 * inv, v3 * inv);
    *(uint2*)&g_Xh[(size_t)gw * F_HID + lane * 4] = make_uint2(h01, h23);
}

// -------- PairNorm F=64 (final, fp32 for decode) --------
__global__ void pairnorm64_kernel(const float* __restrict__ colsum) {
    int gw = ((int)blockIdx.x * blockDim.x + threadIdx.x) >> 5;
    int lane = threadIdx.x & 31;
    if (gw >= N_NODES) return;
    const float invN = 1.0f / N_NODES;
    float2 mean = *(const float2*)&colsum[lane * 2];
    float2 v = *(const float2*)&g_x[(size_t)gw * F_OUTD + lane * 2];
    v.x -= mean.x * invN;
    v.y -= mean.y * invN;
    float ss = v.x * v.x + v.y * v.y;
#pragma unroll
    for (int o = 16; o > 0; o >>= 1) ss += __shfl_xor_sync(0xffffffffu, ss, o);
    float inv = rsqrtf(EPSV + ss);
    *(float2*)&g_x[(size_t)gw * F_OUTD + lane * 2] = make_float2(v.x * inv, v.y * inv);
}

// -------- decode --------
__global__ void decode_kernel(const int* __restrict__ pos, const int* __restrict__ neg,
                              float* __restrict__ out) {
    int gwarp = ((int)blockIdx.x * blockDim.x + threadIdx.x) >> 5;
    int lane = threadIdx.x & 31;
    if (gwarp >= N_EDGES) return;
    const int* ei = (gwarp < 20000) ? (pos + (size_t)gwarp * 2)
                                    : (neg + (size_t)(gwarp - 20000) * 2);
    int a = ei[0];
    int b = ei[1];
    const float* xa = &g_x[(size_t)a * F_OUTD];
    const float* xb = &g_x[(size_t)b * F_OUTD];
    float s = xa[lane] * xb[lane] + xa[lane + 32] * xb[lane + 32];
#pragma unroll
    for (int o = 16; o > 0; o >>= 1) s += __shfl_xor_sync(0xffffffffu, s, o);
    if (lane == 0) out[gwarp] = 1.0f / (1.0f + expf(-s));
}

// ---------------------------------------------------------------
extern "C" void kernel_launch(void* const* d_in, const int* in_sizes, int n_in,
                              void* d_out, int out_size) {
    const float* in_feature = (const float*)d_in[0];
    const int*   adj_row    = (const int*)d_in[1];
    const int*   adj_col    = (const int*)d_in[2];
    const float* adj_val    = (const float*)d_in[3];
    const int*   pos_ei     = (const int*)d_in[4];
    const int*   neg_ei     = (const int*)d_in[5];
    const float* W0 = (const float*)d_in[6];
    const float* W1 = (const float*)d_in[8];
    const float* W2 = (const float*)d_in[10];
    const float* Bv[3] = { (const float*)d_in[7], (const float*)d_in[9], (const float*)d_in[11] };
    float* out = (float*)d_out;

    __half* d_support = nullptr;
    float* d_colsum = nullptr;
    __half* d_Xh = nullptr;
    __half *d_Wh[3];
    cudaGetSymbolAddress((void**)&d_support, g_supporth);
    cudaGetSymbolAddress((void**)&d_colsum, g_colsum3);
    cudaGetSymbolAddress((void**)&d_Xh, g_Xh);
    cudaGetSymbolAddress((void**)&d_Wh[0], g_W0h);
    cudaGetSymbolAddress((void**)&d_Wh[1], g_W1h);
    cudaGetSymbolAddress((void**)&d_Wh[2], g_W2h);

    cudaFuncSetAttribute((const void*)gemm_tc_kernel<0, 128>,
                         cudaFuncAttributeMaxDynamicSharedMemorySize, GEMM_SMEM);
    cudaFuncSetAttribute((const void*)gemm_tc_kernel<1, 128>,
                         cudaFuncAttributeMaxDynamicSharedMemorySize, GEMM_SMEM);
    cudaFuncSetAttribute((const void*)gemm_tc_kernel<1, 64>,
                         cudaFuncAttributeMaxDynamicSharedMemorySize, GEMM_SMEM);

    // one-time side stream + events
    static cudaStream_t s2 = nullptr;
    static cudaEvent_t evF = nullptr, evJ = nullptr;
    if (s2 == nullptr) {
        cudaStreamCreateWithFlags(&s2, cudaStreamNonBlocking);
        cudaEventCreateWithFlags(&evF, cudaEventDisableTiming);
        cudaEventCreateWithFlags(&evJ, cudaEventDisableTiming);
    }

    // ---- fork: CSR build on side stream, overlapping prep + GEMM0 ----
    cudaEventRecord(evF, 0);
    cudaStreamWaitEvent(s2, evF, 0);
    csr_zero_kernel<<<(N_NODES + 255) / 256, 256, 0, s2>>>();
    csr_hist_kernel<<<(NNZ + 255) / 256, 256, 0, s2>>>(adj_row);
    csr_scanA_kernel<<<NBLK_SCAN, SCAN_BLK, 0, s2>>>();
    csr_scanB_kernel<<<1, 128, 0, s2>>>();
    csr_scanC_kernel<<<(N_NODES + 255) / 256, 256, 0, s2>>>();
    csr_scatter_kernel<<<(NNZ + 255) / 256, 256, 0, s2>>>(adj_row, adj_col, adj_val);
    cudaEventRecord(evJ, s2);

    // ---- main stream ----
    prep_kernel<<<(PREP_TOTAL + 255) / 256, 256>>>(W0, W1, W2);

    const int Kdims[3] = { F_IN, F_HID, F_HID };
    const int Ndims[3] = { F_HID, F_HID, F_OUTD };
    const int Kpads[3] = { KPAD0, F_HID, F_HID };

    for (int l = 0; l < 3; l++) {
        int K = Kdims[l], F = Ndims[l], Kpadl = Kpads[l];

        dim3 ggrid(1, (N_NODES + BM - 1) / BM);
        if (l == 0)
            gemm_tc_kernel<0, 128><<<ggrid, 256, GEMM_SMEM>>>(
                in_feature, nullptr, d_Wh[0],
                d_support, N_NODES, K, Kpadl, 0, KPAD0, F);
        else if (l == 1)
            gemm_tc_kernel<1, 128><<<ggrid, 256, GEMM_SMEM>>>(
                nullptr, d_Xh, d_Wh[1],
                d_support, N_NODES, K, Kpadl, F_HID, F_HID, F);
        else
            gemm_tc_kernel<1, 64><<<ggrid, 256, GEMM_SMEM>>>(
                nullptr, d_Xh, d_Wh[2],
                d_support, N_NODES, K, Kpadl, F_HID, F_HID, F);

        if (l == 0) cudaStreamWaitEvent(0, evJ, 0);

        int nwarps = (N_NODES + RPW - 1) / RPW;
        int nblk = (nwarps * 32 + 255) / 256;
        float* csum = d_colsum + l * F_HID;
        if (F == 128)
            spmm_fused_kernel<128, 1><<<nblk, 256>>>(Bv[l], csum);
        else
            spmm_fused_kernel<64, 0><<<nblk, 256>>>(Bv[l], csum);

        if (l < 2)
            pairnorm128_split_kernel<<<(N_NODES * 32 + 255) / 256, 256>>>(csum);
        else
            pairnorm64_kernel<<<(N_NODES * 32 + 255) / 256, 256>>>(csum);
    }

    int dblocks = (N_EDGES * 32 + 255) / 256;
    decode_kernel<<<dblocks, 256>>>(pos_ei, neg_ei, out);
}